// round 2
// baseline (speedup 1.0000x reference)
#include <cuda_runtime.h>
#include <cstdint>
#include <cstddef>

#define Bsz  512
#define S3v  512
#define Tsz  16
#define Cd   128
#define Mrows (Bsz * S3v)
#define EPSL 1e-5f
#define RT   7680   // B * 15 transformer rows

// ---------------- device scratch (no runtime allocation allowed) ----------------
__device__ float g_x0[(size_t)Mrows * Cd];
__device__ float g_x1[(size_t)Mrows * Cd];
__device__ float g_sA[Bsz * Cd];
__device__ float g_sB[Bsz * Cd];
__device__ float g_alpha[Bsz];
__device__ float g_m[Mrows];
__device__ float g_tv[Bsz * Cd];
__device__ float g_a[(size_t)RT * 128];
__device__ float g_h[(size_t)RT * 128];
__device__ float g_qkv[(size_t)RT * 384];
__device__ float g_o[(size_t)RT * 128];
__device__ float g_f[(size_t)RT * 512];

// ---------------- helpers ----------------
__device__ __forceinline__ float tf32r(float x) {
    unsigned u;
    asm("cvt.rna.tf32.f32 %0, %1;" : "=r"(u) : "f"(x));
    return __uint_as_float(u);
}
__device__ __forceinline__ void mma8(float* d, const unsigned* a, unsigned b0, unsigned b1) {
    asm("mma.sync.aligned.m16n8k8.row.col.f32.tf32.tf32.f32 "
        "{%0,%1,%2,%3},{%4,%5,%6,%7},{%8,%9},{%0,%1,%2,%3};"
        : "+f"(d[0]), "+f"(d[1]), "+f"(d[2]), "+f"(d[3])
        : "r"(a[0]), "r"(a[1]), "r"(a[2]), "r"(a[3]), "r"(b0), "r"(b1));
}
__device__ __forceinline__ float wredsum(float v) {
#pragma unroll
    for (int o = 16; o > 0; o >>= 1) v += __shfl_xor_sync(0xffffffffu, v, o);
    return v;
}

// ======================================================================
// K1: features + lin_in + mask + per-batch masked colsum + alpha
// ======================================================================
__global__ void k_init(const int* __restrict__ xx, const float* __restrict__ ss,
                       const float* __restrict__ Win, const float* __restrict__ b_in) {
    int b = blockIdx.x, c = threadIdx.x;
    float w0 = Win[c * 5 + 0], w1 = Win[c * 5 + 1], w2 = Win[c * 5 + 2];
    float w3 = Win[c * 5 + 3], w4 = Win[c * 5 + 4];
    float base = (ss[b] * 0.125f) * w4 + b_in[c];
    const int* fp = xx + (size_t)b * Tsz * S3v;
    float ssum = 0.f; int ncnt = 0;
    const float inv7 = 1.0f / 7.0f;
    for (int p = 0; p < S3v; p++) {
        int f = fp[p];
        int i = p >> 6, j = (p >> 3) & 7, k = p & 7;
        float val = base + (float)i * inv7 * w0 + (float)j * inv7 * w1 +
                    (float)k * inv7 * w2 + (float)f * 0.5f * w3;
        g_x0[((size_t)b * S3v + p) * Cd + c] = val;
        if (f != 0) { ssum += val; ncnt++; }
        if ((p & 127) == c) g_m[b * S3v + p] = (f != 0) ? 1.0f : 0.0f;
    }
    g_sA[b * Cd + c] = ssum;
    if (c == 0) g_alpha[b] = (ncnt > 1) ? 1.0f / (float)(ncnt - 1) : 0.0f;
}

// ======================================================================
// K2: per-batch tv[b,c] = alpha_b * (s_b @ Wl^T)[c] + bl[c]; zero snext
// ======================================================================
__global__ void k_prep(const float* __restrict__ sin_, const float* __restrict__ Wl_l,
                       const float* __restrict__ bl_l, float* __restrict__ snext) {
    __shared__ float ssm[Cd];
    int b = blockIdx.x, c = threadIdx.x;
    ssm[c] = sin_[b * Cd + c];
    __syncthreads();
    const float4* wr = (const float4*)(Wl_l + c * Cd);
    float acc = 0.f;
#pragma unroll 8
    for (int k4 = 0; k4 < 32; k4++) {
        float4 w = wr[k4];
        acc += ssm[k4 * 4 + 0] * w.x + ssm[k4 * 4 + 1] * w.y +
               ssm[k4 * 4 + 2] * w.z + ssm[k4 * 4 + 3] * w.w;
    }
    g_tv[b * Cd + c] = g_alpha[b] * acc + bl_l[c];
    snext[b * Cd + c] = 0.f;
}

// ======================================================================
// K3: GNN layer GEMM (tf32 mma) + fused epilogue (h, relu, LN, colsum)
// BM=128, BN=256, 256 threads (8 warps: 2 in M x 4 in N)
// ======================================================================
#define LDA 132
#define LDC 260
#define GNN_SMEM_FLOATS (256*LDA + 128*LDA + 5*128)
__global__ void __launch_bounds__(256, 1)
k_gnn(const float* __restrict__ xin, const float* __restrict__ Wr_l,
      const float* __restrict__ Wl_l, const float* __restrict__ ln_g,
      const float* __restrict__ ln_b, float* __restrict__ xout,
      float* __restrict__ snext) {
    extern __shared__ float sm[];
    float* Wsm = sm;                  // 256 x LDA
    float* Asm = sm + 256 * LDA;      // 128 x LDA
    float* tvs = sm + 256 * LDA + 128 * LDA;
    float* gs  = tvs + 128;
    float* bs2 = gs + 128;
    float* msk = bs2 + 128;
    float* sacc = msk + 128;
    float* accbuf = sm;               // reuse Wsm region: 128 x LDC

    int tid = threadIdx.x;
    int row0 = blockIdx.x * 128;
    int b = row0 >> 9;

    // stage W [256 n][128 k] (tf32-rounded)
    for (int u = tid; u < 8192; u += 256) {
        int n = u >> 5, c4 = (u & 31) << 2;
        const float* src = (n < Cd) ? (Wr_l + n * Cd + c4) : (Wl_l + (n - Cd) * Cd + c4);
        float4 v = *(const float4*)src;
        float* d = Wsm + n * LDA + c4;
        d[0] = tf32r(v.x); d[1] = tf32r(v.y); d[2] = tf32r(v.z); d[3] = tf32r(v.w);
    }
    // stage A [128][128]
    for (int u = tid; u < 4096; u += 256) {
        int r = u >> 5, c4 = (u & 31) << 2;
        float4 v = *(const float4*)(xin + (size_t)(row0 + r) * Cd + c4);
        float* d = Asm + r * LDA + c4;
        d[0] = tf32r(v.x); d[1] = tf32r(v.y); d[2] = tf32r(v.z); d[3] = tf32r(v.w);
    }
    if (tid < 128) {
        tvs[tid] = g_tv[b * Cd + tid];
        gs[tid]  = ln_g[tid];
        bs2[tid] = ln_b[tid];
        msk[tid] = g_m[row0 + tid];
        sacc[tid] = 0.f;
    }
    float alpha = g_alpha[b];
    __syncthreads();

    int wid = tid >> 5, lane = tid & 31;
    int wm = wid & 1, wn = wid >> 1;
    int gid = lane >> 2, tig = lane & 3;

    float acc[4][8][4];
#pragma unroll
    for (int a0 = 0; a0 < 4; a0++)
#pragma unroll
        for (int a1 = 0; a1 < 8; a1++)
#pragma unroll
            for (int a2 = 0; a2 < 4; a2++) acc[a0][a1][a2] = 0.f;

#pragma unroll 2
    for (int ks = 0; ks < Cd; ks += 8) {
        unsigned af[4][4], bf[8][2];
#pragma unroll
        for (int mf = 0; mf < 4; mf++) {
            const unsigned* p = (const unsigned*)(Asm + (wm * 64 + mf * 16 + gid) * LDA + ks + tig);
            af[mf][0] = p[0]; af[mf][1] = p[8 * LDA]; af[mf][2] = p[4]; af[mf][3] = p[8 * LDA + 4];
        }
#pragma unroll
        for (int nf = 0; nf < 8; nf++) {
            const unsigned* p = (const unsigned*)(Wsm + (wn * 64 + nf * 8 + gid) * LDA + ks + tig);
            bf[nf][0] = p[0]; bf[nf][1] = p[4];
        }
#pragma unroll
        for (int mf = 0; mf < 4; mf++)
#pragma unroll
            for (int nf = 0; nf < 8; nf++)
                mma8(acc[mf][nf], af[mf], bf[nf][0], bf[nf][1]);
    }
    __syncthreads();   // done reading Wsm/Asm

    // dump accumulators to smem (cols 0..255)
#pragma unroll
    for (int mf = 0; mf < 4; mf++)
#pragma unroll
        for (int nf = 0; nf < 8; nf++) {
            int row = wm * 64 + mf * 16 + gid;
            int col = wn * 64 + nf * 8 + tig * 2;
            *(float2*)(accbuf + row * LDC + col) = make_float2(acc[mf][nf][0], acc[mf][nf][1]);
            *(float2*)(accbuf + (row + 8) * LDC + col) = make_float2(acc[mf][nf][2], acc[mf][nf][3]);
        }
    __syncthreads();

    // epilogue: warp wid handles rows wid*16..+15, lane owns cols lane*4..+3
    float cs0 = 0.f, cs1 = 0.f, cs2 = 0.f, cs3 = 0.f;
    float tg0 = gs[lane * 4], tg1 = gs[lane * 4 + 1], tg2 = gs[lane * 4 + 2], tg3 = gs[lane * 4 + 3];
    float tb0 = bs2[lane * 4], tb1 = bs2[lane * 4 + 1], tb2 = bs2[lane * 4 + 2], tb3 = bs2[lane * 4 + 3];
    float tv0 = tvs[lane * 4], tv1 = tvs[lane * 4 + 1], tv2 = tvs[lane * 4 + 2], tv3 = tvs[lane * 4 + 3];
    for (int rr = 0; rr < 16; rr++) {
        int row = wid * 16 + rr;
        float4 y1 = *(float4*)(accbuf + row * LDC + lane * 4);
        float4 y2 = *(float4*)(accbuf + row * LDC + 128 + lane * 4);
        float v0 = fmaxf(y1.x - alpha * y2.x + tv0, 0.f);
        float v1 = fmaxf(y1.y - alpha * y2.y + tv1, 0.f);
        float v2 = fmaxf(y1.z - alpha * y2.z + tv2, 0.f);
        float v3 = fmaxf(y1.w - alpha * y2.w + tv3, 0.f);
        float s = wredsum(v0 + v1 + v2 + v3);
        float sq = wredsum(v0 * v0 + v1 * v1 + v2 * v2 + v3 * v3);
        float mu = s * (1.0f / 128.0f);
        float var = fmaxf(sq * (1.0f / 128.0f) - mu * mu, 0.f);
        float rs = rsqrtf(var + EPSL);
        float4 xn;
        xn.x = (v0 - mu) * rs * tg0 + tb0;
        xn.y = (v1 - mu) * rs * tg1 + tb1;
        xn.z = (v2 - mu) * rs * tg2 + tb2;
        xn.w = (v3 - mu) * rs * tg3 + tb3;
        *(float4*)(xout + (size_t)(row0 + row) * Cd + lane * 4) = xn;
        float mk = msk[row];
        cs0 += mk * xn.x; cs1 += mk * xn.y; cs2 += mk * xn.z; cs3 += mk * xn.w;
    }
    atomicAdd(&sacc[lane * 4 + 0], cs0);
    atomicAdd(&sacc[lane * 4 + 1], cs1);
    atomicAdd(&sacc[lane * 4 + 2], cs2);
    atomicAdd(&sacc[lane * 4 + 3], cs3);
    __syncthreads();
    if (tid < 128) atomicAdd(&snext[b * Cd + tid], sacc[tid]);
}

// ======================================================================
// K4: pooling (out rows 0..23) + mv_emb (row 25)
// ======================================================================
__global__ void k_pool(const float* __restrict__ x, const float* __restrict__ ss,
                       const float* __restrict__ Wsc, const float* __restrict__ bsc,
                       float* __restrict__ out) {
    __shared__ float ms[S3v];
    int b = blockIdx.x, c = threadIdx.x;
    for (int p = c; p < S3v; p += 128) ms[p] = g_m[b * S3v + p];
    __syncthreads();
    float aj[8], ak[8];
#pragma unroll
    for (int q = 0; q < 8; q++) { aj[q] = 0.f; ak[q] = 0.f; }
    const float* xb = x + (size_t)b * S3v * Cd + c;
    for (int i = 0; i < 8; i++) {
        float ai = 0.f;
#pragma unroll
        for (int jk = 0; jk < 64; jk++) {
            int p = i * 64 + jk;
            float v = ms[p] * xb[(size_t)p * Cd];
            ai += v; aj[jk >> 3] += v; ak[jk & 7] += v;
        }
        out[((size_t)b * 26 + i) * Cd + c] = ai * 0.015625f;
    }
#pragma unroll
    for (int q = 0; q < 8; q++) {
        out[((size_t)b * 26 + 8 + q) * Cd + c] = aj[q] * 0.015625f;
        out[((size_t)b * 26 + 16 + q) * Cd + c] = ak[q] * 0.015625f;
    }
    out[((size_t)b * 26 + 25) * Cd + c] = fmaxf(ss[b] * Wsc[c] + bsc[c], 0.f);
}

// ======================================================================
// K5: generic tf32 GEMM  out[M,NT] = op(A[M,KT] @ W[NT,KT]^T + bias [+res])
// BM=128, BN=128, 256 threads (4 M-warps x 2 N-warps)
// EPI: 0=bias, 1=bias+relu, 2=bias+residual.  ASRC: 0=float, 1=xx actions
// ======================================================================
#define GEMM_SMEM_FLOATS (2 * 128 * LDA)
template <int NT, int KT, int EPI, int ASRC>
__global__ void __launch_bounds__(256, 1)
k_gemm(const void* __restrict__ Av, const float* __restrict__ W,
       const float* __restrict__ bias, const float* __restrict__ res,
       float* __restrict__ out) {
    extern __shared__ float sm[];
    float* sW = sm;
    float* sA = sm + 128 * LDA;
    int tid = threadIdx.x;
    int row0 = blockIdx.x * 128, n0 = blockIdx.y * 128;
    int wid = tid >> 5, lane = tid & 31;
    int wm = wid & 3, wn = wid >> 2;
    int gid = lane >> 2, tig = lane & 3;

    float acc[2][8][4];
#pragma unroll
    for (int a0 = 0; a0 < 2; a0++)
#pragma unroll
        for (int a1 = 0; a1 < 8; a1++)
#pragma unroll
            for (int a2 = 0; a2 < 4; a2++) acc[a0][a1][a2] = 0.f;

    for (int kc = 0; kc < KT; kc += 128) {
        for (int u = tid; u < 4096; u += 256) {
            int n = u >> 5, c4 = (u & 31) << 2;
            float4 v = *(const float4*)(W + (size_t)(n0 + n) * KT + kc + c4);
            float* d = sW + n * LDA + c4;
            d[0] = tf32r(v.x); d[1] = tf32r(v.y); d[2] = tf32r(v.z); d[3] = tf32r(v.w);
        }
        if (ASRC == 0) {
            const float* A = (const float*)Av;
            for (int u = tid; u < 4096; u += 256) {
                int r = u >> 5, c4 = (u & 31) << 2;
                float4 v = *(const float4*)(A + (size_t)(row0 + r) * KT + kc + c4);
                float* d = sA + r * LDA + c4;
                d[0] = tf32r(v.x); d[1] = tf32r(v.y); d[2] = tf32r(v.z); d[3] = tf32r(v.w);
            }
        } else {
            const int* X = (const int*)Av;
            for (int u = tid; u < 4096; u += 256) {
                int r = u >> 5, c4 = (u & 31) << 2;
                int gr = row0 + r, bb = gr / 15, tt = gr - bb * 15;
                int4 v = *(const int4*)(X + ((size_t)bb * 16 + tt + 1) * 512 + kc + c4);
                float* d = sA + r * LDA + c4;
                d[0] = (float)v.x; d[1] = (float)v.y; d[2] = (float)v.z; d[3] = (float)v.w;
            }
        }
        __syncthreads();
#pragma unroll 2
        for (int ks = 0; ks < 128; ks += 8) {
            unsigned af[2][4], bf[8][2];
#pragma unroll
            for (int mf = 0; mf < 2; mf++) {
                const unsigned* p = (const unsigned*)(sA + (wm * 32 + mf * 16 + gid) * LDA + ks + tig);
                af[mf][0] = p[0]; af[mf][1] = p[8 * LDA]; af[mf][2] = p[4]; af[mf][3] = p[8 * LDA + 4];
            }
#pragma unroll
            for (int nf = 0; nf < 8; nf++) {
                const unsigned* p = (const unsigned*)(sW + (wn * 64 + nf * 8 + gid) * LDA + ks + tig);
                bf[nf][0] = p[0]; bf[nf][1] = p[4];
            }
#pragma unroll
            for (int mf = 0; mf < 2; mf++)
#pragma unroll
                for (int nf = 0; nf < 8; nf++)
                    mma8(acc[mf][nf], af[mf], bf[nf][0], bf[nf][1]);
        }
        __syncthreads();
    }
    // epilogue straight from registers
#pragma unroll
    for (int mf = 0; mf < 2; mf++)
#pragma unroll
        for (int nf = 0; nf < 8; nf++) {
            int gm = row0 + wm * 32 + mf * 16 + gid;
            int gn = n0 + wn * 64 + nf * 8 + tig * 2;
            float b0 = bias[gn], b1 = bias[gn + 1];
            float v00 = acc[mf][nf][0] + b0, v01 = acc[mf][nf][1] + b1;
            float v10 = acc[mf][nf][2] + b0, v11 = acc[mf][nf][3] + b1;
            if (EPI == 1) {
                v00 = fmaxf(v00, 0.f); v01 = fmaxf(v01, 0.f);
                v10 = fmaxf(v10, 0.f); v11 = fmaxf(v11, 0.f);
            }
            if (EPI == 2) {
                v00 += res[(size_t)gm * NT + gn];     v01 += res[(size_t)gm * NT + gn + 1];
                v10 += res[(size_t)(gm + 8) * NT + gn]; v11 += res[(size_t)(gm + 8) * NT + gn + 1];
            }
            *(float2*)(out + (size_t)gm * NT + gn) = make_float2(v00, v01);
            *(float2*)(out + (size_t)(gm + 8) * NT + gn) = make_float2(v10, v11);
        }
}

// ======================================================================
// K6: LayerNorm over rows of (RT,128): warp per row
// ======================================================================
__global__ void k_ln(const float* __restrict__ a, const float* __restrict__ g,
                     const float* __restrict__ bb, float* __restrict__ h) {
    int row = blockIdx.x * 8 + (threadIdx.x >> 5);
    int lane = threadIdx.x & 31;
    float4 v = *(const float4*)(a + (size_t)row * 128 + lane * 4);
    float s = wredsum(v.x + v.y + v.z + v.w);
    float sq = wredsum(v.x * v.x + v.y * v.y + v.z * v.z + v.w * v.w);
    float mu = s * (1.0f / 128.0f);
    float var = fmaxf(sq * (1.0f / 128.0f) - mu * mu, 0.f);
    float rs = rsqrtf(var + EPSL);
    float4 o;
    o.x = (v.x - mu) * rs * g[lane * 4 + 0] + bb[lane * 4 + 0];
    o.y = (v.y - mu) * rs * g[lane * 4 + 1] + bb[lane * 4 + 1];
    o.z = (v.z - mu) * rs * g[lane * 4 + 2] + bb[lane * 4 + 2];
    o.w = (v.w - mu) * rs * g[lane * 4 + 3] + bb[lane * 4 + 3];
    *(float4*)(h + (size_t)row * 128 + lane * 4) = o;
}

// ======================================================================
// K7: attention. block = batch, warp = head. T=15, Hd=32.
// ======================================================================
__global__ void k_attn(const float* __restrict__ qkv, float* __restrict__ o) {
    __shared__ float sq[4][15 * 33], sk[4][15 * 33], sv[4][15 * 33];
    int b = blockIdx.x, w = threadIdx.x >> 5, lane = threadIdx.x & 31;
    for (int idx = lane; idx < 480; idx += 32) {
        int t = idx >> 5, d = idx & 31;
        const float* base = qkv + (size_t)(b * 15 + t) * 384 + w * 32 + d;
        sq[w][t * 33 + d] = base[0];
        sk[w][t * 33 + d] = base[128];
        sv[w][t * 33 + d] = base[256];
    }
    __syncwarp();
    if (lane < 15) {
        float qr[32];
#pragma unroll
        for (int d = 0; d < 32; d++) qr[d] = sq[w][lane * 33 + d];
        float sc[15];
        float mx = -1e30f;
#pragma unroll
        for (int tk = 0; tk < 15; tk++) {
            float a = 0.f;
#pragma unroll
            for (int d = 0; d < 32; d++) a += qr[d] * sk[w][tk * 33 + d];
            sc[tk] = a * 0.17677669529663687f;
            mx = fmaxf(mx, sc[tk]);
        }
        float ssum = 0.f;
#pragma unroll
        for (int tk = 0; tk < 15; tk++) { sc[tk] = expf(sc[tk] - mx); ssum += sc[tk]; }
        float inv = 1.0f / ssum;
        float od[32];
#pragma unroll
        for (int d = 0; d < 32; d++) od[d] = 0.f;
#pragma unroll
        for (int tk = 0; tk < 15; tk++) {
            float p = sc[tk] * inv;
#pragma unroll
            for (int d = 0; d < 32; d++) od[d] += p * sv[w][tk * 33 + d];
        }
        float* op = o + (size_t)(b * 15 + lane) * 128 + w * 32;
#pragma unroll
        for (int d4 = 0; d4 < 32; d4 += 4)
            *(float4*)(op + d4) = make_float4(od[d4], od[d4 + 1], od[d4 + 2], od[d4 + 3]);
    }
}

// ======================================================================
// K8: act_emb = mean over T-1 rows -> out row 24
// ======================================================================
__global__ void k_amean(const float* __restrict__ a, float* __restrict__ out) {
    int b = blockIdx.x, c = threadIdx.x;
    float s = 0.f;
#pragma unroll
    for (int t = 0; t < 15; t++) s += a[(size_t)(b * 15 + t) * 128 + c];
    out[((size_t)b * 26 + 24) * 128 + c] = s * (1.0f / 15.0f);
}

// ======================================================================
// host launcher
// ======================================================================
extern "C" void kernel_launch(void* const* d_in, const int* in_sizes, int n_in,
                              void* d_out, int out_size) {
    const int*   xx    = (const int*)d_in[0];
    const float* ss    = (const float*)d_in[1];
    const float* Win   = (const float*)d_in[2];
    const float* b_in  = (const float*)d_in[3];
    const float* Wl    = (const float*)d_in[4];
    const float* bl    = (const float*)d_in[5];
    const float* Wr    = (const float*)d_in[6];
    const float* ln_g  = (const float*)d_in[7];
    const float* ln_b  = (const float*)d_in[8];
    const float* Wqkv  = (const float*)d_in[9];
    const float* bqkv  = (const float*)d_in[10];
    const float* Wo    = (const float*)d_in[11];
    const float* bo    = (const float*)d_in[12];
    const float* ln1_g = (const float*)d_in[13];
    const float* ln1_b = (const float*)d_in[14];
    const float* ln2_g = (const float*)d_in[15];
    const float* ln2_b = (const float*)d_in[16];
    const float* W1    = (const float*)d_in[17];
    const float* b1    = (const float*)d_in[18];
    const float* W2    = (const float*)d_in[19];
    const float* b2    = (const float*)d_in[20];
    const float* Wact  = (const float*)d_in[21];
    const float* bact  = (const float*)d_in[22];
    const float* Wsc   = (const float*)d_in[23];
    const float* bsc   = (const float*)d_in[24];
    float* out = (float*)d_out;

    void *px0, *px1, *psA, *psB, *pa, *ph, *pqkv, *po, *pf;
    cudaGetSymbolAddress(&px0, g_x0);
    cudaGetSymbolAddress(&px1, g_x1);
    cudaGetSymbolAddress(&psA, g_sA);
    cudaGetSymbolAddress(&psB, g_sB);
    cudaGetSymbolAddress(&pa, g_a);
    cudaGetSymbolAddress(&ph, g_h);
    cudaGetSymbolAddress(&pqkv, g_qkv);
    cudaGetSymbolAddress(&po, g_o);
    cudaGetSymbolAddress(&pf, g_f);

    const int GNN_SMEM = GNN_SMEM_FLOATS * 4;
    const int GEMM_SMEM = GEMM_SMEM_FLOATS * 4;
    cudaFuncSetAttribute(k_gnn, cudaFuncAttributeMaxDynamicSharedMemorySize, GNN_SMEM);
    cudaFuncSetAttribute(k_gemm<128, 512, 0, 1>, cudaFuncAttributeMaxDynamicSharedMemorySize, GEMM_SMEM);
    cudaFuncSetAttribute(k_gemm<384, 128, 0, 0>, cudaFuncAttributeMaxDynamicSharedMemorySize, GEMM_SMEM);
    cudaFuncSetAttribute(k_gemm<128, 128, 2, 0>, cudaFuncAttributeMaxDynamicSharedMemorySize, GEMM_SMEM);
    cudaFuncSetAttribute(k_gemm<512, 128, 1, 0>, cudaFuncAttributeMaxDynamicSharedMemorySize, GEMM_SMEM);
    cudaFuncSetAttribute(k_gemm<128, 512, 2, 0>, cudaFuncAttributeMaxDynamicSharedMemorySize, GEMM_SMEM);

    k_init<<<Bsz, 128>>>(xx, ss, Win, b_in);

    float* X[2] = {(float*)px0, (float*)px1};
    float* Sp[2] = {(float*)psA, (float*)psB};
    int cur = 0;
    for (int l = 0; l < 3; l++) {
        k_prep<<<Bsz, 128>>>(Sp[cur], Wl + l * 16384, bl + l * 128, Sp[1 - cur]);
        k_gnn<<<Mrows / 128, 256, GNN_SMEM>>>(X[cur], Wr + l * 16384, Wl + l * 16384,
                                              ln_g, ln_b, X[1 - cur], Sp[1 - cur]);
        cur ^= 1;
    }
    k_pool<<<Bsz, 128>>>(X[cur], ss, Wsc, bsc, out);

    float* a = (float*)pa; float* h = (float*)ph; float* qkv = (float*)pqkv;
    float* o = (float*)po; float* f = (float*)pf;

    k_gemm<128, 512, 0, 1><<<dim3(RT / 128, 1), 256, GEMM_SMEM>>>(xx, Wact, bact, nullptr, a);
    for (int l = 0; l < 2; l++) {
        k_ln<<<RT / 8, 256>>>(a, ln1_g + l * 128, ln1_b + l * 128, h);
        k_gemm<384, 128, 0, 0><<<dim3(RT / 128, 3), 256, GEMM_SMEM>>>(h, Wqkv + l * 49152,
                                                                      bqkv + l * 384, nullptr, qkv);
        k_attn<<<Bsz, 128>>>(qkv, o);
        k_gemm<128, 128, 2, 0><<<dim3(RT / 128, 1), 256, GEMM_SMEM>>>(o, Wo + l * 16384,
                                                                      bo + l * 128, a, a);
        k_ln<<<RT / 8, 256>>>(a, ln2_g + l * 128, ln2_b + l * 128, h);
        k_gemm<512, 128, 1, 0><<<dim3(RT / 128, 4), 256, GEMM_SMEM>>>(h, W1 + l * 65536,
                                                                      b1 + l * 512, nullptr, f);
        k_gemm<128, 512, 2, 0><<<dim3(RT / 128, 1), 256, GEMM_SMEM>>>(f, W2 + l * 65536,
                                                                      b2 + l * 128, a, a);
    }
    k_amean<<<Bsz, 128>>>(a, out);
}

// round 3
// speedup vs baseline: 1.3278x; 1.3278x over previous
#include <cuda_runtime.h>
#include <cuda_fp16.h>
#include <cstdint>
#include <cstddef>

#define Bsz  512
#define S3v  512
#define Tsz  16
#define Cd   128
#define Mrows (Bsz * S3v)
#define EPSL 1e-5f
#define RT   7680   // B * 15 transformer rows

// ---------------- device scratch ----------------
__device__ __half g_xh0[(size_t)Mrows * Cd];
__device__ __half g_xh1[(size_t)Mrows * Cd];
__device__ float  g_xf[(size_t)Mrows * Cd];     // final-layer fp32 x for pooling
__device__ __half g_Wh[3 * 256 * 128];          // fp16 [Wr;Wl] per layer
__device__ float g_s0[Bsz * Cd];
__device__ float g_s1[Bsz * Cd];
__device__ float g_s2[Bsz * Cd];
__device__ float g_alpha[Bsz];
__device__ float g_m[Mrows];
__device__ float g_a[(size_t)RT * 128];
__device__ float g_h[(size_t)RT * 128];
__device__ float g_qkv[(size_t)RT * 384];
__device__ float g_o[(size_t)RT * 128];
__device__ float g_f[(size_t)RT * 512];

// ---------------- helpers ----------------
__device__ __forceinline__ void mmaf16(float* d, const unsigned* a, unsigned b0, unsigned b1) {
    asm("mma.sync.aligned.m16n8k16.row.col.f32.f16.f16.f32 "
        "{%0,%1,%2,%3},{%4,%5,%6,%7},{%8,%9},{%0,%1,%2,%3};"
        : "+f"(d[0]), "+f"(d[1]), "+f"(d[2]), "+f"(d[3])
        : "r"(a[0]), "r"(a[1]), "r"(a[2]), "r"(a[3]), "r"(b0), "r"(b1));
}
__device__ __forceinline__ float wredsum(float v) {
#pragma unroll
    for (int o = 16; o > 0; o >>= 1) v += __shfl_xor_sync(0xffffffffu, v, o);
    return v;
}

#define LDAh 136   // half stride for staged tiles (272B rows, 16B aligned, conflict-free frags)
#define LDC  260

// ======================================================================
// K_wconv: Wr|Wl (3 layers) fp32 -> fp16 concat [l][256][128]
// ======================================================================
__global__ void k_wconv(const float* __restrict__ Wr, const float* __restrict__ Wl) {
    int idx = (blockIdx.x * 256 + threadIdx.x) * 4;   // 98304 total
    int l = idx >> 15;
    int r = (idx >> 7) & 255;
    int k = idx & 127;
    const float* src = (r < 128) ? (Wr + l * 16384 + r * 128 + k)
                                 : (Wl + l * 16384 + (r - 128) * 128 + k);
    float4 v = *(const float4*)src;
    __half2* d = (__half2*)(g_Wh + idx);
    d[0] = __floats2half2_rn(v.x, v.y);
    d[1] = __floats2half2_rn(v.z, v.w);
}

// ======================================================================
// K1: features + lin_in (fp16 out) + mask + masked colsum + alpha + zero s1/s2
// ======================================================================
__global__ void k_init(const int* __restrict__ xx, const float* __restrict__ ss,
                       const float* __restrict__ Win, const float* __restrict__ b_in) {
    int b = blockIdx.x, c = threadIdx.x;
    float w0 = Win[c * 5 + 0], w1 = Win[c * 5 + 1], w2 = Win[c * 5 + 2];
    float w3 = Win[c * 5 + 3], w4 = Win[c * 5 + 4];
    float base = (ss[b] * 0.125f) * w4 + b_in[c];
    const int* fp = xx + (size_t)b * Tsz * S3v;
    float ssum = 0.f; int ncnt = 0;
    const float inv7 = 1.0f / 7.0f;
    for (int p = 0; p < S3v; p++) {
        int f = fp[p];
        int i = p >> 6, j = (p >> 3) & 7, k = p & 7;
        float val = base + (float)i * inv7 * w0 + (float)j * inv7 * w1 +
                    (float)k * inv7 * w2 + (float)f * 0.5f * w3;
        g_xh0[((size_t)b * S3v + p) * Cd + c] = __float2half_rn(val);
        if (f != 0) { ssum += val; ncnt++; }
        if ((p & 127) == c) g_m[b * S3v + p] = (f != 0) ? 1.0f : 0.0f;
    }
    g_s0[b * Cd + c] = ssum;
    g_s1[b * Cd + c] = 0.f;
    g_s2[b * Cd + c] = 0.f;
    if (c == 0) g_alpha[b] = (ncnt > 1) ? 1.0f / (float)(ncnt - 1) : 0.0f;
}

// ======================================================================
// K3: GNN layer GEMM (fp16 mma, fp32 acc) + fused tv + epilogue
// BM=128, BN=256, 256 threads (2 M-warps x 4 N-warps), warp tile 64x64
// ======================================================================
#define GNN_SMEM_BYTES (128 * LDC * 4 + 6 * 128 * 4)
template <int LAST>
__global__ void __launch_bounds__(256, 1)
k_gnn(const __half* __restrict__ xin, const __half* __restrict__ Wh_l,
      const float* __restrict__ bl_l, const float* __restrict__ sin_,
      const float* __restrict__ ln_g, const float* __restrict__ ln_b,
      __half* __restrict__ xout, float* __restrict__ snext) {
    extern __shared__ char smc[];
    __half* Wh = (__half*)smc;                    // 256 x LDAh halves
    __half* Ah = (__half*)(smc + 256 * LDAh * 2); // 128 x LDAh halves
    float* accbuf = (float*)smc;                  // 128 x LDC (aliases staging)
    float* misc = (float*)(smc + 128 * LDC * 4);
    float* ssm  = misc;
    float* tvs  = misc + 128;
    float* gs   = misc + 256;
    float* bs2  = misc + 384;
    float* msk  = misc + 512;
    float* sacc = misc + 640;

    int tid = threadIdx.x;
    int row0 = blockIdx.x * 128;
    int b = row0 >> 9;

    // stage W [256][128] fp16 (16B chunks)
    {
        const uint4* src = (const uint4*)Wh_l;
        for (int u = tid; u < 4096; u += 256) {           // 4096 uint4 = 32768 halves
            int n = u >> 4, c8 = (u & 15) << 3;
            *(uint4*)(Wh + n * LDAh + c8) = src[u];
        }
    }
    // stage A [128][128] fp16
    {
        const uint4* src = (const uint4*)(xin + (size_t)row0 * Cd);
        for (int u = tid; u < 2048; u += 256) {
            int r = u >> 4, c8 = (u & 15) << 3;
            *(uint4*)(Ah + r * LDAh + c8) = src[u];
        }
    }
    if (tid < 128) {
        ssm[tid] = sin_[b * Cd + tid];
        gs[tid]  = ln_g[tid];
        bs2[tid] = ln_b[tid];
        msk[tid] = g_m[row0 + tid];
        sacc[tid] = 0.f;
    }
    float alpha = g_alpha[b];
    __syncthreads();

    // tv[c] = alpha * sum_k s[k] * Wl_h[c][k] + bl[c]   (Wl = rows 128..255 of Wh)
    if (tid < 128) {
        const __half2* wr2 = (const __half2*)(Wh + (128 + tid) * LDAh);
        float acc = 0.f;
#pragma unroll 16
        for (int k2 = 0; k2 < 64; k2++) {
            float2 w = __half22float2(wr2[k2]);
            acc += ssm[k2 * 2] * w.x + ssm[k2 * 2 + 1] * w.y;
        }
        tvs[tid] = alpha * acc + bl_l[tid];
    }

    int wid = tid >> 5, lane = tid & 31;
    int wm = wid & 1, wn = wid >> 1;
    int gid = lane >> 2, tig = lane & 3;

    float acc[4][8][4];
#pragma unroll
    for (int a0 = 0; a0 < 4; a0++)
#pragma unroll
        for (int a1 = 0; a1 < 8; a1++)
#pragma unroll
            for (int a2 = 0; a2 < 4; a2++) acc[a0][a1][a2] = 0.f;

#pragma unroll
    for (int ks = 0; ks < Cd; ks += 16) {
        unsigned af[4][4], bf[8][2];
#pragma unroll
        for (int mf = 0; mf < 4; mf++) {
            const unsigned* p = (const unsigned*)(Ah + (wm * 64 + mf * 16 + gid) * LDAh + ks);
            af[mf][0] = p[tig];            // (gid,    2tig)
            af[mf][1] = p[tig + 4 * LDAh]; // (gid+8,  2tig)  [8 rows * LDAh/2 u32]
            af[mf][2] = p[tig + 4];        // (gid,    2tig+8)
            af[mf][3] = p[tig + 4 * LDAh + 4];
        }
#pragma unroll
        for (int nf = 0; nf < 8; nf++) {
            const unsigned* p = (const unsigned*)(Wh + (wn * 64 + nf * 8 + gid) * LDAh + ks);
            bf[nf][0] = p[tig];
            bf[nf][1] = p[tig + 4];
        }
#pragma unroll
        for (int mf = 0; mf < 4; mf++)
#pragma unroll
            for (int nf = 0; nf < 8; nf++)
                mmaf16(acc[mf][nf], af[mf], bf[nf][0], bf[nf][1]);
    }
    __syncthreads();   // staging regions dead; reuse as accbuf

    // dump accumulators (cols 0..255)
#pragma unroll
    for (int mf = 0; mf < 4; mf++)
#pragma unroll
        for (int nf = 0; nf < 8; nf++) {
            int row = wm * 64 + mf * 16 + gid;
            int col = wn * 64 + nf * 8 + tig * 2;
            *(float2*)(accbuf + row * LDC + col) = make_float2(acc[mf][nf][0], acc[mf][nf][1]);
            *(float2*)(accbuf + (row + 8) * LDC + col) = make_float2(acc[mf][nf][2], acc[mf][nf][3]);
        }
    __syncthreads();

    // epilogue: warp wid -> rows wid*16..+15, lane owns 4 cols
    float cs0 = 0.f, cs1 = 0.f, cs2 = 0.f, cs3 = 0.f;
    float tg0 = gs[lane * 4], tg1 = gs[lane * 4 + 1], tg2 = gs[lane * 4 + 2], tg3 = gs[lane * 4 + 3];
    float tb0 = bs2[lane * 4], tb1 = bs2[lane * 4 + 1], tb2 = bs2[lane * 4 + 2], tb3 = bs2[lane * 4 + 3];
    float tv0 = tvs[lane * 4], tv1 = tvs[lane * 4 + 1], tv2 = tvs[lane * 4 + 2], tv3 = tvs[lane * 4 + 3];
    for (int rr = 0; rr < 16; rr++) {
        int row = wid * 16 + rr;
        float4 y1 = *(float4*)(accbuf + row * LDC + lane * 4);
        float4 y2 = *(float4*)(accbuf + row * LDC + 128 + lane * 4);
        float v0 = fmaxf(y1.x - alpha * y2.x + tv0, 0.f);
        float v1 = fmaxf(y1.y - alpha * y2.y + tv1, 0.f);
        float v2 = fmaxf(y1.z - alpha * y2.z + tv2, 0.f);
        float v3 = fmaxf(y1.w - alpha * y2.w + tv3, 0.f);
        float s = wredsum(v0 + v1 + v2 + v3);
        float sq = wredsum(v0 * v0 + v1 * v1 + v2 * v2 + v3 * v3);
        float mu = s * (1.0f / 128.0f);
        float var = fmaxf(sq * (1.0f / 128.0f) - mu * mu, 0.f);
        float rs = rsqrtf(var + EPSL);
        float x0 = (v0 - mu) * rs * tg0 + tb0;
        float x1 = (v1 - mu) * rs * tg1 + tb1;
        float x2 = (v2 - mu) * rs * tg2 + tb2;
        float x3 = (v3 - mu) * rs * tg3 + tb3;
        if (LAST) {
            *(float4*)(g_xf + (size_t)(row0 + row) * Cd + lane * 4) = make_float4(x0, x1, x2, x3);
        } else {
            __half2* op = (__half2*)(xout + (size_t)(row0 + row) * Cd + lane * 4);
            op[0] = __floats2half2_rn(x0, x1);
            op[1] = __floats2half2_rn(x2, x3);
            float mk = msk[row];
            cs0 += mk * x0; cs1 += mk * x1; cs2 += mk * x2; cs3 += mk * x3;
        }
    }
    if (!LAST) {
        atomicAdd(&sacc[lane * 4 + 0], cs0);
        atomicAdd(&sacc[lane * 4 + 1], cs1);
        atomicAdd(&sacc[lane * 4 + 2], cs2);
        atomicAdd(&sacc[lane * 4 + 3], cs3);
        __syncthreads();
        if (tid < 128) atomicAdd(&snext[b * Cd + tid], sacc[tid]);
    }
}

// ======================================================================
// K4: pooling (out rows 0..23) + mv_emb (row 25)
// ======================================================================
__global__ void k_pool(const float* __restrict__ ss, const float* __restrict__ Wsc,
                       const float* __restrict__ bsc, float* __restrict__ out) {
    __shared__ float ms[S3v];
    int b = blockIdx.x, c = threadIdx.x;
    for (int p = c; p < S3v; p += 128) ms[p] = g_m[b * S3v + p];
    __syncthreads();
    float aj[8], ak[8];
#pragma unroll
    for (int q = 0; q < 8; q++) { aj[q] = 0.f; ak[q] = 0.f; }
    const float* xb = g_xf + (size_t)b * S3v * Cd + c;
    for (int i = 0; i < 8; i++) {
        float ai = 0.f;
#pragma unroll
        for (int jk = 0; jk < 64; jk++) {
            int p = i * 64 + jk;
            float v = ms[p] * xb[(size_t)p * Cd];
            ai += v; aj[jk >> 3] += v; ak[jk & 7] += v;
        }
        out[((size_t)b * 26 + i) * Cd + c] = ai * 0.015625f;
    }
#pragma unroll
    for (int q = 0; q < 8; q++) {
        out[((size_t)b * 26 + 8 + q) * Cd + c] = aj[q] * 0.015625f;
        out[((size_t)b * 26 + 16 + q) * Cd + c] = ak[q] * 0.015625f;
    }
    out[((size_t)b * 26 + 25) * Cd + c] = fmaxf(ss[b] * Wsc[c] + bsc[c], 0.f);
}

// ======================================================================
// K5: generic fp16 GEMM  out[M,NT] = op(A[M,KT] @ W[NT,KT]^T + bias [+res])
// BM=128, BN=128, 256 threads (4 M x 2 N warps, warp tile 32x64)
// EPI: 0=bias, 1=bias+relu, 2=bias+residual.  ASRC: 0=float, 1=xx actions
// ======================================================================
#define GEMM_SMEM_BYTES (2 * 128 * LDAh * 2)
template <int NT, int KT, int EPI, int ASRC>
__global__ void __launch_bounds__(256, 1)
k_gemm(const void* __restrict__ Av, const float* __restrict__ W,
       const float* __restrict__ bias, const float* __restrict__ res,
       float* __restrict__ out) {
    extern __shared__ char smc[];
    __half* sW = (__half*)smc;
    __half* sA = (__half*)(smc + 128 * LDAh * 2);
    int tid = threadIdx.x;
    int row0 = blockIdx.x * 128, n0 = blockIdx.y * 128;
    int wid = tid >> 5, lane = tid & 31;
    int wm = wid & 3, wn = wid >> 2;
    int gid = lane >> 2, tig = lane & 3;

    float acc[2][8][4];
#pragma unroll
    for (int a0 = 0; a0 < 2; a0++)
#pragma unroll
        for (int a1 = 0; a1 < 8; a1++)
#pragma unroll
            for (int a2 = 0; a2 < 4; a2++) acc[a0][a1][a2] = 0.f;

    for (int kc = 0; kc < KT; kc += 128) {
        for (int u = tid; u < 4096; u += 256) {
            int n = u >> 5, c4 = (u & 31) << 2;
            float4 v = *(const float4*)(W + (size_t)(n0 + n) * KT + kc + c4);
            __half2* d = (__half2*)(sW + n * LDAh + c4);
            d[0] = __floats2half2_rn(v.x, v.y);
            d[1] = __floats2half2_rn(v.z, v.w);
        }
        if (ASRC == 0) {
            const float* A = (const float*)Av;
            for (int u = tid; u < 4096; u += 256) {
                int r = u >> 5, c4 = (u & 31) << 2;
                float4 v = *(const float4*)(A + (size_t)(row0 + r) * KT + kc + c4);
                __half2* d = (__half2*)(sA + r * LDAh + c4);
                d[0] = __floats2half2_rn(v.x, v.y);
                d[1] = __floats2half2_rn(v.z, v.w);
            }
        } else {
            const int* X = (const int*)Av;
            for (int u = tid; u < 4096; u += 256) {
                int r = u >> 5, c4 = (u & 31) << 2;
                int gr = row0 + r, bb = gr / 15, tt = gr - bb * 15;
                int4 v = *(const int4*)(X + ((size_t)bb * 16 + tt + 1) * 512 + kc + c4);
                __half2* d = (__half2*)(sA + r * LDAh + c4);
                d[0] = __floats2half2_rn((float)v.x, (float)v.y);
                d[1] = __floats2half2_rn((float)v.z, (float)v.w);
            }
        }
        __syncthreads();
#pragma unroll
        for (int ks = 0; ks < 128; ks += 16) {
            unsigned af[2][4], bf[8][2];
#pragma unroll
            for (int mf = 0; mf < 2; mf++) {
                const unsigned* p = (const unsigned*)(sA + (wm * 32 + mf * 16 + gid) * LDAh + ks);
                af[mf][0] = p[tig];
                af[mf][1] = p[tig + 4 * LDAh];
                af[mf][2] = p[tig + 4];
                af[mf][3] = p[tig + 4 * LDAh + 4];
            }
#pragma unroll
            for (int nf = 0; nf < 8; nf++) {
                const unsigned* p = (const unsigned*)(sW + (wn * 64 + nf * 8 + gid) * LDAh + ks);
                bf[nf][0] = p[tig];
                bf[nf][1] = p[tig + 4];
            }
#pragma unroll
            for (int mf = 0; mf < 2; mf++)
#pragma unroll
                for (int nf = 0; nf < 8; nf++)
                    mmaf16(acc[mf][nf], af[mf], bf[nf][0], bf[nf][1]);
        }
        __syncthreads();
    }
#pragma unroll
    for (int mf = 0; mf < 2; mf++)
#pragma unroll
        for (int nf = 0; nf < 8; nf++) {
            int gm = row0 + wm * 32 + mf * 16 + gid;
            int gn = n0 + wn * 64 + nf * 8 + tig * 2;
            float b0 = bias[gn], b1 = bias[gn + 1];
            float v00 = acc[mf][nf][0] + b0, v01 = acc[mf][nf][1] + b1;
            float v10 = acc[mf][nf][2] + b0, v11 = acc[mf][nf][3] + b1;
            if (EPI == 1) {
                v00 = fmaxf(v00, 0.f); v01 = fmaxf(v01, 0.f);
                v10 = fmaxf(v10, 0.f); v11 = fmaxf(v11, 0.f);
            }
            if (EPI == 2) {
                v00 += res[(size_t)gm * NT + gn];       v01 += res[(size_t)gm * NT + gn + 1];
                v10 += res[(size_t)(gm + 8) * NT + gn]; v11 += res[(size_t)(gm + 8) * NT + gn + 1];
            }
            *(float2*)(out + (size_t)gm * NT + gn) = make_float2(v00, v01);
            *(float2*)(out + (size_t)(gm + 8) * NT + gn) = make_float2(v10, v11);
        }
}

// ======================================================================
// K6: LayerNorm rows of (RT,128): warp per row
// ======================================================================
__global__ void k_ln(const float* __restrict__ a, const float* __restrict__ g,
                     const float* __restrict__ bb, float* __restrict__ h) {
    int row = blockIdx.x * 8 + (threadIdx.x >> 5);
    int lane = threadIdx.x & 31;
    float4 v = *(const float4*)(a + (size_t)row * 128 + lane * 4);
    float s = wredsum(v.x + v.y + v.z + v.w);
    float sq = wredsum(v.x * v.x + v.y * v.y + v.z * v.z + v.w * v.w);
    float mu = s * (1.0f / 128.0f);
    float var = fmaxf(sq * (1.0f / 128.0f) - mu * mu, 0.f);
    float rs = rsqrtf(var + EPSL);
    float4 o;
    o.x = (v.x - mu) * rs * g[lane * 4 + 0] + bb[lane * 4 + 0];
    o.y = (v.y - mu) * rs * g[lane * 4 + 1] + bb[lane * 4 + 1];
    o.z = (v.z - mu) * rs * g[lane * 4 + 2] + bb[lane * 4 + 2];
    o.w = (v.w - mu) * rs * g[lane * 4 + 3] + bb[lane * 4 + 3];
    *(float4*)(h + (size_t)row * 128 + lane * 4) = o;
}

// ======================================================================
// K7: attention. block = batch, warp = head. T=15, Hd=32.
// ======================================================================
__global__ void k_attn(const float* __restrict__ qkv, float* __restrict__ o) {
    __shared__ float sq[4][15 * 33], sk[4][15 * 33], sv[4][15 * 33];
    int b = blockIdx.x, w = threadIdx.x >> 5, lane = threadIdx.x & 31;
    for (int idx = lane; idx < 480; idx += 32) {
        int t = idx >> 5, d = idx & 31;
        const float* base = qkv + (size_t)(b * 15 + t) * 384 + w * 32 + d;
        sq[w][t * 33 + d] = base[0];
        sk[w][t * 33 + d] = base[128];
        sv[w][t * 33 + d] = base[256];
    }
    __syncwarp();
    if (lane < 15) {
        float qr[32];
#pragma unroll
        for (int d = 0; d < 32; d++) qr[d] = sq[w][lane * 33 + d];
        float sc[15];
        float mx = -1e30f;
#pragma unroll
        for (int tk = 0; tk < 15; tk++) {
            float a = 0.f;
#pragma unroll
            for (int d = 0; d < 32; d++) a += qr[d] * sk[w][tk * 33 + d];
            sc[tk] = a * 0.17677669529663687f;
            mx = fmaxf(mx, sc[tk]);
        }
        float ssum = 0.f;
#pragma unroll
        for (int tk = 0; tk < 15; tk++) { sc[tk] = expf(sc[tk] - mx); ssum += sc[tk]; }
        float inv = 1.0f / ssum;
        float od[32];
#pragma unroll
        for (int d = 0; d < 32; d++) od[d] = 0.f;
#pragma unroll
        for (int tk = 0; tk < 15; tk++) {
            float p = sc[tk] * inv;
#pragma unroll
            for (int d = 0; d < 32; d++) od[d] += p * sv[w][tk * 33 + d];
        }
        float* op = o + (size_t)(b * 15 + lane) * 128 + w * 32;
#pragma unroll
        for (int d4 = 0; d4 < 32; d4 += 4)
            *(float4*)(op + d4) = make_float4(od[d4], od[d4 + 1], od[d4 + 2], od[d4 + 3]);
    }
}

// ======================================================================
// K8: act_emb = mean over 15 rows -> out row 24
// ======================================================================
__global__ void k_amean(const float* __restrict__ a, float* __restrict__ out) {
    int b = blockIdx.x, c = threadIdx.x;
    float s = 0.f;
#pragma unroll
    for (int t = 0; t < 15; t++) s += a[(size_t)(b * 15 + t) * 128 + c];
    out[((size_t)b * 26 + 24) * 128 + c] = s * (1.0f / 15.0f);
}

// ======================================================================
// host launcher
// ======================================================================
extern "C" void kernel_launch(void* const* d_in, const int* in_sizes, int n_in,
                              void* d_out, int out_size) {
    const int*   xx    = (const int*)d_in[0];
    const float* ss    = (const float*)d_in[1];
    const float* Win   = (const float*)d_in[2];
    const float* b_in  = (const float*)d_in[3];
    const float* Wl    = (const float*)d_in[4];
    const float* bl    = (const float*)d_in[5];
    const float* Wr    = (const float*)d_in[6];
    const float* ln_g  = (const float*)d_in[7];
    const float* ln_b  = (const float*)d_in[8];
    const float* Wqkv  = (const float*)d_in[9];
    const float* bqkv  = (const float*)d_in[10];
    const float* Wo    = (const float*)d_in[11];
    const float* bo    = (const float*)d_in[12];
    const float* ln1_g = (const float*)d_in[13];
    const float* ln1_b = (const float*)d_in[14];
    const float* ln2_g = (const float*)d_in[15];
    const float* ln2_b = (const float*)d_in[16];
    const float* W1    = (const float*)d_in[17];
    const float* b1    = (const float*)d_in[18];
    const float* W2    = (const float*)d_in[19];
    const float* b2    = (const float*)d_in[20];
    const float* Wact  = (const float*)d_in[21];
    const float* bact  = (const float*)d_in[22];
    const float* Wsc   = (const float*)d_in[23];
    const float* bsc   = (const float*)d_in[24];
    float* out = (float*)d_out;

    void *pxh0, *pxh1, *pWh, *ps0, *ps1, *ps2, *pa, *ph, *pqkv, *po, *pf;
    cudaGetSymbolAddress(&pxh0, g_xh0);
    cudaGetSymbolAddress(&pxh1, g_xh1);
    cudaGetSymbolAddress(&pWh, g_Wh);
    cudaGetSymbolAddress(&ps0, g_s0);
    cudaGetSymbolAddress(&ps1, g_s1);
    cudaGetSymbolAddress(&ps2, g_s2);
    cudaGetSymbolAddress(&pa, g_a);
    cudaGetSymbolAddress(&ph, g_h);
    cudaGetSymbolAddress(&pqkv, g_qkv);
    cudaGetSymbolAddress(&po, g_o);
    cudaGetSymbolAddress(&pf, g_f);

    cudaFuncSetAttribute(k_gnn<0>, cudaFuncAttributeMaxDynamicSharedMemorySize, GNN_SMEM_BYTES);
    cudaFuncSetAttribute(k_gnn<1>, cudaFuncAttributeMaxDynamicSharedMemorySize, GNN_SMEM_BYTES);
    cudaFuncSetAttribute(k_gemm<128, 512, 0, 1>, cudaFuncAttributeMaxDynamicSharedMemorySize, GEMM_SMEM_BYTES);
    cudaFuncSetAttribute(k_gemm<384, 128, 0, 0>, cudaFuncAttributeMaxDynamicSharedMemorySize, GEMM_SMEM_BYTES);
    cudaFuncSetAttribute(k_gemm<128, 128, 2, 0>, cudaFuncAttributeMaxDynamicSharedMemorySize, GEMM_SMEM_BYTES);
    cudaFuncSetAttribute(k_gemm<512, 128, 1, 0>, cudaFuncAttributeMaxDynamicSharedMemorySize, GEMM_SMEM_BYTES);
    cudaFuncSetAttribute(k_gemm<128, 512, 2, 0>, cudaFuncAttributeMaxDynamicSharedMemorySize, GEMM_SMEM_BYTES);

    __half* Xh[2] = {(__half*)pxh0, (__half*)pxh1};
    const __half* Whp = (const __half*)pWh;
    float* Sv[3] = {(float*)ps0, (float*)ps1, (float*)ps2};
    float* a = (float*)pa; float* h = (float*)ph; float* qkv = (float*)pqkv;
    float* o = (float*)po; float* f = (float*)pf;

    // launch order arranged so launch #6 (ncu -s 5 -c 1) = k_gnn layer 0
    k_init<<<Bsz, 128>>>(xx, ss, Win, b_in);                                        // 1
    k_gemm<128, 512, 0, 1><<<dim3(RT / 128, 1), 256, GEMM_SMEM_BYTES>>>(xx, Wact, bact, nullptr, a); // 2
    k_ln<<<RT / 8, 256>>>(a, ln1_g, ln1_b, h);                                      // 3
    k_gemm<384, 128, 0, 0><<<dim3(RT / 128, 3), 256, GEMM_SMEM_BYTES>>>(h, Wqkv, bqkv, nullptr, qkv); // 4
    k_wconv<<<96, 256>>>(Wr, Wl);                                                   // 5
    k_gnn<0><<<Mrows / 128, 256, GNN_SMEM_BYTES>>>(Xh[0], Whp, bl, Sv[0],           // 6  <- profiled
                                                   ln_g, ln_b, Xh[1], Sv[1]);
    k_gnn<0><<<Mrows / 128, 256, GNN_SMEM_BYTES>>>(Xh[1], Whp + 32768, bl + 128, Sv[1],
                                                   ln_g, ln_b, Xh[0], Sv[2]);
    k_gnn<1><<<Mrows / 128, 256, GNN_SMEM_BYTES>>>(Xh[0], Whp + 65536, bl + 256, Sv[2],
                                                   ln_g, ln_b, Xh[1], nullptr);
    k_pool<<<Bsz, 128>>>(ss, Wsc, bsc, out);

    // transformer continues (layer 0 attn onward, then layer 1)
    k_attn<<<Bsz, 128>>>(qkv, o);
    k_gemm<128, 128, 2, 0><<<dim3(RT / 128, 1), 256, GEMM_SMEM_BYTES>>>(o, Wo, bo, a, a);
    k_ln<<<RT / 8, 256>>>(a, ln2_g, ln2_b, h);
    k_gemm<512, 128, 1, 0><<<dim3(RT / 128, 4), 256, GEMM_SMEM_BYTES>>>(h, W1, b1, nullptr, f);
    k_gemm<128, 512, 2, 0><<<dim3(RT / 128, 1), 256, GEMM_SMEM_BYTES>>>(f, W2, b2, a, a);
    {
        int l = 1;
        k_ln<<<RT / 8, 256>>>(a, ln1_g + l * 128, ln1_b + l * 128, h);
        k_gemm<384, 128, 0, 0><<<dim3(RT / 128, 3), 256, GEMM_SMEM_BYTES>>>(h, Wqkv + l * 49152,
                                                                            bqkv + l * 384, nullptr, qkv);
        k_attn<<<Bsz, 128>>>(qkv, o);
        k_gemm<128, 128, 2, 0><<<dim3(RT / 128, 1), 256, GEMM_SMEM_BYTES>>>(o, Wo + l * 16384,
                                                                            bo + l * 128, a, a);
        k_ln<<<RT / 8, 256>>>(a, ln2_g + l * 128, ln2_b + l * 128, h);
        k_gemm<512, 128, 1, 0><<<dim3(RT / 128, 4), 256, GEMM_SMEM_BYTES>>>(h, W1 + l * 65536,
                                                                            b1 + l * 512, nullptr, f);
        k_gemm<128, 512, 2, 0><<<dim3(RT / 128, 1), 256, GEMM_SMEM_BYTES>>>(f, W2 + l * 65536,
                                                                            b2 + l * 128, a, a);
    }
    k_amean<<<Bsz, 128>>>(a, out);
}

// round 4
// speedup vs baseline: 2.3165x; 1.7446x over previous
#include <cuda_runtime.h>
#include <cuda_fp16.h>
#include <cstdint>
#include <cstddef>

#define Bsz  512
#define S3v  512
#define Cd   128
#define Mrows (Bsz * S3v)
#define EPSL 1e-5f
#define RT   7680
#define LDAh 136   // halves per staged row (272B, 16B aligned, conflict-free frags)

// ---------------- device scratch ----------------
__device__ __half g_xh0[(size_t)Mrows * Cd];
__device__ __half g_xh1[(size_t)Mrows * Cd];
__device__ __half g_Wg[3 * 256 * 128];        // GNN [Wr;Wl] fp16
__device__ __half g_Wqkvh[2 * 384 * 128];
__device__ __half g_Woh[2 * 128 * 128];
__device__ __half g_W1h[2 * 512 * 128];
__device__ __half g_W2h[2 * 128 * 512];
__device__ __half g_Wacth[128 * 512];
__device__ float g_s0[Bsz * Cd];
__device__ float g_s1[Bsz * Cd];
__device__ float g_s2[Bsz * Cd];
__device__ float g_alpha[Bsz];
__device__ float g_m[Mrows];
__device__ float g_a[(size_t)RT * 128];
__device__ __half g_h[(size_t)RT * 128];
__device__ float g_qkv[(size_t)RT * 384];
__device__ __half g_o[(size_t)RT * 128];
__device__ __half g_f[(size_t)RT * 512];

// ---------------- helpers ----------------
__device__ __forceinline__ void mmaf16(float* d, const unsigned* a, unsigned b0, unsigned b1) {
    asm("mma.sync.aligned.m16n8k16.row.col.f32.f16.f16.f32 "
        "{%0,%1,%2,%3},{%4,%5,%6,%7},{%8,%9},{%0,%1,%2,%3};"
        : "+f"(d[0]), "+f"(d[1]), "+f"(d[2]), "+f"(d[3])
        : "r"(a[0]), "r"(a[1]), "r"(a[2]), "r"(a[3]), "r"(b0), "r"(b1));
}
__device__ __forceinline__ float shred2(float v) {   // reduce over tig (lane bits 0,1)
    v += __shfl_xor_sync(0xffffffffu, v, 1);
    v += __shfl_xor_sync(0xffffffffu, v, 2);
    return v;
}
__device__ __forceinline__ float shredg(float v) {   // reduce over gid (lane bits 2,3,4)
    v += __shfl_xor_sync(0xffffffffu, v, 4);
    v += __shfl_xor_sync(0xffffffffu, v, 8);
    v += __shfl_xor_sync(0xffffffffu, v, 16);
    return v;
}

// ======================================================================
// K_wtf: convert all weights fp32 -> fp16 (GNN concat + transformer)
// 544 blocks x 256 threads x 4 elems = 557056 elems
// ======================================================================
__global__ void k_wtf(const float* __restrict__ Wr, const float* __restrict__ Wl,
                      const float* __restrict__ Wqkv, const float* __restrict__ Wo,
                      const float* __restrict__ W1, const float* __restrict__ W2,
                      const float* __restrict__ Wact) {
    int idx = (blockIdx.x * 256 + threadIdx.x) * 4;
    const float* src;
    __half2* dst;
    if (idx < 98304) {
        int l = idx >> 15, r = (idx >> 7) & 255, k = idx & 127;
        src = (r < 128) ? (Wr + l * 16384 + r * 128 + k) : (Wl + l * 16384 + (r - 128) * 128 + k);
        dst = (__half2*)(g_Wg + idx);
    } else if (idx < 196608) { int j = idx - 98304;  src = Wqkv + j; dst = (__half2*)(g_Wqkvh + j); }
    else if (idx < 229376)   { int j = idx - 196608; src = Wo + j;   dst = (__half2*)(g_Woh + j); }
    else if (idx < 360448)   { int j = idx - 229376; src = W1 + j;   dst = (__half2*)(g_W1h + j); }
    else if (idx < 491520)   { int j = idx - 360448; src = W2 + j;   dst = (__half2*)(g_W2h + j); }
    else                     { int j = idx - 491520; src = Wact + j; dst = (__half2*)(g_Wacth + j); }
    float4 v = *(const float4*)src;
    dst[0] = __floats2half2_rn(v.x, v.y);
    dst[1] = __floats2half2_rn(v.z, v.w);
}

// ======================================================================
// K_init: features + lin_in (fp16) + mask + masked colsum + alpha
// 512 threads = 4 p-phases x 128 channels. Also zeros s1,s2 and out row 24.
// ======================================================================
__global__ void k_init(const int* __restrict__ xx, const float* __restrict__ ss,
                       const float* __restrict__ Win, const float* __restrict__ b_in,
                       float* __restrict__ out) {
    __shared__ float ssm4[4][128];
    __shared__ int nct[4];
    int b = blockIdx.x, tid = threadIdx.x;
    int ph = tid >> 7, c = tid & 127;
    float w0 = Win[c * 5 + 0], w1 = Win[c * 5 + 1], w2 = Win[c * 5 + 2];
    float w3 = Win[c * 5 + 3], w4 = Win[c * 5 + 4];
    float base = (ss[b] * 0.125f) * w4 + b_in[c];
    const int* fp = xx + (size_t)b * 16 * S3v;
    const float inv7 = 1.0f / 7.0f;
    float ssum = 0.f; int ncnt = 0;
    for (int i = 0; i < 128; i++) {
        int p = i * 4 + ph;
        int f = fp[p];
        int ii = p >> 6, jj = (p >> 3) & 7, kk = p & 7;
        float val = base + (float)ii * inv7 * w0 + (float)jj * inv7 * w1 +
                    (float)kk * inv7 * w2 + (float)f * 0.5f * w3;
        g_xh0[((size_t)b * S3v + p) * Cd + c] = __float2half_rn(val);
        if (f != 0) { ssum += val; ncnt++; }
        if (c == 0) g_m[b * S3v + p] = (f != 0) ? 1.0f : 0.0f;
    }
    ssm4[ph][c] = ssum;
    if (c == 0) nct[ph] = ncnt;
    __syncthreads();
    if (tid < 128) {
        float s = ssm4[0][tid] + ssm4[1][tid] + ssm4[2][tid] + ssm4[3][tid];
        g_s0[b * Cd + tid] = s;
        g_s1[b * Cd + tid] = 0.f;
        g_s2[b * Cd + tid] = 0.f;
        out[((size_t)b * 26 + 24) * Cd + tid] = 0.f;
    }
    if (tid == 0) {
        int n = nct[0] + nct[1] + nct[2] + nct[3];
        g_alpha[b] = (n > 1) ? 1.0f / (float)(n - 1) : 0.f;
    }
}

// ======================================================================
// K_gnn: persistent GNN layer. grid=148, block=256.
// W staged once; A tiles double-buffered via cp.async; register epilogue.
// Warp layout 2(M) x 4(N-pairs): warp (wm,wn) computes rows wm*64..+63,
// cols wn*32..+31 of BOTH y1 (n) and y2 (n+128).
// ======================================================================
#define GNN_DSMEM (69632 + 2 * 34816 + 8192)
__global__ void __launch_bounds__(256, 1)
k_gnn(const __half* __restrict__ xin, const __half* __restrict__ Wh_l,
      const float* __restrict__ bl_l, const float* __restrict__ sin_,
      const float* __restrict__ ln_g, const float* __restrict__ ln_b,
      __half* __restrict__ xout, float* __restrict__ snext, int last) {
    extern __shared__ char smc[];
    __half* W = (__half*)smc;                               // 256 x LDAh
    __half* Ab[2] = { (__half*)(smc + 69632), (__half*)(smc + 69632 + 34816) };
    float* fx  = (float*)(smc + 139264);
    float* ssm = fx;          float* tvs = fx + 128;
    float* gsh = fx + 256;    float* bsh = fx + 384;
    float* msk = fx + 512;    float* sacc = fx + 640;
    float* mus = fx + 768;    float* rss = fx + 896;
    float* redS = fx + 1024;  float* redQ = fx + 1536;      // [128][4]

    int tid = threadIdx.x, wid = tid >> 5, lane = tid & 31;
    int wm = wid & 1, wn = wid >> 1;
    int gid = lane >> 2, tig = lane & 3;

    // stage W once
    {
        const uint4* src = (const uint4*)Wh_l;
        for (int u = tid; u < 4096; u += 256) {
            int n = u >> 4, j = u & 15;
            ((uint4*)(W + n * LDAh))[j] = src[u];
        }
    }
    if (tid < 128) { gsh[tid] = ln_g[tid]; bsh[tid] = ln_b[tid]; }

    // prefetch tile 0
    {
        uint32_t s0 = (uint32_t)__cvta_generic_to_shared(Ab[0]);
        const __half* src = xin + (size_t)blockIdx.x * 128 * Cd;
        for (int u = tid; u < 2048; u += 256) {
            int r = u >> 4, j = u & 15;
            uint32_t d = s0 + (uint32_t)(r * LDAh + j * 8) * 2;
            asm volatile("cp.async.ca.shared.global [%0], [%1], 16;\n" :: "r"(d), "l"(src + r * Cd + j * 8));
        }
        asm volatile("cp.async.commit_group;\n");
    }

    int bufi = 0;
    for (int t = blockIdx.x; t < 2048; t += gridDim.x) {
        int row0 = t * 128, b = row0 >> 9;
        float alpha = g_alpha[b];
        if (tid < 128) {
            ssm[tid] = sin_[b * Cd + tid];
            msk[tid] = g_m[row0 + tid];
            sacc[tid] = 0.f;
        }
        asm volatile("cp.async.wait_group 0;\n");
        __syncthreads();
        // prefetch next tile into other buffer
        int nt = t + gridDim.x;
        if (nt < 2048) {
            uint32_t s0 = (uint32_t)__cvta_generic_to_shared(Ab[bufi ^ 1]);
            const __half* src = xin + (size_t)nt * 128 * Cd;
            for (int u = tid; u < 2048; u += 256) {
                int r = u >> 4, j = u & 15;
                uint32_t d = s0 + (uint32_t)(r * LDAh + j * 8) * 2;
                asm volatile("cp.async.ca.shared.global [%0], [%1], 16;\n" :: "r"(d), "l"(src + r * Cd + j * 8));
            }
            asm volatile("cp.async.commit_group;\n");
        }
        // tv[c] = alpha * sum_k s[k]*Wl[c][k] + bl[c]
        if (tid < 128) {
            const __half2* wr2 = (const __half2*)(W + (128 + tid) * LDAh);
            float acc = 0.f;
#pragma unroll 16
            for (int k2 = 0; k2 < 64; k2++) {
                float2 w = __half22float2(wr2[k2]);
                acc += ssm[k2 * 2] * w.x + ssm[k2 * 2 + 1] * w.y;
            }
            tvs[tid] = alpha * acc + bl_l[tid];
        }
        __syncthreads();

        const __half* A = Ab[bufi];
        float acc[4][8][4];
#pragma unroll
        for (int a0 = 0; a0 < 4; a0++)
#pragma unroll
            for (int a1 = 0; a1 < 8; a1++)
#pragma unroll
                for (int a2 = 0; a2 < 4; a2++) acc[a0][a1][a2] = 0.f;

#pragma unroll
        for (int ks = 0; ks < Cd; ks += 16) {
            unsigned af[4][4], bf[8][2];
#pragma unroll
            for (int mf = 0; mf < 4; mf++) {
                const unsigned* p = (const unsigned*)(A + (wm * 64 + mf * 16 + gid) * LDAh + ks);
                af[mf][0] = p[tig]; af[mf][1] = p[tig + 4 * LDAh];
                af[mf][2] = p[tig + 4]; af[mf][3] = p[tig + 4 * LDAh + 4];
            }
#pragma unroll
            for (int nf = 0; nf < 8; nf++) {
                int n = (nf < 4) ? (wn * 32 + nf * 8 + gid) : (128 + wn * 32 + (nf - 4) * 8 + gid);
                const unsigned* p = (const unsigned*)(W + n * LDAh + ks);
                bf[nf][0] = p[tig]; bf[nf][1] = p[tig + 4];
            }
#pragma unroll
            for (int mf = 0; mf < 4; mf++)
#pragma unroll
                for (int nf = 0; nf < 8; nf++)
                    mmaf16(acc[mf][nf], af[mf], bf[nf][0], bf[nf][1]);
        }

        // ---- epilogue in registers ----
        // v = relu(y1 - alpha*y2 + tv), overwrite acc[mf][nf<4]
#pragma unroll
        for (int mf = 0; mf < 4; mf++)
#pragma unroll
            for (int nf = 0; nf < 4; nf++) {
                int col = wn * 32 + nf * 8 + 2 * tig;
                float tv0 = tvs[col], tv1 = tvs[col + 1];
#pragma unroll
                for (int rp = 0; rp < 2; rp++) {
                    float v0 = acc[mf][nf][rp * 2]     - alpha * acc[mf][nf + 4][rp * 2]     + tv0;
                    float v1 = acc[mf][nf][rp * 2 + 1] - alpha * acc[mf][nf + 4][rp * 2 + 1] + tv1;
                    acc[mf][nf][rp * 2]     = fmaxf(v0, 0.f);
                    acc[mf][nf][rp * 2 + 1] = fmaxf(v1, 0.f);
                }
            }
        // row sums over this warp's 32 cols
#pragma unroll
        for (int mf = 0; mf < 4; mf++)
#pragma unroll
            for (int rp = 0; rp < 2; rp++) {
                float s = 0.f, q = 0.f;
#pragma unroll
                for (int nf = 0; nf < 4; nf++) {
                    float v0 = acc[mf][nf][rp * 2], v1 = acc[mf][nf][rp * 2 + 1];
                    s += v0 + v1; q += v0 * v0 + v1 * v1;
                }
                s = shred2(s); q = shred2(q);
                if (tig == 0) {
                    int r = wm * 64 + mf * 16 + rp * 8 + gid;
                    redS[r * 4 + wn] = s;
                    redQ[r * 4 + wn] = q;
                }
            }
        __syncthreads();
        if (tid < 128) {
            float s = redS[tid * 4] + redS[tid * 4 + 1] + redS[tid * 4 + 2] + redS[tid * 4 + 3];
            float q = redQ[tid * 4] + redQ[tid * 4 + 1] + redQ[tid * 4 + 2] + redQ[tid * 4 + 3];
            float mu = s * (1.0f / 128.0f);
            float var = fmaxf(q * (1.0f / 128.0f) - mu * mu, 0.f);
            mus[tid] = mu;
            rss[tid] = rsqrtf(var + EPSL);
        }
        __syncthreads();
        float csum[4][2];
#pragma unroll
        for (int nf = 0; nf < 4; nf++) { csum[nf][0] = 0.f; csum[nf][1] = 0.f; }
#pragma unroll
        for (int mf = 0; mf < 4; mf++)
#pragma unroll
            for (int rp = 0; rp < 2; rp++) {
                int r = wm * 64 + mf * 16 + rp * 8 + gid;
                float mu = mus[r], rs = rss[r], mk = msk[r];
#pragma unroll
                for (int nf = 0; nf < 4; nf++) {
                    int col = wn * 32 + nf * 8 + 2 * tig;
                    float x0 = (acc[mf][nf][rp * 2]     - mu) * rs * gsh[col] + bsh[col];
                    float x1 = (acc[mf][nf][rp * 2 + 1] - mu) * rs * gsh[col + 1] + bsh[col + 1];
                    *(__half2*)(xout + (size_t)(row0 + r) * Cd + col) = __floats2half2_rn(x0, x1);
                    csum[nf][0] += mk * x0;
                    csum[nf][1] += mk * x1;
                }
            }
        if (!last) {
#pragma unroll
            for (int nf = 0; nf < 4; nf++) {
                csum[nf][0] = shredg(csum[nf][0]);
                csum[nf][1] = shredg(csum[nf][1]);
            }
            if (gid == 0) {
#pragma unroll
                for (int nf = 0; nf < 4; nf++) {
                    int col = wn * 32 + nf * 8 + 2 * tig;
                    atomicAdd(&sacc[col], csum[nf][0]);
                    atomicAdd(&sacc[col + 1], csum[nf][1]);
                }
            }
            __syncthreads();
            if (tid < 128) atomicAdd(&snext[b * Cd + tid], sacc[tid]);
        }
        __syncthreads();
        bufi ^= 1;
    }
}

// ======================================================================
// K_pool: pooling (rows 0..23) + mv_emb (row 25); reads fp16 x
// ======================================================================
__global__ void k_pool(const float* __restrict__ ss, const float* __restrict__ Wsc,
                       const float* __restrict__ bsc, float* __restrict__ out) {
    __shared__ float ms[S3v];
    int b = blockIdx.x, c = threadIdx.x;
    for (int p = c; p < S3v; p += 128) ms[p] = g_m[b * S3v + p];
    __syncthreads();
    float aj[8], ak[8];
#pragma unroll
    for (int q = 0; q < 8; q++) { aj[q] = 0.f; ak[q] = 0.f; }
    const __half* xb = g_xh1 + (size_t)b * S3v * Cd + c;
    for (int i = 0; i < 8; i++) {
        float ai = 0.f;
#pragma unroll
        for (int jk = 0; jk < 64; jk++) {
            int p = i * 64 + jk;
            float v = ms[p] * __half2float(xb[(size_t)p * Cd]);
            ai += v; aj[jk >> 3] += v; ak[jk & 7] += v;
        }
        out[((size_t)b * 26 + i) * Cd + c] = ai * 0.015625f;
    }
#pragma unroll
    for (int q = 0; q < 8; q++) {
        out[((size_t)b * 26 + 8 + q) * Cd + c] = aj[q] * 0.015625f;
        out[((size_t)b * 26 + 16 + q) * Cd + c] = ak[q] * 0.015625f;
    }
    out[((size_t)b * 26 + 25) * Cd + c] = fmaxf(ss[b] * Wsc[c] + bsc[c], 0.f);
}

// ======================================================================
// K_gemm: fp16 GEMM, BM=64, BN=128, 256 thr (2 M x 4 N warps, tile 32x32)
// EPI: 0 bias->fp32 | 1 bias+relu->fp16 | 2 bias+res+LN->a,h | 3 bias+LN->a,h
//      4 bias+res+amean atomics -> out row 24
// ASRC: 0 = fp16 global A, 1 = int xx actions
// ======================================================================
#define GEMM_DSMEM ((128 + 64) * LDAh * 2)
template <int NT, int KT, int EPI, int ASRC>
__global__ void __launch_bounds__(256, 2)
k_gemm(const void* __restrict__ Av, const __half* __restrict__ Wg,
       const float* __restrict__ bias, const float* __restrict__ res,
       void* __restrict__ outv, __half* __restrict__ hout,
       const float* __restrict__ lng, const float* __restrict__ lnb) {
    extern __shared__ char smc[];
    __half* sW = (__half*)smc;                   // 128 x LDAh
    __half* sA = (__half*)(smc + 128 * LDAh * 2);
    __shared__ float redS[64][4], redQ[64][4], mus[64], rss[64];
    int tid = threadIdx.x, wid = tid >> 5, lane = tid & 31;
    int wm = wid & 1, wn = wid >> 1;
    int gid = lane >> 2, tig = lane & 3;
    int row0 = blockIdx.x * 64, n0 = blockIdx.y * 128;

    float acc[2][4][4];
#pragma unroll
    for (int a0 = 0; a0 < 2; a0++)
#pragma unroll
        for (int a1 = 0; a1 < 4; a1++)
#pragma unroll
            for (int a2 = 0; a2 < 4; a2++) acc[a0][a1][a2] = 0.f;

    for (int kc = 0; kc < KT; kc += 128) {
        for (int u = tid; u < 2048; u += 256) {
            int n = u >> 4, j = u & 15;
            ((uint4*)(sW + n * LDAh))[j] = ((const uint4*)(Wg + (size_t)(n0 + n) * KT + kc))[j];
        }
        if (ASRC == 0) {
            const __half* A = (const __half*)Av;
            for (int u = tid; u < 1024; u += 256) {
                int r = u >> 4, j = u & 15;
                ((uint4*)(sA + r * LDAh))[j] = ((const uint4*)(A + (size_t)(row0 + r) * KT + kc))[j];
            }
        } else {
            const int* X = (const int*)Av;
            for (int u = tid; u < 2048; u += 256) {
                int r = u >> 5, j = u & 31;
                int gr = row0 + r, bb = gr / 15, tt = gr - bb * 15;
                int4 v = ((const int4*)(X + ((size_t)bb * 16 + tt + 1) * 512 + kc))[j];
                __half2* d = (__half2*)(sA + r * LDAh + j * 4);
                d[0] = __floats2half2_rn((float)v.x, (float)v.y);
                d[1] = __floats2half2_rn((float)v.z, (float)v.w);
            }
        }
        __syncthreads();
#pragma unroll
        for (int ks = 0; ks < 128; ks += 16) {
            unsigned af[2][4], bf[4][2];
#pragma unroll
            for (int mf = 0; mf < 2; mf++) {
                const unsigned* p = (const unsigned*)(sA + (wm * 32 + mf * 16 + gid) * LDAh + ks);
                af[mf][0] = p[tig]; af[mf][1] = p[tig + 4 * LDAh];
                af[mf][2] = p[tig + 4]; af[mf][3] = p[tig + 4 * LDAh + 4];
            }
#pragma unroll
            for (int nf = 0; nf < 4; nf++) {
                const unsigned* p = (const unsigned*)(sW + (wn * 32 + nf * 8 + gid) * LDAh + ks);
                bf[nf][0] = p[tig]; bf[nf][1] = p[tig + 4];
            }
#pragma unroll
            for (int mf = 0; mf < 2; mf++)
#pragma unroll
                for (int nf = 0; nf < 4; nf++)
                    mmaf16(acc[mf][nf], af[mf], bf[nf][0], bf[nf][1]);
        }
        __syncthreads();
    }

    int gnb = n0 + wn * 32 + tig * 2;
    float2 b2[4];
#pragma unroll
    for (int nf = 0; nf < 4; nf++) b2[nf] = *(const float2*)(bias + gnb + nf * 8);

    if (EPI == 0) {
        float* out = (float*)outv;
#pragma unroll
        for (int mf = 0; mf < 2; mf++)
#pragma unroll
            for (int rp = 0; rp < 2; rp++) {
                int gm = row0 + wm * 32 + mf * 16 + rp * 8 + gid;
#pragma unroll
                for (int nf = 0; nf < 4; nf++)
                    *(float2*)(out + (size_t)gm * NT + gnb + nf * 8) =
                        make_float2(acc[mf][nf][rp * 2] + b2[nf].x, acc[mf][nf][rp * 2 + 1] + b2[nf].y);
            }
    } else if (EPI == 1) {
        __half* out = (__half*)outv;
#pragma unroll
        for (int mf = 0; mf < 2; mf++)
#pragma unroll
            for (int rp = 0; rp < 2; rp++) {
                int gm = row0 + wm * 32 + mf * 16 + rp * 8 + gid;
#pragma unroll
                for (int nf = 0; nf < 4; nf++) {
                    float v0 = fmaxf(acc[mf][nf][rp * 2] + b2[nf].x, 0.f);
                    float v1 = fmaxf(acc[mf][nf][rp * 2 + 1] + b2[nf].y, 0.f);
                    *(__half2*)(out + (size_t)gm * NT + gnb + nf * 8) = __floats2half2_rn(v0, v1);
                }
            }
    } else if (EPI == 4) {
        float* out = (float*)outv;
#pragma unroll
        for (int mf = 0; mf < 2; mf++)
#pragma unroll
            for (int rp = 0; rp < 2; rp++) {
                int gm = row0 + wm * 32 + mf * 16 + rp * 8 + gid;
                int bb = gm / 15;
                float* dst = out + ((size_t)bb * 26 + 24) * 128 + gnb;
#pragma unroll
                for (int nf = 0; nf < 4; nf++) {
                    float2 r2 = *(const float2*)(res + (size_t)gm * 128 + gnb + nf * 8);
                    float v0 = acc[mf][nf][rp * 2] + b2[nf].x + r2.x;
                    float v1 = acc[mf][nf][rp * 2 + 1] + b2[nf].y + r2.y;
                    atomicAdd(dst + nf * 8, v0 * (1.0f / 15.0f));
                    atomicAdd(dst + nf * 8 + 1, v1 * (1.0f / 15.0f));
                }
            }
    } else {  // EPI 2/3: bias (+res) -> a, then LN -> h
        float* aout = (float*)outv;
        float2 lg2[4], lb2[4];
#pragma unroll
        for (int nf = 0; nf < 4; nf++) {
            lg2[nf] = *(const float2*)(lng + gnb + nf * 8);
            lb2[nf] = *(const float2*)(lnb + gnb + nf * 8);
        }
#pragma unroll
        for (int mf = 0; mf < 2; mf++)
#pragma unroll
            for (int rp = 0; rp < 2; rp++) {
                int gm = row0 + wm * 32 + mf * 16 + rp * 8 + gid;
#pragma unroll
                for (int nf = 0; nf < 4; nf++) {
                    float rx = 0.f, ry = 0.f;
                    if (EPI == 2) {
                        float2 r2 = *(const float2*)(res + (size_t)gm * 128 + gnb + nf * 8);
                        rx = r2.x; ry = r2.y;
                    }
                    float v0 = acc[mf][nf][rp * 2] + b2[nf].x + rx;
                    float v1 = acc[mf][nf][rp * 2 + 1] + b2[nf].y + ry;
                    acc[mf][nf][rp * 2] = v0;
                    acc[mf][nf][rp * 2 + 1] = v1;
                    *(float2*)(aout + (size_t)gm * 128 + gnb + nf * 8) = make_float2(v0, v1);
                }
            }
#pragma unroll
        for (int mf = 0; mf < 2; mf++)
#pragma unroll
            for (int rp = 0; rp < 2; rp++) {
                float s = 0.f, q = 0.f;
#pragma unroll
                for (int nf = 0; nf < 4; nf++) {
                    float v0 = acc[mf][nf][rp * 2], v1 = acc[mf][nf][rp * 2 + 1];
                    s += v0 + v1; q += v0 * v0 + v1 * v1;
                }
                s = shred2(s); q = shred2(q);
                if (tig == 0) {
                    int r = wm * 32 + mf * 16 + rp * 8 + gid;
                    redS[r][wn] = s; redQ[r][wn] = q;
                }
            }
        __syncthreads();
        if (tid < 64) {
            float s = redS[tid][0] + redS[tid][1] + redS[tid][2] + redS[tid][3];
            float q = redQ[tid][0] + redQ[tid][1] + redQ[tid][2] + redQ[tid][3];
            float mu = s * (1.0f / 128.0f);
            float var = fmaxf(q * (1.0f / 128.0f) - mu * mu, 0.f);
            mus[tid] = mu; rss[tid] = rsqrtf(var + EPSL);
        }
        __syncthreads();
#pragma unroll
        for (int mf = 0; mf < 2; mf++)
#pragma unroll
            for (int rp = 0; rp < 2; rp++) {
                int r = wm * 32 + mf * 16 + rp * 8 + gid;
                int gm = row0 + r;
                float mu = mus[r], rs = rss[r];
#pragma unroll
                for (int nf = 0; nf < 4; nf++) {
                    float x0 = (acc[mf][nf][rp * 2] - mu) * rs * lg2[nf].x + lb2[nf].x;
                    float x1 = (acc[mf][nf][rp * 2 + 1] - mu) * rs * lg2[nf].y + lb2[nf].y;
                    *(__half2*)(hout + (size_t)gm * 128 + gnb + nf * 8) = __floats2half2_rn(x0, x1);
                }
            }
    }
}

// ======================================================================
// K_attn: block=batch, warp=head. qkv fp32 in, o fp16 out.
// ======================================================================
__global__ void k_attn(const float* __restrict__ qkv, __half* __restrict__ o) {
    __shared__ float sq[4][15 * 33], sk[4][15 * 33], sv[4][15 * 33];
    int b = blockIdx.x, w = threadIdx.x >> 5, lane = threadIdx.x & 31;
    for (int idx = lane; idx < 480; idx += 32) {
        int t = idx >> 5, d = idx & 31;
        const float* base = qkv + (size_t)(b * 15 + t) * 384 + w * 32 + d;
        sq[w][t * 33 + d] = base[0];
        sk[w][t * 33 + d] = base[128];
        sv[w][t * 33 + d] = base[256];
    }
    __syncwarp();
    if (lane < 15) {
        float qr[32];
#pragma unroll
        for (int d = 0; d < 32; d++) qr[d] = sq[w][lane * 33 + d];
        float sc[15];
        float mx = -1e30f;
#pragma unroll
        for (int tk = 0; tk < 15; tk++) {
            float a = 0.f;
#pragma unroll
            for (int d = 0; d < 32; d++) a += qr[d] * sk[w][tk * 33 + d];
            sc[tk] = a * 0.17677669529663687f;
            mx = fmaxf(mx, sc[tk]);
        }
        float ssum = 0.f;
#pragma unroll
        for (int tk = 0; tk < 15; tk++) { sc[tk] = expf(sc[tk] - mx); ssum += sc[tk]; }
        float inv = 1.0f / ssum;
        float od[32];
#pragma unroll
        for (int d = 0; d < 32; d++) od[d] = 0.f;
#pragma unroll
        for (int tk = 0; tk < 15; tk++) {
            float p = sc[tk] * inv;
#pragma unroll
            for (int d = 0; d < 32; d++) od[d] += p * sv[w][tk * 33 + d];
        }
        __half* op = o + (size_t)(b * 15 + lane) * 128 + w * 32;
#pragma unroll
        for (int d2 = 0; d2 < 16; d2++)
            ((__half2*)op)[d2] = __floats2half2_rn(od[d2 * 2], od[d2 * 2 + 1]);
    }
}

// ======================================================================
// host launcher
// ======================================================================
extern "C" void kernel_launch(void* const* d_in, const int* in_sizes, int n_in,
                              void* d_out, int out_size) {
    const int*   xx    = (const int*)d_in[0];
    const float* ss    = (const float*)d_in[1];
    const float* Win   = (const float*)d_in[2];
    const float* b_in  = (const float*)d_in[3];
    const float* Wl    = (const float*)d_in[4];
    const float* bl    = (const float*)d_in[5];
    const float* Wr    = (const float*)d_in[6];
    const float* ln_g  = (const float*)d_in[7];
    const float* ln_b  = (const float*)d_in[8];
    const float* Wqkv  = (const float*)d_in[9];
    const float* bqkv  = (const float*)d_in[10];
    const float* Wo    = (const float*)d_in[11];
    const float* bo    = (const float*)d_in[12];
    const float* ln1_g = (const float*)d_in[13];
    const float* ln1_b = (const float*)d_in[14];
    const float* ln2_g = (const float*)d_in[15];
    const float* ln2_b = (const float*)d_in[16];
    const float* W1    = (const float*)d_in[17];
    const float* b1    = (const float*)d_in[18];
    const float* W2    = (const float*)d_in[19];
    const float* b2    = (const float*)d_in[20];
    const float* Wact  = (const float*)d_in[21];
    const float* bact  = (const float*)d_in[22];
    const float* Wsc   = (const float*)d_in[23];
    const float* bsc   = (const float*)d_in[24];
    float* out = (float*)d_out;

    void *pxh0, *pxh1, *pWg, *pWqkvh, *pWoh, *pW1h, *pW2h, *pWacth;
    void *ps0, *ps1, *ps2, *pa, *ph, *pqkv, *po, *pf;
    cudaGetSymbolAddress(&pxh0, g_xh0);
    cudaGetSymbolAddress(&pxh1, g_xh1);
    cudaGetSymbolAddress(&pWg, g_Wg);
    cudaGetSymbolAddress(&pWqkvh, g_Wqkvh);
    cudaGetSymbolAddress(&pWoh, g_Woh);
    cudaGetSymbolAddress(&pW1h, g_W1h);
    cudaGetSymbolAddress(&pW2h, g_W2h);
    cudaGetSymbolAddress(&pWacth, g_Wacth);
    cudaGetSymbolAddress(&ps0, g_s0);
    cudaGetSymbolAddress(&ps1, g_s1);
    cudaGetSymbolAddress(&ps2, g_s2);
    cudaGetSymbolAddress(&pa, g_a);
    cudaGetSymbolAddress(&ph, g_h);
    cudaGetSymbolAddress(&pqkv, g_qkv);
    cudaGetSymbolAddress(&po, g_o);
    cudaGetSymbolAddress(&pf, g_f);

    cudaFuncSetAttribute(k_gnn, cudaFuncAttributeMaxDynamicSharedMemorySize, GNN_DSMEM);
    cudaFuncSetAttribute(k_gemm<128, 512, 3, 1>, cudaFuncAttributeMaxDynamicSharedMemorySize, GEMM_DSMEM);
    cudaFuncSetAttribute(k_gemm<384, 128, 0, 0>, cudaFuncAttributeMaxDynamicSharedMemorySize, GEMM_DSMEM);
    cudaFuncSetAttribute(k_gemm<128, 128, 2, 0>, cudaFuncAttributeMaxDynamicSharedMemorySize, GEMM_DSMEM);
    cudaFuncSetAttribute(k_gemm<512, 128, 1, 0>, cudaFuncAttributeMaxDynamicSharedMemorySize, GEMM_DSMEM);
    cudaFuncSetAttribute(k_gemm<128, 512, 2, 0>, cudaFuncAttributeMaxDynamicSharedMemorySize, GEMM_DSMEM);
    cudaFuncSetAttribute(k_gemm<128, 512, 4, 0>, cudaFuncAttributeMaxDynamicSharedMemorySize, GEMM_DSMEM);

    __half* Xh[2] = {(__half*)pxh0, (__half*)pxh1};
    const __half* Wgp = (const __half*)pWg;
    float* Sv[3] = {(float*)ps0, (float*)ps1, (float*)ps2};
    float* a = (float*)pa; __half* h = (__half*)ph; float* qkv = (float*)pqkv;
    __half* o = (__half*)po; __half* f = (__half*)pf;

    // 1
    k_wtf<<<544, 256>>>(Wr, Wl, Wqkv, Wo, W1, W2, Wact);
    // 2
    k_init<<<Bsz, 512>>>(xx, ss, Win, b_in, out);
    // 3: action embed + LN1(l0) fused
    k_gemm<128, 512, 3, 1><<<dim3(120, 1), 256, GEMM_DSMEM>>>(
        xx, (const __half*)pWacth, bact, nullptr, a, h, ln1_g, ln1_b);
    // 4,5,6: GNN layers (persistent)   <- launch #4 profiled
    k_gnn<<<148, 256, GNN_DSMEM>>>(Xh[0], Wgp, bl, Sv[0], ln_g, ln_b, Xh[1], Sv[1], 0);
    k_gnn<<<148, 256, GNN_DSMEM>>>(Xh[1], Wgp + 32768, bl + 128, Sv[1], ln_g, ln_b, Xh[0], Sv[2], 0);
    k_gnn<<<148, 256, GNN_DSMEM>>>(Xh[0], Wgp + 65536, bl + 256, Sv[2], ln_g, ln_b, Xh[1], nullptr, 1);
    // 7
    k_pool<<<Bsz, 128>>>(ss, Wsc, bsc, out);

    for (int l = 0; l < 2; l++) {
        const __half* wq = (const __half*)pWqkvh + l * 49152;
        const __half* wo = (const __half*)pWoh + l * 16384;
        const __half* w1 = (const __half*)pW1h + l * 65536;
        const __half* w2 = (const __half*)pW2h + l * 65536;
        k_gemm<384, 128, 0, 0><<<dim3(120, 3), 256, GEMM_DSMEM>>>(
            h, wq, bqkv + l * 384, nullptr, qkv, nullptr, nullptr, nullptr);
        k_attn<<<Bsz, 128>>>(qkv, o);
        // Wo + residual + LN2(l)
        k_gemm<128, 128, 2, 0><<<dim3(120, 1), 256, GEMM_DSMEM>>>(
            o, wo, bo + l * 128, a, a, h, ln2_g + l * 128, ln2_b + l * 128);
        // W1 + relu -> f
        k_gemm<512, 128, 1, 0><<<dim3(120, 4), 256, GEMM_DSMEM>>>(
            h, w1, b1 + l * 512, nullptr, f, nullptr, nullptr, nullptr);
        if (l == 0) {
            // W2 + residual + LN1(l1)
            k_gemm<128, 512, 2, 0><<<dim3(120, 1), 256, GEMM_DSMEM>>>(
                f, w2, b2, a, a, h, ln1_g + 128, ln1_b + 128);
        } else {
            // W2 + residual + fused mean -> out row 24
            k_gemm<128, 512, 4, 0><<<dim3(120, 1), 256, GEMM_DSMEM>>>(
                f, w2, b2 + 128, a, out, nullptr, nullptr, nullptr);
        }
    }
}

// round 5
// speedup vs baseline: 2.4906x; 1.0752x over previous
#include <cuda_runtime.h>
#include <cuda_fp16.h>
#include <cstdint>
#include <cstddef>

#define Bsz  512
#define S3v  512
#define Cd   128
#define Mrows (Bsz * S3v)
#define EPSL 1e-5f
#define RT   7680
#define LDAh 136   // halves per staged row (272B, 16B aligned, conflict-free frags)

// ---------------- device scratch ----------------
__device__ __half g_xh0[(size_t)Mrows * Cd];
__device__ __half g_xh1[(size_t)Mrows * Cd];
__device__ __half g_Wg[3 * 256 * 128];        // GNN [Wr;Wl] fp16
__device__ __half g_Wqkvh[2 * 384 * 128];
__device__ __half g_Woh[2 * 128 * 128];
__device__ __half g_W1h[2 * 512 * 128];
__device__ __half g_W2h[2 * 128 * 512];
__device__ __half g_Wacth[128 * 512];
__device__ float g_s0[Bsz * Cd];
__device__ float g_s1[Bsz * Cd];
__device__ float g_s2[Bsz * Cd];
__device__ float g_alpha[Bsz];
__device__ float g_m[Mrows];
__device__ float g_a[(size_t)RT * 128];
__device__ __half g_h[(size_t)RT * 128];
__device__ __half g_qkv[(size_t)RT * 384];
__device__ __half g_o[(size_t)RT * 128];
__device__ __half g_f[(size_t)RT * 512];

// ---------------- helpers ----------------
__device__ __forceinline__ void mmaf16(float* d, const unsigned* a, unsigned b0, unsigned b1) {
    asm("mma.sync.aligned.m16n8k16.row.col.f32.f16.f16.f32 "
        "{%0,%1,%2,%3},{%4,%5,%6,%7},{%8,%9},{%0,%1,%2,%3};"
        : "+f"(d[0]), "+f"(d[1]), "+f"(d[2]), "+f"(d[3])
        : "r"(a[0]), "r"(a[1]), "r"(a[2]), "r"(a[3]), "r"(b0), "r"(b1));
}
__device__ __forceinline__ float shred2(float v) {   // reduce over tig (lane bits 0,1)
    v += __shfl_xor_sync(0xffffffffu, v, 1);
    v += __shfl_xor_sync(0xffffffffu, v, 2);
    return v;
}
__device__ __forceinline__ float shredg(float v) {   // reduce over gid (lane bits 2,3,4)
    v += __shfl_xor_sync(0xffffffffu, v, 4);
    v += __shfl_xor_sync(0xffffffffu, v, 8);
    v += __shfl_xor_sync(0xffffffffu, v, 16);
    return v;
}
__device__ __forceinline__ void cpa16(void* dst_smem, const void* src) {
    uint32_t d = (uint32_t)__cvta_generic_to_shared(dst_smem);
    asm volatile("cp.async.ca.shared.global [%0], [%1], 16;\n" :: "r"(d), "l"(src));
}

// ======================================================================
// K_wtf: convert all weights fp32 -> fp16
// ======================================================================
__global__ void k_wtf(const float* __restrict__ Wr, const float* __restrict__ Wl,
                      const float* __restrict__ Wqkv, const float* __restrict__ Wo,
                      const float* __restrict__ W1, const float* __restrict__ W2,
                      const float* __restrict__ Wact) {
    int idx = (blockIdx.x * 256 + threadIdx.x) * 4;
    const float* src;
    __half2* dst;
    if (idx < 98304) {
        int l = idx >> 15, r = (idx >> 7) & 255, k = idx & 127;
        src = (r < 128) ? (Wr + l * 16384 + r * 128 + k) : (Wl + l * 16384 + (r - 128) * 128 + k);
        dst = (__half2*)(g_Wg + idx);
    } else if (idx < 196608) { int j = idx - 98304;  src = Wqkv + j; dst = (__half2*)(g_Wqkvh + j); }
    else if (idx < 229376)   { int j = idx - 196608; src = Wo + j;   dst = (__half2*)(g_Woh + j); }
    else if (idx < 360448)   { int j = idx - 229376; src = W1 + j;   dst = (__half2*)(g_W1h + j); }
    else if (idx < 491520)   { int j = idx - 360448; src = W2 + j;   dst = (__half2*)(g_W2h + j); }
    else                     { int j = idx - 491520; src = Wact + j; dst = (__half2*)(g_Wacth + j); }
    float4 v = *(const float4*)src;
    dst[0] = __floats2half2_rn(v.x, v.y);
    dst[1] = __floats2half2_rn(v.z, v.w);
}

// ======================================================================
// K_init
// ======================================================================
__global__ void k_init(const int* __restrict__ xx, const float* __restrict__ ss,
                       const float* __restrict__ Win, const float* __restrict__ b_in,
                       float* __restrict__ out) {
    __shared__ float ssm4[4][128];
    __shared__ int nct[4];
    int b = blockIdx.x, tid = threadIdx.x;
    int ph = tid >> 7, c = tid & 127;
    float w0 = Win[c * 5 + 0], w1 = Win[c * 5 + 1], w2 = Win[c * 5 + 2];
    float w3 = Win[c * 5 + 3], w4 = Win[c * 5 + 4];
    float base = (ss[b] * 0.125f) * w4 + b_in[c];
    const int* fp = xx + (size_t)b * 16 * S3v;
    const float inv7 = 1.0f / 7.0f;
    float ssum = 0.f; int ncnt = 0;
    for (int i = 0; i < 128; i++) {
        int p = i * 4 + ph;
        int f = fp[p];
        int ii = p >> 6, jj = (p >> 3) & 7, kk = p & 7;
        float val = base + (float)ii * inv7 * w0 + (float)jj * inv7 * w1 +
                    (float)kk * inv7 * w2 + (float)f * 0.5f * w3;
        g_xh0[((size_t)b * S3v + p) * Cd + c] = __float2half_rn(val);
        if (f != 0) { ssum += val; ncnt++; }
        if (c == 0) g_m[b * S3v + p] = (f != 0) ? 1.0f : 0.0f;
    }
    ssm4[ph][c] = ssum;
    if (c == 0) nct[ph] = ncnt;
    __syncthreads();
    if (tid < 128) {
        float s = ssm4[0][tid] + ssm4[1][tid] + ssm4[2][tid] + ssm4[3][tid];
        g_s0[b * Cd + tid] = s;
        g_s1[b * Cd + tid] = 0.f;
        g_s2[b * Cd + tid] = 0.f;
        out[((size_t)b * 26 + 24) * Cd + tid] = 0.f;
    }
    if (tid == 0) {
        int n = nct[0] + nct[1] + nct[2] + nct[3];
        g_alpha[b] = (n > 1) ? 1.0f / (float)(n - 1) : 0.f;
    }
}

// ======================================================================
// K_gnn: persistent. 512 threads (16 warps: 4M x 4N), warp tile 32x(32+32)
// ======================================================================
#define GNN_DSMEM (69632 + 69632 + 8192)
__global__ void __launch_bounds__(512, 1)
k_gnn(const __half* __restrict__ xin, const __half* __restrict__ Wh_l,
      const float* __restrict__ bl_l, const float* __restrict__ sin_,
      const float* __restrict__ ln_g, const float* __restrict__ ln_b,
      __half* __restrict__ xout, float* __restrict__ snext, int last) {
    extern __shared__ char smc[];
    __half* W = (__half*)smc;                               // 256 x LDAh
    __half* Ab[2] = { (__half*)(smc + 69632), (__half*)(smc + 69632 + 34816) };
    float* fx  = (float*)(smc + 139264);
    float* ssm = fx;          float* tvs = fx + 128;
    float* gsh = fx + 256;    float* bsh = fx + 384;
    float* msk = fx + 512;    float* sacc = fx + 640;
    float* mus = fx + 768;    float* rss = fx + 896;
    float* redS = fx + 1024;  float* redQ = fx + 1536;      // [128][4]

    int tid = threadIdx.x, wid = tid >> 5, lane = tid & 31;
    int wm = wid & 3, wn = wid >> 2;
    int gid = lane >> 2, tig = lane & 3;

    // stage W once
    {
        const uint4* src = (const uint4*)Wh_l;
        for (int u = tid; u < 4096; u += 512) {
            int n = u >> 4, j = u & 15;
            ((uint4*)(W + n * LDAh))[j] = src[u];
        }
    }
    if (tid < 128) { gsh[tid] = ln_g[tid]; bsh[tid] = ln_b[tid]; }

    // prefetch tile 0
    {
        const __half* src = xin + (size_t)blockIdx.x * 128 * Cd;
        for (int u = tid; u < 2048; u += 512) {
            int r = u >> 4, j = u & 15;
            cpa16(Ab[0] + r * LDAh + j * 8, src + r * Cd + j * 8);
        }
        asm volatile("cp.async.commit_group;\n");
    }

    int bufi = 0;
    for (int t = blockIdx.x; t < 2048; t += gridDim.x) {
        int row0 = t * 128, b = row0 >> 9;
        float alpha = g_alpha[b];
        // prefetch next tile (its buffer's previous compute finished last iter)
        int nt = t + gridDim.x;
        if (nt < 2048) {
            const __half* src = xin + (size_t)nt * 128 * Cd;
            for (int u = tid; u < 2048; u += 512) {
                int r = u >> 4, j = u & 15;
                cpa16(Ab[bufi ^ 1] + r * LDAh + j * 8, src + r * Cd + j * 8);
            }
            asm volatile("cp.async.commit_group;\n");
        }
        if (tid < 128) {
            ssm[tid] = sin_[b * Cd + tid];
            msk[tid] = g_m[row0 + tid];
            sacc[tid] = 0.f;
        }
        if (nt < 2048) asm volatile("cp.async.wait_group 1;\n");
        else           asm volatile("cp.async.wait_group 0;\n");
        __syncthreads();
        // tv[c] = alpha * sum_k s[k]*Wl[c][k] + bl[c]
        if (tid < 128) {
            const __half2* wr2 = (const __half2*)(W + (128 + tid) * LDAh);
            float acc2 = 0.f;
#pragma unroll 16
            for (int k2 = 0; k2 < 64; k2++) {
                float2 w = __half22float2(wr2[k2]);
                acc2 += ssm[k2 * 2] * w.x + ssm[k2 * 2 + 1] * w.y;
            }
            tvs[tid] = alpha * acc2 + bl_l[tid];
        }
        __syncthreads();

        const __half* A = Ab[bufi];
        float acc[2][8][4];
#pragma unroll
        for (int a0 = 0; a0 < 2; a0++)
#pragma unroll
            for (int a1 = 0; a1 < 8; a1++)
#pragma unroll
                for (int a2 = 0; a2 < 4; a2++) acc[a0][a1][a2] = 0.f;

#pragma unroll
        for (int ks = 0; ks < Cd; ks += 16) {
            unsigned af[2][4], bf[8][2];
#pragma unroll
            for (int mf = 0; mf < 2; mf++) {
                const unsigned* p = (const unsigned*)(A + (wm * 32 + mf * 16 + gid) * LDAh + ks);
                af[mf][0] = p[tig]; af[mf][1] = p[tig + 4 * LDAh];
                af[mf][2] = p[tig + 4]; af[mf][3] = p[tig + 4 * LDAh + 4];
            }
#pragma unroll
            for (int nf = 0; nf < 8; nf++) {
                int n = (nf < 4) ? (wn * 32 + nf * 8 + gid) : (128 + wn * 32 + (nf - 4) * 8 + gid);
                const unsigned* p = (const unsigned*)(W + n * LDAh + ks);
                bf[nf][0] = p[tig]; bf[nf][1] = p[tig + 4];
            }
#pragma unroll
            for (int mf = 0; mf < 2; mf++)
#pragma unroll
                for (int nf = 0; nf < 8; nf++)
                    mmaf16(acc[mf][nf], af[mf], bf[nf][0], bf[nf][1]);
        }

        // ---- epilogue ----
#pragma unroll
        for (int mf = 0; mf < 2; mf++)
#pragma unroll
            for (int nf = 0; nf < 4; nf++) {
                int col = wn * 32 + nf * 8 + 2 * tig;
                float tv0 = tvs[col], tv1 = tvs[col + 1];
#pragma unroll
                for (int rp = 0; rp < 2; rp++) {
                    float v0 = acc[mf][nf][rp * 2]     - alpha * acc[mf][nf + 4][rp * 2]     + tv0;
                    float v1 = acc[mf][nf][rp * 2 + 1] - alpha * acc[mf][nf + 4][rp * 2 + 1] + tv1;
                    acc[mf][nf][rp * 2]     = fmaxf(v0, 0.f);
                    acc[mf][nf][rp * 2 + 1] = fmaxf(v1, 0.f);
                }
            }
#pragma unroll
        for (int mf = 0; mf < 2; mf++)
#pragma unroll
            for (int rp = 0; rp < 2; rp++) {
                float s = 0.f, q = 0.f;
#pragma unroll
                for (int nf = 0; nf < 4; nf++) {
                    float v0 = acc[mf][nf][rp * 2], v1 = acc[mf][nf][rp * 2 + 1];
                    s += v0 + v1; q += v0 * v0 + v1 * v1;
                }
                s = shred2(s); q = shred2(q);
                if (tig == 0) {
                    int r = wm * 32 + mf * 16 + rp * 8 + gid;
                    redS[r * 4 + wn] = s;
                    redQ[r * 4 + wn] = q;
                }
            }
        __syncthreads();
        if (tid < 128) {
            float s = redS[tid * 4] + redS[tid * 4 + 1] + redS[tid * 4 + 2] + redS[tid * 4 + 3];
            float q = redQ[tid * 4] + redQ[tid * 4 + 1] + redQ[tid * 4 + 2] + redQ[tid * 4 + 3];
            float mu = s * (1.0f / 128.0f);
            float var = fmaxf(q * (1.0f / 128.0f) - mu * mu, 0.f);
            mus[tid] = mu;
            rss[tid] = rsqrtf(var + EPSL);
        }
        __syncthreads();
        float csum[4][2];
#pragma unroll
        for (int nf = 0; nf < 4; nf++) { csum[nf][0] = 0.f; csum[nf][1] = 0.f; }
#pragma unroll
        for (int mf = 0; mf < 2; mf++)
#pragma unroll
            for (int rp = 0; rp < 2; rp++) {
                int r = wm * 32 + mf * 16 + rp * 8 + gid;
                float mu = mus[r], rs = rss[r], mk = msk[r];
#pragma unroll
                for (int nf = 0; nf < 4; nf++) {
                    int col = wn * 32 + nf * 8 + 2 * tig;
                    float x0 = (acc[mf][nf][rp * 2]     - mu) * rs * gsh[col] + bsh[col];
                    float x1 = (acc[mf][nf][rp * 2 + 1] - mu) * rs * gsh[col + 1] + bsh[col + 1];
                    *(__half2*)(xout + (size_t)(row0 + r) * Cd + col) = __floats2half2_rn(x0, x1);
                    csum[nf][0] += mk * x0;
                    csum[nf][1] += mk * x1;
                }
            }
        if (!last) {
#pragma unroll
            for (int nf = 0; nf < 4; nf++) {
                csum[nf][0] = shredg(csum[nf][0]);
                csum[nf][1] = shredg(csum[nf][1]);
            }
            if (gid == 0) {
#pragma unroll
                for (int nf = 0; nf < 4; nf++) {
                    int col = wn * 32 + nf * 8 + 2 * tig;
                    atomicAdd(&sacc[col], csum[nf][0]);
                    atomicAdd(&sacc[col + 1], csum[nf][1]);
                }
            }
            __syncthreads();
            if (tid < 128) atomicAdd(&snext[b * Cd + tid], sacc[tid]);
        }
        __syncthreads();
        bufi ^= 1;
    }
}

// ======================================================================
// K_pool
// ======================================================================
__global__ void k_pool(const float* __restrict__ ss, const float* __restrict__ Wsc,
                       const float* __restrict__ bsc, float* __restrict__ out) {
    __shared__ float ms[S3v];
    int b = blockIdx.x, c = threadIdx.x;
    for (int p = c; p < S3v; p += 128) ms[p] = g_m[b * S3v + p];
    __syncthreads();
    float aj[8], ak[8];
#pragma unroll
    for (int q = 0; q < 8; q++) { aj[q] = 0.f; ak[q] = 0.f; }
    const __half* xb = g_xh1 + (size_t)b * S3v * Cd + c;
    for (int i = 0; i < 8; i++) {
        float ai = 0.f;
#pragma unroll
        for (int jk = 0; jk < 64; jk++) {
            int p = i * 64 + jk;
            float v = ms[p] * __half2float(xb[(size_t)p * Cd]);
            ai += v; aj[jk >> 3] += v; ak[jk & 7] += v;
        }
        out[((size_t)b * 26 + i) * Cd + c] = ai * 0.015625f;
    }
#pragma unroll
    for (int q = 0; q < 8; q++) {
        out[((size_t)b * 26 + 8 + q) * Cd + c] = aj[q] * 0.015625f;
        out[((size_t)b * 26 + 16 + q) * Cd + c] = ak[q] * 0.015625f;
    }
    out[((size_t)b * 26 + 25) * Cd + c] = fmaxf(ss[b] * Wsc[c] + bsc[c], 0.f);
}

// ======================================================================
// K_gemm: fp16 GEMM, BM=64, BN=128, 256 thr, cp.async double-buffered
// EPI: 0 bias->fp16 | 1 bias+relu->fp16 | 2 bias+res+LN->a,h | 3 bias+LN->a,h
//      4 bias+res+amean atomics
// ASRC: 0 = fp16 global A (pipelined), 1 = int xx actions (sync)
// ======================================================================
#define GEMM_DSMEM (2 * 34816 + 2 * 17408)
template <int NT, int KT, int EPI, int ASRC>
__global__ void __launch_bounds__(256, 2)
k_gemm(const void* __restrict__ Av, const __half* __restrict__ Wg,
       const float* __restrict__ bias, const float* __restrict__ res,
       void* __restrict__ outv, __half* __restrict__ hout,
       const float* __restrict__ lng, const float* __restrict__ lnb) {
    extern __shared__ char smc[];
    __half* sWb[2] = { (__half*)smc, (__half*)(smc + 34816) };
    __half* sAb[2] = { (__half*)(smc + 69632), (__half*)(smc + 69632 + 17408) };
    __shared__ float redS[64][4], redQ[64][4], mus[64], rss[64];
    int tid = threadIdx.x, wid = tid >> 5, lane = tid & 31;
    int wm = wid & 1, wn = wid >> 1;
    int gid = lane >> 2, tig = lane & 3;
    int row0 = blockIdx.x * 64, n0 = blockIdx.y * 128;
    constexpr int NST = KT / 128;

    float acc[2][4][4];
#pragma unroll
    for (int a0 = 0; a0 < 2; a0++)
#pragma unroll
        for (int a1 = 0; a1 < 4; a1++)
#pragma unroll
            for (int a2 = 0; a2 < 4; a2++) acc[a0][a1][a2] = 0.f;

    if (ASRC == 0) {
        const __half* A = (const __half*)Av;
        // prefetch stage 0
        for (int u = tid; u < 2048; u += 256) {
            int n = u >> 4, j = u & 15;
            cpa16(sWb[0] + n * LDAh + j * 8, Wg + (size_t)(n0 + n) * KT + j * 8);
        }
        for (int u = tid; u < 1024; u += 256) {
            int r = u >> 4, j = u & 15;
            cpa16(sAb[0] + r * LDAh + j * 8, A + (size_t)(row0 + r) * KT + j * 8);
        }
        asm volatile("cp.async.commit_group;\n");
#pragma unroll
        for (int s = 0; s < NST; s++) {
            if (s + 1 < NST) {
                int kc = (s + 1) * 128, bi = (s + 1) & 1;
                for (int u = tid; u < 2048; u += 256) {
                    int n = u >> 4, j = u & 15;
                    cpa16(sWb[bi] + n * LDAh + j * 8, Wg + (size_t)(n0 + n) * KT + kc + j * 8);
                }
                for (int u = tid; u < 1024; u += 256) {
                    int r = u >> 4, j = u & 15;
                    cpa16(sAb[bi] + r * LDAh + j * 8, A + (size_t)(row0 + r) * KT + kc + j * 8);
                }
                asm volatile("cp.async.commit_group;\n");
                asm volatile("cp.async.wait_group 1;\n");
            } else {
                asm volatile("cp.async.wait_group 0;\n");
            }
            __syncthreads();
            const __half* sW = sWb[s & 1];
            const __half* sA = sAb[s & 1];
#pragma unroll
            for (int ks = 0; ks < 128; ks += 16) {
                unsigned af[2][4], bf[4][2];
#pragma unroll
                for (int mf = 0; mf < 2; mf++) {
                    const unsigned* p = (const unsigned*)(sA + (wm * 32 + mf * 16 + gid) * LDAh + ks);
                    af[mf][0] = p[tig]; af[mf][1] = p[tig + 4 * LDAh];
                    af[mf][2] = p[tig + 4]; af[mf][3] = p[tig + 4 * LDAh + 4];
                }
#pragma unroll
                for (int nf = 0; nf < 4; nf++) {
                    const unsigned* p = (const unsigned*)(sW + (wn * 32 + nf * 8 + gid) * LDAh + ks);
                    bf[nf][0] = p[tig]; bf[nf][1] = p[tig + 4];
                }
#pragma unroll
                for (int mf = 0; mf < 2; mf++)
#pragma unroll
                    for (int nf = 0; nf < 4; nf++)
                        mmaf16(acc[mf][nf], af[mf], bf[nf][0], bf[nf][1]);
            }
            __syncthreads();
        }
    } else {
        const int* X = (const int*)Av;
        __half* sW = sWb[0];
        __half* sA = sAb[0];
        for (int kc = 0; kc < KT; kc += 128) {
            for (int u = tid; u < 2048; u += 256) {
                int n = u >> 4, j = u & 15;
                ((uint4*)(sW + n * LDAh))[j] = ((const uint4*)(Wg + (size_t)(n0 + n) * KT + kc))[j];
            }
            for (int u = tid; u < 2048; u += 256) {
                int r = u >> 5, j = u & 31;
                int gr = row0 + r, bb = gr / 15, tt = gr - bb * 15;
                int4 v = ((const int4*)(X + ((size_t)bb * 16 + tt + 1) * 512 + kc))[j];
                __half2* d = (__half2*)(sA + r * LDAh + j * 4);
                d[0] = __floats2half2_rn((float)v.x, (float)v.y);
                d[1] = __floats2half2_rn((float)v.z, (float)v.w);
            }
            __syncthreads();
#pragma unroll
            for (int ks = 0; ks < 128; ks += 16) {
                unsigned af[2][4], bf[4][2];
#pragma unroll
                for (int mf = 0; mf < 2; mf++) {
                    const unsigned* p = (const unsigned*)(sA + (wm * 32 + mf * 16 + gid) * LDAh + ks);
                    af[mf][0] = p[tig]; af[mf][1] = p[tig + 4 * LDAh];
                    af[mf][2] = p[tig + 4]; af[mf][3] = p[tig + 4 * LDAh + 4];
                }
#pragma unroll
                for (int nf = 0; nf < 4; nf++) {
                    const unsigned* p = (const unsigned*)(sW + (wn * 32 + nf * 8 + gid) * LDAh + ks);
                    bf[nf][0] = p[tig]; bf[nf][1] = p[tig + 4];
                }
#pragma unroll
                for (int mf = 0; mf < 2; mf++)
#pragma unroll
                    for (int nf = 0; nf < 4; nf++)
                        mmaf16(acc[mf][nf], af[mf], bf[nf][0], bf[nf][1]);
            }
            __syncthreads();
        }
    }

    int gnb = n0 + wn * 32 + tig * 2;
    float2 b2[4];
#pragma unroll
    for (int nf = 0; nf < 4; nf++) b2[nf] = *(const float2*)(bias + gnb + nf * 8);

    if (EPI == 0) {
        __half* out = (__half*)outv;
#pragma unroll
        for (int mf = 0; mf < 2; mf++)
#pragma unroll
            for (int rp = 0; rp < 2; rp++) {
                int gm = row0 + wm * 32 + mf * 16 + rp * 8 + gid;
#pragma unroll
                for (int nf = 0; nf < 4; nf++)
                    *(__half2*)(out + (size_t)gm * NT + gnb + nf * 8) =
                        __floats2half2_rn(acc[mf][nf][rp * 2] + b2[nf].x, acc[mf][nf][rp * 2 + 1] + b2[nf].y);
            }
    } else if (EPI == 1) {
        __half* out = (__half*)outv;
#pragma unroll
        for (int mf = 0; mf < 2; mf++)
#pragma unroll
            for (int rp = 0; rp < 2; rp++) {
                int gm = row0 + wm * 32 + mf * 16 + rp * 8 + gid;
#pragma unroll
                for (int nf = 0; nf < 4; nf++) {
                    float v0 = fmaxf(acc[mf][nf][rp * 2] + b2[nf].x, 0.f);
                    float v1 = fmaxf(acc[mf][nf][rp * 2 + 1] + b2[nf].y, 0.f);
                    *(__half2*)(out + (size_t)gm * NT + gnb + nf * 8) = __floats2half2_rn(v0, v1);
                }
            }
    } else if (EPI == 4) {
        float* out = (float*)outv;
#pragma unroll
        for (int mf = 0; mf < 2; mf++)
#pragma unroll
            for (int rp = 0; rp < 2; rp++) {
                int gm = row0 + wm * 32 + mf * 16 + rp * 8 + gid;
                int bb = gm / 15;
                float* dst = out + ((size_t)bb * 26 + 24) * 128 + gnb;
#pragma unroll
                for (int nf = 0; nf < 4; nf++) {
                    float2 r2 = *(const float2*)(res + (size_t)gm * 128 + gnb + nf * 8);
                    float v0 = acc[mf][nf][rp * 2] + b2[nf].x + r2.x;
                    float v1 = acc[mf][nf][rp * 2 + 1] + b2[nf].y + r2.y;
                    atomicAdd(dst + nf * 8, v0 * (1.0f / 15.0f));
                    atomicAdd(dst + nf * 8 + 1, v1 * (1.0f / 15.0f));
                }
            }
    } else {  // EPI 2/3: bias (+res) -> a, then LN -> h
        float* aout = (float*)outv;
        float2 lg2[4], lb2[4];
#pragma unroll
        for (int nf = 0; nf < 4; nf++) {
            lg2[nf] = *(const float2*)(lng + gnb + nf * 8);
            lb2[nf] = *(const float2*)(lnb + gnb + nf * 8);
        }
#pragma unroll
        for (int mf = 0; mf < 2; mf++)
#pragma unroll
            for (int rp = 0; rp < 2; rp++) {
                int gm = row0 + wm * 32 + mf * 16 + rp * 8 + gid;
#pragma unroll
                for (int nf = 0; nf < 4; nf++) {
                    float rx = 0.f, ry = 0.f;
                    if (EPI == 2) {
                        float2 r2 = *(const float2*)(res + (size_t)gm * 128 + gnb + nf * 8);
                        rx = r2.x; ry = r2.y;
                    }
                    float v0 = acc[mf][nf][rp * 2] + b2[nf].x + rx;
                    float v1 = acc[mf][nf][rp * 2 + 1] + b2[nf].y + ry;
                    acc[mf][nf][rp * 2] = v0;
                    acc[mf][nf][rp * 2 + 1] = v1;
                    *(float2*)(aout + (size_t)gm * 128 + gnb + nf * 8) = make_float2(v0, v1);
                }
            }
#pragma unroll
        for (int mf = 0; mf < 2; mf++)
#pragma unroll
            for (int rp = 0; rp < 2; rp++) {
                float s = 0.f, q = 0.f;
#pragma unroll
                for (int nf = 0; nf < 4; nf++) {
                    float v0 = acc[mf][nf][rp * 2], v1 = acc[mf][nf][rp * 2 + 1];
                    s += v0 + v1; q += v0 * v0 + v1 * v1;
                }
                s = shred2(s); q = shred2(q);
                if (tig == 0) {
                    int r = wm * 32 + mf * 16 + rp * 8 + gid;
                    redS[r][wn] = s; redQ[r][wn] = q;
                }
            }
        __syncthreads();
        if (tid < 64) {
            float s = redS[tid][0] + redS[tid][1] + redS[tid][2] + redS[tid][3];
            float q = redQ[tid][0] + redQ[tid][1] + redQ[tid][2] + redQ[tid][3];
            float mu = s * (1.0f / 128.0f);
            float var = fmaxf(q * (1.0f / 128.0f) - mu * mu, 0.f);
            mus[tid] = mu; rss[tid] = rsqrtf(var + EPSL);
        }
        __syncthreads();
#pragma unroll
        for (int mf = 0; mf < 2; mf++)
#pragma unroll
            for (int rp = 0; rp < 2; rp++) {
                int r = wm * 32 + mf * 16 + rp * 8 + gid;
                int gm = row0 + r;
                float mu = mus[r], rs = rss[r];
#pragma unroll
                for (int nf = 0; nf < 4; nf++) {
                    float x0 = (acc[mf][nf][rp * 2] - mu) * rs * lg2[nf].x + lb2[nf].x;
                    float x1 = (acc[mf][nf][rp * 2 + 1] - mu) * rs * lg2[nf].y + lb2[nf].y;
                    *(__half2*)(hout + (size_t)gm * 128 + gnb + nf * 8) = __floats2half2_rn(x0, x1);
                }
            }
    }
}

// ======================================================================
// K_attn: block=batch, warp=head. qkv fp16 in, o fp16 out.
// ======================================================================
__global__ void k_attn(const __half* __restrict__ qkv, __half* __restrict__ o) {
    __shared__ float sq[4][15 * 33], sk[4][15 * 33], sv[4][15 * 33];
    int b = blockIdx.x, w = threadIdx.x >> 5, lane = threadIdx.x & 31;
    for (int idx = lane; idx < 480; idx += 32) {
        int t = idx >> 5, d = idx & 31;
        const __half* base = qkv + (size_t)(b * 15 + t) * 384 + w * 32 + d;
        sq[w][t * 33 + d] = __half2float(base[0]);
        sk[w][t * 33 + d] = __half2float(base[128]);
        sv[w][t * 33 + d] = __half2float(base[256]);
    }
    __syncwarp();
    if (lane < 15) {
        float qr[32];
#pragma unroll
        for (int d = 0; d < 32; d++) qr[d] = sq[w][lane * 33 + d];
        float sc[15];
        float mx = -1e30f;
#pragma unroll
        for (int tk = 0; tk < 15; tk++) {
            float a = 0.f;
#pragma unroll
            for (int d = 0; d < 32; d++) a += qr[d] * sk[w][tk * 33 + d];
            sc[tk] = a * 0.17677669529663687f;
            mx = fmaxf(mx, sc[tk]);
        }
        float ssum = 0.f;
#pragma unroll
        for (int tk = 0; tk < 15; tk++) { sc[tk] = expf(sc[tk] - mx); ssum += sc[tk]; }
        float inv = 1.0f / ssum;
        float od[32];
#pragma unroll
        for (int d = 0; d < 32; d++) od[d] = 0.f;
#pragma unroll
        for (int tk = 0; tk < 15; tk++) {
            float p = sc[tk] * inv;
#pragma unroll
            for (int d = 0; d < 32; d++) od[d] += p * sv[w][tk * 33 + d];
        }
        __half* op = o + (size_t)(b * 15 + lane) * 128 + w * 32;
#pragma unroll
        for (int d2 = 0; d2 < 16; d2++)
            ((__half2*)op)[d2] = __floats2half2_rn(od[d2 * 2], od[d2 * 2 + 1]);
    }
}

// ======================================================================
// host launcher
// ======================================================================
extern "C" void kernel_launch(void* const* d_in, const int* in_sizes, int n_in,
                              void* d_out, int out_size) {
    const int*   xx    = (const int*)d_in[0];
    const float* ss    = (const float*)d_in[1];
    const float* Win   = (const float*)d_in[2];
    const float* b_in  = (const float*)d_in[3];
    const float* Wl    = (const float*)d_in[4];
    const float* bl    = (const float*)d_in[5];
    const float* Wr    = (const float*)d_in[6];
    const float* ln_g  = (const float*)d_in[7];
    const float* ln_b  = (const float*)d_in[8];
    const float* Wqkv  = (const float*)d_in[9];
    const float* bqkv  = (const float*)d_in[10];
    const float* Wo    = (const float*)d_in[11];
    const float* bo    = (const float*)d_in[12];
    const float* ln1_g = (const float*)d_in[13];
    const float* ln1_b = (const float*)d_in[14];
    const float* ln2_g = (const float*)d_in[15];
    const float* ln2_b = (const float*)d_in[16];
    const float* W1    = (const float*)d_in[17];
    const float* b1    = (const float*)d_in[18];
    const float* W2    = (const float*)d_in[19];
    const float* b2    = (const float*)d_in[20];
    const float* Wact  = (const float*)d_in[21];
    const float* bact  = (const float*)d_in[22];
    const float* Wsc   = (const float*)d_in[23];
    const float* bsc   = (const float*)d_in[24];
    float* out = (float*)d_out;

    void *pxh0, *pxh1, *pWg, *pWqkvh, *pWoh, *pW1h, *pW2h, *pWacth;
    void *ps0, *ps1, *ps2, *pa, *ph, *pqkv, *po, *pf;
    cudaGetSymbolAddress(&pxh0, g_xh0);
    cudaGetSymbolAddress(&pxh1, g_xh1);
    cudaGetSymbolAddress(&pWg, g_Wg);
    cudaGetSymbolAddress(&pWqkvh, g_Wqkvh);
    cudaGetSymbolAddress(&pWoh, g_Woh);
    cudaGetSymbolAddress(&pW1h, g_W1h);
    cudaGetSymbolAddress(&pW2h, g_W2h);
    cudaGetSymbolAddress(&pWacth, g_Wacth);
    cudaGetSymbolAddress(&ps0, g_s0);
    cudaGetSymbolAddress(&ps1, g_s1);
    cudaGetSymbolAddress(&ps2, g_s2);
    cudaGetSymbolAddress(&pa, g_a);
    cudaGetSymbolAddress(&ph, g_h);
    cudaGetSymbolAddress(&pqkv, g_qkv);
    cudaGetSymbolAddress(&po, g_o);
    cudaGetSymbolAddress(&pf, g_f);

    cudaFuncSetAttribute(k_gnn, cudaFuncAttributeMaxDynamicSharedMemorySize, GNN_DSMEM);
    cudaFuncSetAttribute(k_gemm<128, 512, 3, 1>, cudaFuncAttributeMaxDynamicSharedMemorySize, GEMM_DSMEM);
    cudaFuncSetAttribute(k_gemm<384, 128, 0, 0>, cudaFuncAttributeMaxDynamicSharedMemorySize, GEMM_DSMEM);
    cudaFuncSetAttribute(k_gemm<128, 128, 2, 0>, cudaFuncAttributeMaxDynamicSharedMemorySize, GEMM_DSMEM);
    cudaFuncSetAttribute(k_gemm<512, 128, 1, 0>, cudaFuncAttributeMaxDynamicSharedMemorySize, GEMM_DSMEM);
    cudaFuncSetAttribute(k_gemm<128, 512, 2, 0>, cudaFuncAttributeMaxDynamicSharedMemorySize, GEMM_DSMEM);
    cudaFuncSetAttribute(k_gemm<128, 512, 4, 0>, cudaFuncAttributeMaxDynamicSharedMemorySize, GEMM_DSMEM);

    __half* Xh[2] = {(__half*)pxh0, (__half*)pxh1};
    const __half* Wgp = (const __half*)pWg;
    float* Sv[3] = {(float*)ps0, (float*)ps1, (float*)ps2};
    float* a = (float*)pa; __half* h = (__half*)ph; __half* qkv = (__half*)pqkv;
    __half* o = (__half*)po; __half* f = (__half*)pf;

    k_wtf<<<544, 256>>>(Wr, Wl, Wqkv, Wo, W1, W2, Wact);
    k_init<<<Bsz, 512>>>(xx, ss, Win, b_in, out);
    k_gemm<128, 512, 3, 1><<<dim3(120, 1), 256, GEMM_DSMEM>>>(
        xx, (const __half*)pWacth, bact, nullptr, a, h, ln1_g, ln1_b);
    // launch #4 profiled
    k_gnn<<<148, 512, GNN_DSMEM>>>(Xh[0], Wgp, bl, Sv[0], ln_g, ln_b, Xh[1], Sv[1], 0);
    k_gnn<<<148, 512, GNN_DSMEM>>>(Xh[1], Wgp + 32768, bl + 128, Sv[1], ln_g, ln_b, Xh[0], Sv[2], 0);
    k_gnn<<<148, 512, GNN_DSMEM>>>(Xh[0], Wgp + 65536, bl + 256, Sv[2], ln_g, ln_b, Xh[1], nullptr, 1);
    k_pool<<<Bsz, 128>>>(ss, Wsc, bsc, out);

    for (int l = 0; l < 2; l++) {
        const __half* wq = (const __half*)pWqkvh + l * 49152;
        const __half* wo = (const __half*)pWoh + l * 16384;
        const __half* w1 = (const __half*)pW1h + l * 65536;
        const __half* w2 = (const __half*)pW2h + l * 65536;
        k_gemm<384, 128, 0, 0><<<dim3(120, 3), 256, GEMM_DSMEM>>>(
            h, wq, bqkv + l * 384, nullptr, qkv, nullptr, nullptr, nullptr);
        k_attn<<<Bsz, 128>>>(qkv, o);
        k_gemm<128, 128, 2, 0><<<dim3(120, 1), 256, GEMM_DSMEM>>>(
            o, wo, bo + l * 128, a, a, h, ln2_g + l * 128, ln2_b + l * 128);
        k_gemm<512, 128, 1, 0><<<dim3(120, 4), 256, GEMM_DSMEM>>>(
            h, w1, b1 + l * 512, nullptr, f, nullptr, nullptr, nullptr);
        if (l == 0) {
            k_gemm<128, 512, 2, 0><<<dim3(120, 1), 256, GEMM_DSMEM>>>(
                f, w2, b2, a, a, h, ln1_g + 128, ln1_b + 128);
        } else {
            k_gemm<128, 512, 4, 0><<<dim3(120, 1), 256, GEMM_DSMEM>>>(
                f, w2, b2 + 128, a, out, nullptr, nullptr, nullptr);
        }
    }
}

// round 6
// speedup vs baseline: 2.6206x; 1.0522x over previous
#include <cuda_runtime.h>
#include <cuda_fp16.h>
#include <cstdint>
#include <cstddef>

#define Bsz  512
#define S3v  512
#define Cd   128
#define Mrows (Bsz * S3v)
#define EPSL 1e-5f
#define RT   7680
#define LDAh 136   // halves per staged row (272B, 16B aligned)

// ---------------- device scratch ----------------
__device__ __half g_xh0[(size_t)Mrows * Cd];
__device__ __half g_xh1[(size_t)Mrows * Cd];
__device__ __half g_Wg[3 * 256 * 128];        // GNN [Wr;Wl] fp16
__device__ __half g_Wqkvh[2 * 384 * 128];
__device__ __half g_Woh[2 * 128 * 128];
__device__ __half g_W1h[2 * 512 * 128];
__device__ __half g_W2h[2 * 128 * 512];
__device__ __half g_Wacth[128 * 512];
__device__ float g_s0[Bsz * Cd];
__device__ float g_s1[Bsz * Cd];
__device__ float g_s2[Bsz * Cd];
__device__ float g_alpha[Bsz];
__device__ float g_m[Mrows];
__device__ float g_a[(size_t)RT * 128];
__device__ __half g_h[(size_t)RT * 128];
__device__ __half g_qkv[(size_t)RT * 384];
__device__ __half g_o[(size_t)RT * 128];
__device__ __half g_f[(size_t)RT * 512];

// ---------------- helpers ----------------
__device__ __forceinline__ void mmaf16(float* d, const unsigned* a, unsigned b0, unsigned b1) {
    asm("mma.sync.aligned.m16n8k16.row.col.f32.f16.f16.f32 "
        "{%0,%1,%2,%3},{%4,%5,%6,%7},{%8,%9},{%0,%1,%2,%3};"
        : "+f"(d[0]), "+f"(d[1]), "+f"(d[2]), "+f"(d[3])
        : "r"(a[0]), "r"(a[1]), "r"(a[2]), "r"(a[3]), "r"(b0), "r"(b1));
}
__device__ __forceinline__ void ldsm4(unsigned& r0, unsigned& r1, unsigned& r2, unsigned& r3,
                                      uint32_t addr) {
    asm volatile("ldmatrix.sync.aligned.m8n8.x4.shared.b16 {%0,%1,%2,%3}, [%4];"
                 : "=r"(r0), "=r"(r1), "=r"(r2), "=r"(r3) : "r"(addr));
}
__device__ __forceinline__ float shred2(float v) {
    v += __shfl_xor_sync(0xffffffffu, v, 1);
    v += __shfl_xor_sync(0xffffffffu, v, 2);
    return v;
}
__device__ __forceinline__ float shredg(float v) {
    v += __shfl_xor_sync(0xffffffffu, v, 4);
    v += __shfl_xor_sync(0xffffffffu, v, 8);
    v += __shfl_xor_sync(0xffffffffu, v, 16);
    return v;
}
__device__ __forceinline__ void cpa16(void* dst_smem, const void* src) {
    uint32_t d = (uint32_t)__cvta_generic_to_shared(dst_smem);
    asm volatile("cp.async.ca.shared.global [%0], [%1], 16;\n" :: "r"(d), "l"(src));
}

// ======================================================================
// K_wtf: weights fp32 -> fp16
// ======================================================================
__global__ void k_wtf(const float* __restrict__ Wr, const float* __restrict__ Wl,
                      const float* __restrict__ Wqkv, const float* __restrict__ Wo,
                      const float* __restrict__ W1, const float* __restrict__ W2,
                      const float* __restrict__ Wact) {
    int idx = (blockIdx.x * 256 + threadIdx.x) * 4;
    const float* src;
    __half2* dst;
    if (idx < 98304) {
        int l = idx >> 15, r = (idx >> 7) & 255, k = idx & 127;
        src = (r < 128) ? (Wr + l * 16384 + r * 128 + k) : (Wl + l * 16384 + (r - 128) * 128 + k);
        dst = (__half2*)(g_Wg + idx);
    } else if (idx < 196608) { int j = idx - 98304;  src = Wqkv + j; dst = (__half2*)(g_Wqkvh + j); }
    else if (idx < 229376)   { int j = idx - 196608; src = Wo + j;   dst = (__half2*)(g_Woh + j); }
    else if (idx < 360448)   { int j = idx - 229376; src = W1 + j;   dst = (__half2*)(g_W1h + j); }
    else if (idx < 491520)   { int j = idx - 360448; src = W2 + j;   dst = (__half2*)(g_W2h + j); }
    else                     { int j = idx - 491520; src = Wact + j; dst = (__half2*)(g_Wacth + j); }
    float4 v = *(const float4*)src;
    dst[0] = __floats2half2_rn(v.x, v.y);
    dst[1] = __floats2half2_rn(v.z, v.w);
}

// ======================================================================
// K_init
// ======================================================================
__global__ void k_init(const int* __restrict__ xx, const float* __restrict__ ss,
                       const float* __restrict__ Win, const float* __restrict__ b_in,
                       float* __restrict__ out) {
    __shared__ float ssm4[4][128];
    __shared__ int nct[4];
    int b = blockIdx.x, tid = threadIdx.x;
    int ph = tid >> 7, c = tid & 127;
    float w0 = Win[c * 5 + 0], w1 = Win[c * 5 + 1], w2 = Win[c * 5 + 2];
    float w3 = Win[c * 5 + 3], w4 = Win[c * 5 + 4];
    float base = (ss[b] * 0.125f) * w4 + b_in[c];
    const int* fp = xx + (size_t)b * 16 * S3v;
    const float inv7 = 1.0f / 7.0f;
    float ssum = 0.f; int ncnt = 0;
    for (int i = 0; i < 128; i++) {
        int p = i * 4 + ph;
        int f = fp[p];
        int ii = p >> 6, jj = (p >> 3) & 7, kk = p & 7;
        float val = base + (float)ii * inv7 * w0 + (float)jj * inv7 * w1 +
                    (float)kk * inv7 * w2 + (float)f * 0.5f * w3;
        g_xh0[((size_t)b * S3v + p) * Cd + c] = __float2half_rn(val);
        if (f != 0) { ssum += val; ncnt++; }
        if (c == 0) g_m[b * S3v + p] = (f != 0) ? 1.0f : 0.0f;
    }
    ssm4[ph][c] = ssum;
    if (c == 0) nct[ph] = ncnt;
    __syncthreads();
    if (tid < 128) {
        float s = ssm4[0][tid] + ssm4[1][tid] + ssm4[2][tid] + ssm4[3][tid];
        g_s0[b * Cd + tid] = s;
        g_s1[b * Cd + tid] = 0.f;
        g_s2[b * Cd + tid] = 0.f;
        out[((size_t)b * 26 + 24) * Cd + tid] = 0.f;
    }
    if (tid == 0) {
        int n = nct[0] + nct[1] + nct[2] + nct[3];
        g_alpha[b] = (n > 1) ? 1.0f / (float)(n - 1) : 0.f;
    }
}

// ======================================================================
// K_gnn: persistent, 256 thr, 2 CTAs/SM, BM=64, BN=256, ldmatrix frags.
// Warps 2(M)x4(N): warp tile 32 x (32 y1 + 32 y2).
// ======================================================================
#define GNN_DSMEM (69632 + 34816 + 5376)
__global__ void __launch_bounds__(256, 2)
k_gnn(const __half* __restrict__ xin, const __half* __restrict__ Wh_l,
      const float* __restrict__ bl_l, const float* __restrict__ sin_,
      const float* __restrict__ ln_g, const float* __restrict__ ln_b,
      __half* __restrict__ xout, float* __restrict__ snext, int last) {
    extern __shared__ char smc[];
    __half* W = (__half*)smc;                      // 256 x LDAh
    __half* Ab0 = (__half*)(smc + 69632);          // 2 x 64 x LDAh
    float* fx = (float*)(smc + 69632 + 34816);
    float* ssm = fx;        float* tvs = fx + 128;
    float* gsh = fx + 256;  float* bsh = fx + 384;
    float* msk = fx + 512;  float* sacc = fx + 576;
    float* mus = fx + 704;  float* rss = fx + 768;
    float* redS = fx + 832; float* redQ = fx + 1088;   // [64][4]

    int tid = threadIdx.x, wid = tid >> 5, lane = tid & 31;
    int wm = wid & 1, wn = wid >> 1;
    int gid = lane >> 2, tig = lane & 3;

    // stage W once
    {
        const uint4* src = (const uint4*)Wh_l;
        for (int u = tid; u < 4096; u += 256) {
            int n = u >> 4, j = u & 15;
            ((uint4*)(W + n * LDAh))[j] = src[u];
        }
    }
    if (tid < 128) { gsh[tid] = ln_g[tid]; bsh[tid] = ln_b[tid]; }

    uint32_t Wsb = (uint32_t)__cvta_generic_to_shared(W);
    uint32_t Asb = (uint32_t)__cvta_generic_to_shared(Ab0);
    uint32_t aoff[2], boff[2][2];
#pragma unroll
    for (int mf = 0; mf < 2; mf++)
        aoff[mf] = (uint32_t)(((wm * 32 + mf * 16 + (lane & 15)) * LDAh + ((lane >> 4) << 3)) * 2);
#pragma unroll
    for (int y = 0; y < 2; y++)
#pragma unroll
        for (int p = 0; p < 2; p++) {
            int n = y * 128 + wn * 32 + p * 16 + (lane & 7) + ((lane >> 4) << 3);
            int koff = ((lane >> 3) & 1) << 3;
            boff[y][p] = Wsb + (uint32_t)((n * LDAh + koff) * 2);
        }

    // prefetch tile 0
    {
        const __half* src = xin + (size_t)blockIdx.x * 64 * Cd;
        for (int u = tid; u < 1024; u += 256) {
            int r = u >> 4, j = u & 15;
            cpa16(Ab0 + r * LDAh + j * 8, src + r * Cd + j * 8);
        }
        asm volatile("cp.async.commit_group;\n");
    }

    int bufi = 0;
    for (int t = blockIdx.x; t < 4096; t += gridDim.x) {
        int row0 = t * 64, b = t >> 3;
        float alpha = g_alpha[b];
        int nt = t + gridDim.x;
        if (nt < 4096) {
            const __half* src = xin + (size_t)nt * 64 * Cd;
            __half* dst = Ab0 + (bufi ^ 1) * (64 * LDAh);
            for (int u = tid; u < 1024; u += 256) {
                int r = u >> 4, j = u & 15;
                cpa16(dst + r * LDAh + j * 8, src + r * Cd + j * 8);
            }
            asm volatile("cp.async.commit_group;\n");
        }
        if (tid < 128) { ssm[tid] = sin_[b * Cd + tid]; sacc[tid] = 0.f; }
        if (tid < 64) msk[tid] = g_m[row0 + tid];
        if (nt < 4096) asm volatile("cp.async.wait_group 1;\n");
        else           asm volatile("cp.async.wait_group 0;\n");
        __syncthreads();

        // tv[c] = alpha * (s . Wl[c]) + bl[c]   (4-way unrolled chains)
        if (tid < 128) {
            const __half2* wr2 = (const __half2*)(W + (128 + tid) * LDAh);
            float a0 = 0.f, a1 = 0.f, a2 = 0.f, a3 = 0.f;
#pragma unroll
            for (int k2 = 0; k2 < 64; k2 += 4) {
                float2 w0 = __half22float2(wr2[k2]);
                float2 w1 = __half22float2(wr2[k2 + 1]);
                float2 w2 = __half22float2(wr2[k2 + 2]);
                float2 w3 = __half22float2(wr2[k2 + 3]);
                a0 += ssm[k2 * 2 + 0] * w0.x + ssm[k2 * 2 + 1] * w0.y;
                a1 += ssm[k2 * 2 + 2] * w1.x + ssm[k2 * 2 + 3] * w1.y;
                a2 += ssm[k2 * 2 + 4] * w2.x + ssm[k2 * 2 + 5] * w2.y;
                a3 += ssm[k2 * 2 + 6] * w3.x + ssm[k2 * 2 + 7] * w3.y;
            }
            tvs[tid] = alpha * (a0 + a1 + a2 + a3) + bl_l[tid];
        }

        uint32_t ab = Asb + (uint32_t)(bufi * (64 * LDAh * 2));
        float acc[2][8][4];
#pragma unroll
        for (int a0 = 0; a0 < 2; a0++)
#pragma unroll
            for (int a1 = 0; a1 < 8; a1++)
#pragma unroll
                for (int a2 = 0; a2 < 4; a2++) acc[a0][a1][a2] = 0.f;

#pragma unroll
        for (int ks = 0; ks < 128; ks += 16) {
            unsigned af[2][4], bf[8][2];
#pragma unroll
            for (int mf = 0; mf < 2; mf++)
                ldsm4(af[mf][0], af[mf][1], af[mf][2], af[mf][3], ab + aoff[mf] + ks * 2);
#pragma unroll
            for (int y = 0; y < 2; y++)
#pragma unroll
                for (int p = 0; p < 2; p++) {
                    int nf = y * 4 + p * 2;
                    ldsm4(bf[nf][0], bf[nf][1], bf[nf + 1][0], bf[nf + 1][1], boff[y][p] + ks * 2);
                }
#pragma unroll
            for (int mf = 0; mf < 2; mf++)
#pragma unroll
                for (int nf = 0; nf < 8; nf++)
                    mmaf16(acc[mf][nf], af[mf], bf[nf][0], bf[nf][1]);
        }
        __syncthreads();   // tvs visible to all; A buffer reads complete

        // combine + relu
#pragma unroll
        for (int mf = 0; mf < 2; mf++)
#pragma unroll
            for (int nf = 0; nf < 4; nf++) {
                int col = wn * 32 + nf * 8 + 2 * tig;
                float tv0 = tvs[col], tv1 = tvs[col + 1];
#pragma unroll
                for (int rp = 0; rp < 2; rp++) {
                    float v0 = acc[mf][nf][rp * 2]     - alpha * acc[mf][nf + 4][rp * 2]     + tv0;
                    float v1 = acc[mf][nf][rp * 2 + 1] - alpha * acc[mf][nf + 4][rp * 2 + 1] + tv1;
                    acc[mf][nf][rp * 2]     = fmaxf(v0, 0.f);
                    acc[mf][nf][rp * 2 + 1] = fmaxf(v1, 0.f);
                }
            }
        // partial row sums
#pragma unroll
        for (int mf = 0; mf < 2; mf++)
#pragma unroll
            for (int rp = 0; rp < 2; rp++) {
                float s = 0.f, q = 0.f;
#pragma unroll
                for (int nf = 0; nf < 4; nf++) {
                    float v0 = acc[mf][nf][rp * 2], v1 = acc[mf][nf][rp * 2 + 1];
                    s += v0 + v1; q += v0 * v0 + v1 * v1;
                }
                s = shred2(s); q = shred2(q);
                if (tig == 0) {
                    int r = wm * 32 + mf * 16 + rp * 8 + gid;
                    redS[r * 4 + wn] = s;
                    redQ[r * 4 + wn] = q;
                }
            }
        __syncthreads();
        if (tid < 64) {
            float s = redS[tid * 4] + redS[tid * 4 + 1] + redS[tid * 4 + 2] + redS[tid * 4 + 3];
            float q = redQ[tid * 4] + redQ[tid * 4 + 1] + redQ[tid * 4 + 2] + redQ[tid * 4 + 3];
            float mu = s * (1.0f / 128.0f);
            float var = fmaxf(q * (1.0f / 128.0f) - mu * mu, 0.f);
            mus[tid] = mu;
            rss[tid] = rsqrtf(var + EPSL);
        }
        __syncthreads();
        float csum[4][2];
#pragma unroll
        for (int nf = 0; nf < 4; nf++) { csum[nf][0] = 0.f; csum[nf][1] = 0.f; }
#pragma unroll
        for (int mf = 0; mf < 2; mf++)
#pragma unroll
            for (int rp = 0; rp < 2; rp++) {
                int r = wm * 32 + mf * 16 + rp * 8 + gid;
                float mu = mus[r], rs = rss[r], mk = msk[r];
#pragma unroll
                for (int nf = 0; nf < 4; nf++) {
                    int col = wn * 32 + nf * 8 + 2 * tig;
                    float x0 = (acc[mf][nf][rp * 2]     - mu) * rs * gsh[col] + bsh[col];
                    float x1 = (acc[mf][nf][rp * 2 + 1] - mu) * rs * gsh[col + 1] + bsh[col + 1];
                    *(__half2*)(xout + (size_t)(row0 + r) * Cd + col) = __floats2half2_rn(x0, x1);
                    csum[nf][0] += mk * x0;
                    csum[nf][1] += mk * x1;
                }
            }
        if (!last) {
#pragma unroll
            for (int nf = 0; nf < 4; nf++) {
                csum[nf][0] = shredg(csum[nf][0]);
                csum[nf][1] = shredg(csum[nf][1]);
            }
            if (gid == 0) {
#pragma unroll
                for (int nf = 0; nf < 4; nf++) {
                    int col = wn * 32 + nf * 8 + 2 * tig;
                    atomicAdd(&sacc[col], csum[nf][0]);
                    atomicAdd(&sacc[col + 1], csum[nf][1]);
                }
            }
            __syncthreads();
            if (tid < 128) atomicAdd(&snext[b * Cd + tid], sacc[tid]);
        }
        __syncthreads();
        bufi ^= 1;
    }
}

// ======================================================================
// K_pool
// ======================================================================
__global__ void k_pool(const float* __restrict__ ss, const float* __restrict__ Wsc,
                       const float* __restrict__ bsc, float* __restrict__ out) {
    __shared__ float ms[S3v];
    int b = blockIdx.x, c = threadIdx.x;
    for (int p = c; p < S3v; p += 128) ms[p] = g_m[b * S3v + p];
    __syncthreads();
    float aj[8], ak[8];
#pragma unroll
    for (int q = 0; q < 8; q++) { aj[q] = 0.f; ak[q] = 0.f; }
    const __half* xb = g_xh1 + (size_t)b * S3v * Cd + c;
    for (int i = 0; i < 8; i++) {
        float ai = 0.f;
#pragma unroll
        for (int jk = 0; jk < 64; jk++) {
            int p = i * 64 + jk;
            float v = ms[p] * __half2float(xb[(size_t)p * Cd]);
            ai += v; aj[jk >> 3] += v; ak[jk & 7] += v;
        }
        out[((size_t)b * 26 + i) * Cd + c] = ai * 0.015625f;
    }
#pragma unroll
    for (int q = 0; q < 8; q++) {
        out[((size_t)b * 26 + 8 + q) * Cd + c] = aj[q] * 0.015625f;
        out[((size_t)b * 26 + 16 + q) * Cd + c] = ak[q] * 0.015625f;
    }
    out[((size_t)b * 26 + 25) * Cd + c] = fmaxf(ss[b] * Wsc[c] + bsc[c], 0.f);
}

// ======================================================================
// K_gemm: fp16 GEMM, BM=64, BN=128, 256 thr, cp.async + ldmatrix
// ======================================================================
#define GEMM_DSMEM (2 * 34816 + 2 * 17408)
template <int NT, int KT, int EPI, int ASRC>
__global__ void __launch_bounds__(256, 2)
k_gemm(const void* __restrict__ Av, const __half* __restrict__ Wg,
       const float* __restrict__ bias, const float* __restrict__ res,
       void* __restrict__ outv, __half* __restrict__ hout,
       const float* __restrict__ lng, const float* __restrict__ lnb) {
    extern __shared__ char smc[];
    __half* sWb[2] = { (__half*)smc, (__half*)(smc + 34816) };
    __half* sAb[2] = { (__half*)(smc + 69632), (__half*)(smc + 69632 + 17408) };
    __shared__ float redS[64][4], redQ[64][4], mus[64], rss[64];
    int tid = threadIdx.x, wid = tid >> 5, lane = tid & 31;
    int wm = wid & 1, wn = wid >> 1;
    int gid = lane >> 2, tig = lane & 3;
    int row0 = blockIdx.x * 64, n0 = blockIdx.y * 128;
    constexpr int NST = KT / 128;

    uint32_t aoff[2], boff[2];
#pragma unroll
    for (int mf = 0; mf < 2; mf++)
        aoff[mf] = (uint32_t)(((wm * 32 + mf * 16 + (lane & 15)) * LDAh + ((lane >> 4) << 3)) * 2);
#pragma unroll
    for (int p = 0; p < 2; p++) {
        int n = wn * 32 + p * 16 + (lane & 7) + ((lane >> 4) << 3);
        int koff = ((lane >> 3) & 1) << 3;
        boff[p] = (uint32_t)((n * LDAh + koff) * 2);
    }
    uint32_t sWsb[2] = { (uint32_t)__cvta_generic_to_shared(sWb[0]),
                         (uint32_t)__cvta_generic_to_shared(sWb[1]) };
    uint32_t sAsb[2] = { (uint32_t)__cvta_generic_to_shared(sAb[0]),
                         (uint32_t)__cvta_generic_to_shared(sAb[1]) };

    float acc[2][4][4];
#pragma unroll
    for (int a0 = 0; a0 < 2; a0++)
#pragma unroll
        for (int a1 = 0; a1 < 4; a1++)
#pragma unroll
            for (int a2 = 0; a2 < 4; a2++) acc[a0][a1][a2] = 0.f;

    if (ASRC == 0) {
        const __half* A = (const __half*)Av;
        for (int u = tid; u < 2048; u += 256) {
            int n = u >> 4, j = u & 15;
            cpa16(sWb[0] + n * LDAh + j * 8, Wg + (size_t)(n0 + n) * KT + j * 8);
        }
        for (int u = tid; u < 1024; u += 256) {
            int r = u >> 4, j = u & 15;
            cpa16(sAb[0] + r * LDAh + j * 8, A + (size_t)(row0 + r) * KT + j * 8);
        }
        asm volatile("cp.async.commit_group;\n");
#pragma unroll
        for (int s = 0; s < NST; s++) {
            if (s + 1 < NST) {
                int kc = (s + 1) * 128, bi = (s + 1) & 1;
                for (int u = tid; u < 2048; u += 256) {
                    int n = u >> 4, j = u & 15;
                    cpa16(sWb[bi] + n * LDAh + j * 8, Wg + (size_t)(n0 + n) * KT + kc + j * 8);
                }
                for (int u = tid; u < 1024; u += 256) {
                    int r = u >> 4, j = u & 15;
                    cpa16(sAb[bi] + r * LDAh + j * 8, A + (size_t)(row0 + r) * KT + kc + j * 8);
                }
                asm volatile("cp.async.commit_group;\n");
                asm volatile("cp.async.wait_group 1;\n");
            } else {
                asm volatile("cp.async.wait_group 0;\n");
            }
            __syncthreads();
            uint32_t wb = sWsb[s & 1], ab = sAsb[s & 1];
#pragma unroll
            for (int ks = 0; ks < 128; ks += 16) {
                unsigned af[2][4], bf[4][2];
#pragma unroll
                for (int mf = 0; mf < 2; mf++)
                    ldsm4(af[mf][0], af[mf][1], af[mf][2], af[mf][3], ab + aoff[mf] + ks * 2);
#pragma unroll
                for (int p = 0; p < 2; p++)
                    ldsm4(bf[p * 2][0], bf[p * 2][1], bf[p * 2 + 1][0], bf[p * 2 + 1][1],
                          wb + boff[p] + ks * 2);
#pragma unroll
                for (int mf = 0; mf < 2; mf++)
#pragma unroll
                    for (int nf = 0; nf < 4; nf++)
                        mmaf16(acc[mf][nf], af[mf], bf[nf][0], bf[nf][1]);
            }
            __syncthreads();
        }
    } else {
        const int* X = (const int*)Av;
        for (int kc = 0; kc < KT; kc += 128) {
            for (int u = tid; u < 2048; u += 256) {
                int n = u >> 4, j = u & 15;
                ((uint4*)(sWb[0] + n * LDAh))[j] = ((const uint4*)(Wg + (size_t)(n0 + n) * KT + kc))[j];
            }
            for (int u = tid; u < 2048; u += 256) {
                int r = u >> 5, j = u & 31;
                int gr = row0 + r, bb = gr / 15, tt = gr - bb * 15;
                int4 v = ((const int4*)(X + ((size_t)bb * 16 + tt + 1) * 512 + kc))[j];
                __half2* d = (__half2*)(sAb[0] + r * LDAh + j * 4);
                d[0] = __floats2half2_rn((float)v.x, (float)v.y);
                d[1] = __floats2half2_rn((float)v.z, (float)v.w);
            }
            __syncthreads();
#pragma unroll
            for (int ks = 0; ks < 128; ks += 16) {
                unsigned af[2][4], bf[4][2];
#pragma unroll
                for (int mf = 0; mf < 2; mf++)
                    ldsm4(af[mf][0], af[mf][1], af[mf][2], af[mf][3], sAsb[0] + aoff[mf] + ks * 2);
#pragma unroll
                for (int p = 0; p < 2; p++)
                    ldsm4(bf[p * 2][0], bf[p * 2][1], bf[p * 2 + 1][0], bf[p * 2 + 1][1],
                          sWsb[0] + boff[p] + ks * 2);
#pragma unroll
                for (int mf = 0; mf < 2; mf++)
#pragma unroll
                    for (int nf = 0; nf < 4; nf++)
                        mmaf16(acc[mf][nf], af[mf], bf[nf][0], bf[nf][1]);
            }
            __syncthreads();
        }
    }

    int gnb = n0 + wn * 32 + tig * 2;
    float2 b2[4];
#pragma unroll
    for (int nf = 0; nf < 4; nf++) b2[nf] = *(const float2*)(bias + gnb + nf * 8);

    if (EPI == 0) {
        __half* out = (__half*)outv;
#pragma unroll
        for (int mf = 0; mf < 2; mf++)
#pragma unroll
            for (int rp = 0; rp < 2; rp++) {
                int gm = row0 + wm * 32 + mf * 16 + rp * 8 + gid;
#pragma unroll
                for (int nf = 0; nf < 4; nf++)
                    *(__half2*)(out + (size_t)gm * NT + gnb + nf * 8) =
                        __floats2half2_rn(acc[mf][nf][rp * 2] + b2[nf].x, acc[mf][nf][rp * 2 + 1] + b2[nf].y);
            }
    } else if (EPI == 1) {
        __half* out = (__half*)outv;
#pragma unroll
        for (int mf = 0; mf < 2; mf++)
#pragma unroll
            for (int rp = 0; rp < 2; rp++) {
                int gm = row0 + wm * 32 + mf * 16 + rp * 8 + gid;
#pragma unroll
                for (int nf = 0; nf < 4; nf++) {
                    float v0 = fmaxf(acc[mf][nf][rp * 2] + b2[nf].x, 0.f);
                    float v1 = fmaxf(acc[mf][nf][rp * 2 + 1] + b2[nf].y, 0.f);
                    *(__half2*)(out + (size_t)gm * NT + gnb + nf * 8) = __floats2half2_rn(v0, v1);
                }
            }
    } else if (EPI == 4) {
        float* out = (float*)outv;
#pragma unroll
        for (int mf = 0; mf < 2; mf++)
#pragma unroll
            for (int rp = 0; rp < 2; rp++) {
                int gm = row0 + wm * 32 + mf * 16 + rp * 8 + gid;
                int bb = gm / 15;
                float* dst = out + ((size_t)bb * 26 + 24) * 128 + gnb;
#pragma unroll
                for (int nf = 0; nf < 4; nf++) {
                    float2 r2 = *(const float2*)(res + (size_t)gm * 128 + gnb + nf * 8);
                    float v0 = acc[mf][nf][rp * 2] + b2[nf].x + r2.x;
                    float v1 = acc[mf][nf][rp * 2 + 1] + b2[nf].y + r2.y;
                    atomicAdd(dst + nf * 8, v0 * (1.0f / 15.0f));
                    atomicAdd(dst + nf * 8 + 1, v1 * (1.0f / 15.0f));
                }
            }
    } else {
        float* aout = (float*)outv;
        float2 lg2[4], lb2[4];
#pragma unroll
        for (int nf = 0; nf < 4; nf++) {
            lg2[nf] = *(const float2*)(lng + gnb + nf * 8);
            lb2[nf] = *(const float2*)(lnb + gnb + nf * 8);
        }
#pragma unroll
        for (int mf = 0; mf < 2; mf++)
#pragma unroll
            for (int rp = 0; rp < 2; rp++) {
                int gm = row0 + wm * 32 + mf * 16 + rp * 8 + gid;
#pragma unroll
                for (int nf = 0; nf < 4; nf++) {
                    float rx = 0.f, ry = 0.f;
                    if (EPI == 2) {
                        float2 r2 = *(const float2*)(res + (size_t)gm * 128 + gnb + nf * 8);
                        rx = r2.x; ry = r2.y;
                    }
                    float v0 = acc[mf][nf][rp * 2] + b2[nf].x + rx;
                    float v1 = acc[mf][nf][rp * 2 + 1] + b2[nf].y + ry;
                    acc[mf][nf][rp * 2] = v0;
                    acc[mf][nf][rp * 2 + 1] = v1;
                    *(float2*)(aout + (size_t)gm * 128 + gnb + nf * 8) = make_float2(v0, v1);
                }
            }
#pragma unroll
        for (int mf = 0; mf < 2; mf++)
#pragma unroll
            for (int rp = 0; rp < 2; rp++) {
                float s = 0.f, q = 0.f;
#pragma unroll
                for (int nf = 0; nf < 4; nf++) {
                    float v0 = acc[mf][nf][rp * 2], v1 = acc[mf][nf][rp * 2 + 1];
                    s += v0 + v1; q += v0 * v0 + v1 * v1;
                }
                s = shred2(s); q = shred2(q);
                if (tig == 0) {
                    int r = wm * 32 + mf * 16 + rp * 8 + gid;
                    redS[r][wn] = s; redQ[r][wn] = q;
                }
            }
        __syncthreads();
        if (tid < 64) {
            float s = redS[tid][0] + redS[tid][1] + redS[tid][2] + redS[tid][3];
            float q = redQ[tid][0] + redQ[tid][1] + redQ[tid][2] + redQ[tid][3];
            float mu = s * (1.0f / 128.0f);
            float var = fmaxf(q * (1.0f / 128.0f) - mu * mu, 0.f);
            mus[tid] = mu; rss[tid] = rsqrtf(var + EPSL);
        }
        __syncthreads();
#pragma unroll
        for (int mf = 0; mf < 2; mf++)
#pragma unroll
            for (int rp = 0; rp < 2; rp++) {
                int r = wm * 32 + mf * 16 + rp * 8 + gid;
                int gm = row0 + r;
                float mu = mus[r], rs = rss[r];
#pragma unroll
                for (int nf = 0; nf < 4; nf++) {
                    float x0 = (acc[mf][nf][rp * 2] - mu) * rs * lg2[nf].x + lb2[nf].x;
                    float x1 = (acc[mf][nf][rp * 2 + 1] - mu) * rs * lg2[nf].y + lb2[nf].y;
                    *(__half2*)(hout + (size_t)gm * 128 + gnb + nf * 8) = __floats2half2_rn(x0, x1);
                }
            }
    }
}

// ======================================================================
// K_attn
// ======================================================================
__global__ void k_attn(const __half* __restrict__ qkv, __half* __restrict__ o) {
    __shared__ float sq[4][15 * 33], sk[4][15 * 33], sv[4][15 * 33];
    int b = blockIdx.x, w = threadIdx.x >> 5, lane = threadIdx.x & 31;
    for (int idx = lane; idx < 480; idx += 32) {
        int t = idx >> 5, d = idx & 31;
        const __half* base = qkv + (size_t)(b * 15 + t) * 384 + w * 32 + d;
        sq[w][t * 33 + d] = __half2float(base[0]);
        sk[w][t * 33 + d] = __half2float(base[128]);
        sv[w][t * 33 + d] = __half2float(base[256]);
    }
    __syncwarp();
    if (lane < 15) {
        float qr[32];
#pragma unroll
        for (int d = 0; d < 32; d++) qr[d] = sq[w][lane * 33 + d];
        float sc[15];
        float mx = -1e30f;
#pragma unroll
        for (int tk = 0; tk < 15; tk++) {
            float a = 0.f;
#pragma unroll
            for (int d = 0; d < 32; d++) a += qr[d] * sk[w][tk * 33 + d];
            sc[tk] = a * 0.17677669529663687f;
            mx = fmaxf(mx, sc[tk]);
        }
        float ssum = 0.f;
#pragma unroll
        for (int tk = 0; tk < 15; tk++) { sc[tk] = expf(sc[tk] - mx); ssum += sc[tk]; }
        float inv = 1.0f / ssum;
        float od[32];
#pragma unroll
        for (int d = 0; d < 32; d++) od[d] = 0.f;
#pragma unroll
        for (int tk = 0; tk < 15; tk++) {
            float p = sc[tk] * inv;
#pragma unroll
            for (int d = 0; d < 32; d++) od[d] += p * sv[w][tk * 33 + d];
        }
        __half* op = o + (size_t)(b * 15 + lane) * 128 + w * 32;
#pragma unroll
        for (int d2 = 0; d2 < 16; d2++)
            ((__half2*)op)[d2] = __floats2half2_rn(od[d2 * 2], od[d2 * 2 + 1]);
    }
}

// ======================================================================
// host launcher
// ======================================================================
extern "C" void kernel_launch(void* const* d_in, const int* in_sizes, int n_in,
                              void* d_out, int out_size) {
    const int*   xx    = (const int*)d_in[0];
    const float* ss    = (const float*)d_in[1];
    const float* Win   = (const float*)d_in[2];
    const float* b_in  = (const float*)d_in[3];
    const float* Wl    = (const float*)d_in[4];
    const float* bl    = (const float*)d_in[5];
    const float* Wr    = (const float*)d_in[6];
    const float* ln_g  = (const float*)d_in[7];
    const float* ln_b  = (const float*)d_in[8];
    const float* Wqkv  = (const float*)d_in[9];
    const float* bqkv  = (const float*)d_in[10];
    const float* Wo    = (const float*)d_in[11];
    const float* bo    = (const float*)d_in[12];
    const float* ln1_g = (const float*)d_in[13];
    const float* ln1_b = (const float*)d_in[14];
    const float* ln2_g = (const float*)d_in[15];
    const float* ln2_b = (const float*)d_in[16];
    const float* W1    = (const float*)d_in[17];
    const float* b1    = (const float*)d_in[18];
    const float* W2    = (const float*)d_in[19];
    const float* b2    = (const float*)d_in[20];
    const float* Wact  = (const float*)d_in[21];
    const float* bact  = (const float*)d_in[22];
    const float* Wsc   = (const float*)d_in[23];
    const float* bsc   = (const float*)d_in[24];
    float* out = (float*)d_out;

    void *pxh0, *pxh1, *pWg, *pWqkvh, *pWoh, *pW1h, *pW2h, *pWacth;
    void *ps0, *ps1, *ps2, *pa, *ph, *pqkv, *po, *pf;
    cudaGetSymbolAddress(&pxh0, g_xh0);
    cudaGetSymbolAddress(&pxh1, g_xh1);
    cudaGetSymbolAddress(&pWg, g_Wg);
    cudaGetSymbolAddress(&pWqkvh, g_Wqkvh);
    cudaGetSymbolAddress(&pWoh, g_Woh);
    cudaGetSymbolAddress(&pW1h, g_W1h);
    cudaGetSymbolAddress(&pW2h, g_W2h);
    cudaGetSymbolAddress(&pWacth, g_Wacth);
    cudaGetSymbolAddress(&ps0, g_s0);
    cudaGetSymbolAddress(&ps1, g_s1);
    cudaGetSymbolAddress(&ps2, g_s2);
    cudaGetSymbolAddress(&pa, g_a);
    cudaGetSymbolAddress(&ph, g_h);
    cudaGetSymbolAddress(&pqkv, g_qkv);
    cudaGetSymbolAddress(&po, g_o);
    cudaGetSymbolAddress(&pf, g_f);

    cudaFuncSetAttribute(k_gnn, cudaFuncAttributeMaxDynamicSharedMemorySize, GNN_DSMEM);
    cudaFuncSetAttribute(k_gemm<128, 512, 3, 1>, cudaFuncAttributeMaxDynamicSharedMemorySize, GEMM_DSMEM);
    cudaFuncSetAttribute(k_gemm<384, 128, 0, 0>, cudaFuncAttributeMaxDynamicSharedMemorySize, GEMM_DSMEM);
    cudaFuncSetAttribute(k_gemm<128, 128, 2, 0>, cudaFuncAttributeMaxDynamicSharedMemorySize, GEMM_DSMEM);
    cudaFuncSetAttribute(k_gemm<512, 128, 1, 0>, cudaFuncAttributeMaxDynamicSharedMemorySize, GEMM_DSMEM);
    cudaFuncSetAttribute(k_gemm<128, 512, 2, 0>, cudaFuncAttributeMaxDynamicSharedMemorySize, GEMM_DSMEM);
    cudaFuncSetAttribute(k_gemm<128, 512, 4, 0>, cudaFuncAttributeMaxDynamicSharedMemorySize, GEMM_DSMEM);

    __half* Xh[2] = {(__half*)pxh0, (__half*)pxh1};
    const __half* Wgp = (const __half*)pWg;
    float* Sv[3] = {(float*)ps0, (float*)ps1, (float*)ps2};
    float* a = (float*)pa; __half* h = (__half*)ph; __half* qkv = (__half*)pqkv;
    __half* o = (__half*)po; __half* f = (__half*)pf;

    k_wtf<<<544, 256>>>(Wr, Wl, Wqkv, Wo, W1, W2, Wact);
    k_init<<<Bsz, 512>>>(xx, ss, Win, b_in, out);
    k_gemm<128, 512, 3, 1><<<dim3(120, 1), 256, GEMM_DSMEM>>>(
        xx, (const __half*)pWacth, bact, nullptr, a, h, ln1_g, ln1_b);
    // launch #4 profiled
    k_gnn<<<296, 256, GNN_DSMEM>>>(Xh[0], Wgp, bl, Sv[0], ln_g, ln_b, Xh[1], Sv[1], 0);
    k_gnn<<<296, 256, GNN_DSMEM>>>(Xh[1], Wgp + 32768, bl + 128, Sv[1], ln_g, ln_b, Xh[0], Sv[2], 0);
    k_gnn<<<296, 256, GNN_DSMEM>>>(Xh[0], Wgp + 65536, bl + 256, Sv[2], ln_g, ln_b, Xh[1], nullptr, 1);
    k_pool<<<Bsz, 128>>>(ss, Wsc, bsc, out);

    for (int l = 0; l < 2; l++) {
        const __half* wq = (const __half*)pWqkvh + l * 49152;
        const __half* wo = (const __half*)pWoh + l * 16384;
        const __half* w1 = (const __half*)pW1h + l * 65536;
        const __half* w2 = (const __half*)pW2h + l * 65536;
        k_gemm<384, 128, 0, 0><<<dim3(120, 3), 256, GEMM_DSMEM>>>(
            h, wq, bqkv + l * 384, nullptr, qkv, nullptr, nullptr, nullptr);
        k_attn<<<Bsz, 128>>>(qkv, o);
        k_gemm<128, 128, 2, 0><<<dim3(120, 1), 256, GEMM_DSMEM>>>(
            o, wo, bo + l * 128, a, a, h, ln2_g + l * 128, ln2_b + l * 128);
        k_gemm<512, 128, 1, 0><<<dim3(120, 4), 256, GEMM_DSMEM>>>(
            h, w1, b1 + l * 512, nullptr, f, nullptr, nullptr, nullptr);
        if (l == 0) {
            k_gemm<128, 512, 2, 0><<<dim3(120, 1), 256, GEMM_DSMEM>>>(
                f, w2, b2, a, a, h, ln1_g + 128, ln1_b + 128);
        } else {
            k_gemm<128, 512, 4, 0><<<dim3(120, 1), 256, GEMM_DSMEM>>>(
                f, w2, b2 + 128, a, out, nullptr, nullptr, nullptr);
        }
    }
}

// round 7
// speedup vs baseline: 2.7036x; 1.0317x over previous
#include <cuda_runtime.h>
#include <cuda_fp16.h>
#include <cstdint>
#include <cstddef>

#define Bsz  512
#define S3v  512
#define Cd   128
#define Mrows (Bsz * S3v)
#define EPSL 1e-5f
#define RT   7680
#define LDAh 136   // halves per staged row (272B, 16B aligned)

// ---------------- device scratch ----------------
__device__ __half g_xh0[(size_t)Mrows * Cd];
__device__ __half g_xh1[(size_t)Mrows * Cd];
__device__ __half g_Weff[(size_t)Bsz * 128 * 128];   // per-batch Wr - alpha*Wl
__device__ float  g_tvg[Bsz * 128];
__device__ __half g_Wqkvh[2 * 384 * 128];
__device__ __half g_Woh[2 * 128 * 128];
__device__ __half g_W1h[2 * 512 * 128];
__device__ __half g_W2h[2 * 128 * 512];
__device__ __half g_Wacth[128 * 512];
__device__ float g_s0[Bsz * Cd];
__device__ float g_s1[Bsz * Cd];
__device__ float g_s2[Bsz * Cd];
__device__ float g_alpha[Bsz];
__device__ float g_m[Mrows];
__device__ float g_a[(size_t)RT * 128];
__device__ __half g_h[(size_t)RT * 128];
__device__ __half g_qkv[(size_t)RT * 384];
__device__ __half g_o[(size_t)RT * 128];
__device__ __half g_f[(size_t)RT * 512];

// ---------------- helpers ----------------
__device__ __forceinline__ void mmaf16(float* d, const unsigned* a, unsigned b0, unsigned b1) {
    asm("mma.sync.aligned.m16n8k16.row.col.f32.f16.f16.f32 "
        "{%0,%1,%2,%3},{%4,%5,%6,%7},{%8,%9},{%0,%1,%2,%3};"
        : "+f"(d[0]), "+f"(d[1]), "+f"(d[2]), "+f"(d[3])
        : "r"(a[0]), "r"(a[1]), "r"(a[2]), "r"(a[3]), "r"(b0), "r"(b1));
}
__device__ __forceinline__ void ldsm4(unsigned& r0, unsigned& r1, unsigned& r2, unsigned& r3,
                                      uint32_t addr) {
    asm volatile("ldmatrix.sync.aligned.m8n8.x4.shared.b16 {%0,%1,%2,%3}, [%4];"
                 : "=r"(r0), "=r"(r1), "=r"(r2), "=r"(r3) : "r"(addr));
}
__device__ __forceinline__ float shred2(float v) {
    v += __shfl_xor_sync(0xffffffffu, v, 1);
    v += __shfl_xor_sync(0xffffffffu, v, 2);
    return v;
}
__device__ __forceinline__ float shredg(float v) {
    v += __shfl_xor_sync(0xffffffffu, v, 4);
    v += __shfl_xor_sync(0xffffffffu, v, 8);
    v += __shfl_xor_sync(0xffffffffu, v, 16);
    return v;
}
__device__ __forceinline__ void cpa16(void* dst_smem, const void* src) {
    uint32_t d = (uint32_t)__cvta_generic_to_shared(dst_smem);
    asm volatile("cp.async.ca.shared.global [%0], [%1], 16;\n" :: "r"(d), "l"(src));
}

// ======================================================================
// K_wtf: weights fp32 -> fp16 (transformer + action)
// ======================================================================
__global__ void k_wtf(const float* __restrict__ Wqkv, const float* __restrict__ Wo,
                      const float* __restrict__ W1, const float* __restrict__ W2,
                      const float* __restrict__ Wact) {
    int idx = (blockIdx.x * 256 + threadIdx.x) * 4;
    const float* src;
    __half2* dst;
    if (idx < 98304)        { int j = idx;          src = Wqkv + j; dst = (__half2*)(g_Wqkvh + j); }
    else if (idx < 131072)  { int j = idx - 98304;  src = Wo + j;   dst = (__half2*)(g_Woh + j); }
    else if (idx < 262144)  { int j = idx - 131072; src = W1 + j;   dst = (__half2*)(g_W1h + j); }
    else if (idx < 393216)  { int j = idx - 262144; src = W2 + j;   dst = (__half2*)(g_W2h + j); }
    else                    { int j = idx - 393216; src = Wact + j; dst = (__half2*)(g_Wacth + j); }
    float4 v = *(const float4*)src;
    dst[0] = __floats2half2_rn(v.x, v.y);
    dst[1] = __floats2half2_rn(v.z, v.w);
}

// ======================================================================
// K_init
// ======================================================================
__global__ void k_init(const int* __restrict__ xx, const float* __restrict__ ss,
                       const float* __restrict__ Win, const float* __restrict__ b_in,
                       float* __restrict__ out) {
    __shared__ float ssm4[4][128];
    __shared__ int nct[4];
    int b = blockIdx.x, tid = threadIdx.x;
    int ph = tid >> 7, c = tid & 127;
    float w0 = Win[c * 5 + 0], w1 = Win[c * 5 + 1], w2 = Win[c * 5 + 2];
    float w3 = Win[c * 5 + 3], w4 = Win[c * 5 + 4];
    float base = (ss[b] * 0.125f) * w4 + b_in[c];
    const int* fp = xx + (size_t)b * 16 * S3v;
    const float inv7 = 1.0f / 7.0f;
    float ssum = 0.f; int ncnt = 0;
    for (int i = 0; i < 128; i++) {
        int p = i * 4 + ph;
        int f = fp[p];
        int ii = p >> 6, jj = (p >> 3) & 7, kk = p & 7;
        float val = base + (float)ii * inv7 * w0 + (float)jj * inv7 * w1 +
                    (float)kk * inv7 * w2 + (float)f * 0.5f * w3;
        g_xh0[((size_t)b * S3v + p) * Cd + c] = __float2half_rn(val);
        if (f != 0) { ssum += val; ncnt++; }
        if (c == 0) g_m[b * S3v + p] = (f != 0) ? 1.0f : 0.0f;
    }
    ssm4[ph][c] = ssum;
    if (c == 0) nct[ph] = ncnt;
    __syncthreads();
    if (tid < 128) {
        float s = ssm4[0][tid] + ssm4[1][tid] + ssm4[2][tid] + ssm4[3][tid];
        g_s0[b * Cd + tid] = s;
        g_s1[b * Cd + tid] = 0.f;
        g_s2[b * Cd + tid] = 0.f;
        out[((size_t)b * 26 + 24) * Cd + tid] = 0.f;
    }
    if (tid == 0) {
        int n = nct[0] + nct[1] + nct[2] + nct[3];
        g_alpha[b] = (n > 1) ? 1.0f / (float)(n - 1) : 0.f;
    }
}

// ======================================================================
// K_weff: per-batch effective weight W_eff[b] = Wr - alpha_b*Wl (fp16)
//         and tv[b,c] = alpha_b*(s_b . Wl[c]) + bl[c]
// grid = 512, block = 256
// ======================================================================
__global__ void k_weff(const float* __restrict__ Wr_l, const float* __restrict__ Wl_l,
                       const float* __restrict__ bl_l, const float* __restrict__ sin_) {
    __shared__ float ssm[128];
    int b = blockIdx.x, tid = threadIdx.x;
    float alpha = g_alpha[b];
    if (tid < 128) ssm[tid] = sin_[b * 128 + tid];
    __syncthreads();
    const float4* wr4 = (const float4*)Wr_l;
    const float4* wl4 = (const float4*)Wl_l;
    __half2* dst = (__half2*)(g_Weff + (size_t)b * 16384);
    for (int u = tid; u < 4096; u += 256) {
        float4 wr = wr4[u];
        float4 wl = wl4[u];
        dst[u * 2 + 0] = __floats2half2_rn(wr.x - alpha * wl.x, wr.y - alpha * wl.y);
        dst[u * 2 + 1] = __floats2half2_rn(wr.z - alpha * wl.z, wr.w - alpha * wl.w);
    }
    if (tid < 128) {
        const float4* wl = (const float4*)(Wl_l + tid * 128);
        float a0 = 0.f, a1 = 0.f, a2 = 0.f, a3 = 0.f;
#pragma unroll
        for (int k4 = 0; k4 < 32; k4 += 4) {
            float4 w0 = wl[k4], w1 = wl[k4 + 1], w2 = wl[k4 + 2], w3 = wl[k4 + 3];
            a0 += ssm[k4 * 4 + 0] * w0.x + ssm[k4 * 4 + 1] * w0.y + ssm[k4 * 4 + 2] * w0.z + ssm[k4 * 4 + 3] * w0.w;
            a1 += ssm[k4 * 4 + 4] * w1.x + ssm[k4 * 4 + 5] * w1.y + ssm[k4 * 4 + 6] * w1.z + ssm[k4 * 4 + 7] * w1.w;
            a2 += ssm[k4 * 4 + 8] * w2.x + ssm[k4 * 4 + 9] * w2.y + ssm[k4 * 4 + 10] * w2.z + ssm[k4 * 4 + 11] * w2.w;
            a3 += ssm[k4 * 4 + 12] * w3.x + ssm[k4 * 4 + 13] * w3.y + ssm[k4 * 4 + 14] * w3.z + ssm[k4 * 4 + 15] * w3.w;
        }
        g_tvg[b * 128 + tid] = alpha * (a0 + a1 + a2 + a3) + bl_l[tid];
    }
}

// ======================================================================
// K_gnn: one CTA per batch (<=2 batches/CTA). BM=128, BN=128 (W_eff).
// 256 thr (8 warps: 4M x 2N), warp tile 32x64. W_eff staged per batch.
// ======================================================================
#define GNN_DSMEM (34816 * 3 + 5632)
__global__ void __launch_bounds__(256, 2)
k_gnn(const __half* __restrict__ xin, const float* __restrict__ ln_g,
      const float* __restrict__ ln_b, __half* __restrict__ xout,
      float* __restrict__ snext, int last) {
    extern __shared__ char smc[];
    __half* W = (__half*)smc;                      // 128 x LDAh
    __half* Ab0 = (__half*)(smc + 34816);          // 2 x 128 x LDAh
    float* fx = (float*)(smc + 34816 * 3);
    float* tvs = fx;        float* gsh = fx + 128;
    float* bsh = fx + 256;  float* msk = fx + 384;
    float* sacc = fx + 512; float* mus = fx + 640;
    float* rss = fx + 768;  float* redS = fx + 896;   // [128][2]
    float* redQ = fx + 1152;                          // [128][2]

    int tid = threadIdx.x, wid = tid >> 5, lane = tid & 31;
    int wm = wid >> 1, wn = wid & 1;
    int gid = lane >> 2, tig = lane & 3;

    if (tid < 128) { gsh[tid] = ln_g[tid]; bsh[tid] = ln_b[tid]; sacc[tid] = 0.f; }

    uint32_t Wsb = (uint32_t)__cvta_generic_to_shared(W);
    uint32_t Asb = (uint32_t)__cvta_generic_to_shared(Ab0);
    uint32_t aoff[2], boff[4];
#pragma unroll
    for (int mf = 0; mf < 2; mf++)
        aoff[mf] = (uint32_t)(((wm * 32 + mf * 16 + (lane & 15)) * LDAh + ((lane >> 4) << 3)) * 2);
#pragma unroll
    for (int p = 0; p < 4; p++) {
        int n = wn * 64 + p * 16 + (lane & 7) + ((lane >> 4) << 3);
        int koff = ((lane >> 3) & 1) << 3;
        boff[p] = Wsb + (uint32_t)((n * LDAh + koff) * 2);
    }

    for (int rep = 0; rep < 2; rep++) {
        int b = blockIdx.x + rep * 296;
        if (b >= Bsz) break;

        // stage W_eff[b] + A tile 0 (one group)
        {
            const uint4* wsrc = (const uint4*)(g_Weff + (size_t)b * 16384);
            for (int u = tid; u < 2048; u += 256) {
                int n = u >> 4, j = u & 15;
                cpa16(W + n * LDAh + j * 8, wsrc + u);
            }
            const __half* asrc = xin + (size_t)b * 512 * Cd;
            for (int u = tid; u < 2048; u += 256) {
                int r = u >> 4, j = u & 15;
                cpa16(Ab0 + r * LDAh + j * 8, asrc + r * Cd + j * 8);
            }
            asm volatile("cp.async.commit_group;\n");
        }
        if (tid < 128) tvs[tid] = g_tvg[b * 128 + tid];

        int bufi = 0;
        for (int tt = 0; tt < 4; tt++) {
            int row0 = b * 512 + tt * 128;
            bool havenext = (tt < 3);
            if (havenext) {
                const __half* asrc = xin + (size_t)(row0 + 128) * Cd;
                __half* dst = Ab0 + (bufi ^ 1) * (128 * LDAh);
                for (int u = tid; u < 2048; u += 256) {
                    int r = u >> 4, j = u & 15;
                    cpa16(dst + r * LDAh + j * 8, asrc + r * Cd + j * 8);
                }
                asm volatile("cp.async.commit_group;\n");
            }
            if (tid < 128) msk[tid] = g_m[row0 + tid];
            if (havenext) asm volatile("cp.async.wait_group 1;\n");
            else          asm volatile("cp.async.wait_group 0;\n");
            __syncthreads();

            uint32_t ab = Asb + (uint32_t)(bufi * (128 * LDAh * 2));
            float acc[2][8][4];
#pragma unroll
            for (int a0 = 0; a0 < 2; a0++)
#pragma unroll
                for (int a1 = 0; a1 < 8; a1++)
#pragma unroll
                    for (int a2 = 0; a2 < 4; a2++) acc[a0][a1][a2] = 0.f;

#pragma unroll
            for (int ks = 0; ks < 128; ks += 16) {
                unsigned af[2][4], bf[8][2];
#pragma unroll
                for (int mf = 0; mf < 2; mf++)
                    ldsm4(af[mf][0], af[mf][1], af[mf][2], af[mf][3], ab + aoff[mf] + ks * 2);
#pragma unroll
                for (int p = 0; p < 4; p++)
                    ldsm4(bf[p * 2][0], bf[p * 2][1], bf[p * 2 + 1][0], bf[p * 2 + 1][1],
                          boff[p] + ks * 2);
#pragma unroll
                for (int mf = 0; mf < 2; mf++)
#pragma unroll
                    for (int nf = 0; nf < 8; nf++)
                        mmaf16(acc[mf][nf], af[mf], bf[nf][0], bf[nf][1]);
            }
            __syncthreads();

            // v = relu(y + tv)
#pragma unroll
            for (int mf = 0; mf < 2; mf++)
#pragma unroll
                for (int nf = 0; nf < 8; nf++) {
                    int col = wn * 64 + nf * 8 + 2 * tig;
                    float tv0 = tvs[col], tv1 = tvs[col + 1];
#pragma unroll
                    for (int rp = 0; rp < 2; rp++) {
                        acc[mf][nf][rp * 2]     = fmaxf(acc[mf][nf][rp * 2]     + tv0, 0.f);
                        acc[mf][nf][rp * 2 + 1] = fmaxf(acc[mf][nf][rp * 2 + 1] + tv1, 0.f);
                    }
                }
            // row partial sums over this warp's 64 cols
#pragma unroll
            for (int mf = 0; mf < 2; mf++)
#pragma unroll
                for (int rp = 0; rp < 2; rp++) {
                    float s = 0.f, q = 0.f;
#pragma unroll
                    for (int nf = 0; nf < 8; nf++) {
                        float v0 = acc[mf][nf][rp * 2], v1 = acc[mf][nf][rp * 2 + 1];
                        s += v0 + v1; q += v0 * v0 + v1 * v1;
                    }
                    s = shred2(s); q = shred2(q);
                    if (tig == 0) {
                        int r = wm * 32 + mf * 16 + rp * 8 + gid;
                        redS[r * 2 + wn] = s;
                        redQ[r * 2 + wn] = q;
                    }
                }
            __syncthreads();
            if (tid < 128) {
                float s = redS[tid * 2] + redS[tid * 2 + 1];
                float q = redQ[tid * 2] + redQ[tid * 2 + 1];
                float mu = s * (1.0f / 128.0f);
                float var = fmaxf(q * (1.0f / 128.0f) - mu * mu, 0.f);
                mus[tid] = mu;
                rss[tid] = rsqrtf(var + EPSL);
            }
            __syncthreads();
            float csum[8][2];
#pragma unroll
            for (int nf = 0; nf < 8; nf++) { csum[nf][0] = 0.f; csum[nf][1] = 0.f; }
#pragma unroll
            for (int mf = 0; mf < 2; mf++)
#pragma unroll
                for (int rp = 0; rp < 2; rp++) {
                    int r = wm * 32 + mf * 16 + rp * 8 + gid;
                    float mu = mus[r], rs = rss[r], mk = msk[r];
#pragma unroll
                    for (int nf = 0; nf < 8; nf++) {
                        int col = wn * 64 + nf * 8 + 2 * tig;
                        float x0 = (acc[mf][nf][rp * 2]     - mu) * rs * gsh[col] + bsh[col];
                        float x1 = (acc[mf][nf][rp * 2 + 1] - mu) * rs * gsh[col + 1] + bsh[col + 1];
                        *(__half2*)(xout + (size_t)(row0 + r) * Cd + col) = __floats2half2_rn(x0, x1);
                        csum[nf][0] += mk * x0;
                        csum[nf][1] += mk * x1;
                    }
                }
            if (!last) {
#pragma unroll
                for (int nf = 0; nf < 8; nf++) {
                    csum[nf][0] = shredg(csum[nf][0]);
                    csum[nf][1] = shredg(csum[nf][1]);
                }
                if (gid == 0) {
#pragma unroll
                    for (int nf = 0; nf < 8; nf++) {
                        int col = wn * 64 + nf * 8 + 2 * tig;
                        atomicAdd(&sacc[col], csum[nf][0]);
                        atomicAdd(&sacc[col + 1], csum[nf][1]);
                    }
                }
            }
            __syncthreads();
            bufi ^= 1;
        }
        if (!last && tid < 128) {
            snext[b * Cd + tid] = sacc[tid];
            sacc[tid] = 0.f;
        }
    }
}

// ======================================================================
// K_pool
// ======================================================================
__global__ void k_pool(const float* __restrict__ ss, const float* __restrict__ Wsc,
                       const float* __restrict__ bsc, float* __restrict__ out) {
    __shared__ float ms[S3v];
    int b = blockIdx.x, c = threadIdx.x;
    for (int p = c; p < S3v; p += 128) ms[p] = g_m[b * S3v + p];
    __syncthreads();
    float aj[8], ak[8];
#pragma unroll
    for (int q = 0; q < 8; q++) { aj[q] = 0.f; ak[q] = 0.f; }
    const __half* xb = g_xh1 + (size_t)b * S3v * Cd + c;
    for (int i = 0; i < 8; i++) {
        float ai = 0.f;
#pragma unroll
        for (int jk = 0; jk < 64; jk++) {
            int p = i * 64 + jk;
            float v = ms[p] * __half2float(xb[(size_t)p * Cd]);
            ai += v; aj[jk >> 3] += v; ak[jk & 7] += v;
        }
        out[((size_t)b * 26 + i) * Cd + c] = ai * 0.015625f;
    }
#pragma unroll
    for (int q = 0; q < 8; q++) {
        out[((size_t)b * 26 + 8 + q) * Cd + c] = aj[q] * 0.015625f;
        out[((size_t)b * 26 + 16 + q) * Cd + c] = ak[q] * 0.015625f;
    }
    out[((size_t)b * 26 + 25) * Cd + c] = fmaxf(ss[b] * Wsc[c] + bsc[c], 0.f);
}

// ======================================================================
// K_gemm: fp16 GEMM, BM=64, BN=128, 256 thr, cp.async + ldmatrix
// ======================================================================
#define GEMM_DSMEM (2 * 34816 + 2 * 17408)
template <int NT, int KT, int EPI, int ASRC>
__global__ void __launch_bounds__(256, 2)
k_gemm(const void* __restrict__ Av, const __half* __restrict__ Wg,
       const float* __restrict__ bias, const float* __restrict__ res,
       void* __restrict__ outv, __half* __restrict__ hout,
       const float* __restrict__ lng, const float* __restrict__ lnb) {
    extern __shared__ char smc[];
    __half* sWb[2] = { (__half*)smc, (__half*)(smc + 34816) };
    __half* sAb[2] = { (__half*)(smc + 69632), (__half*)(smc + 69632 + 17408) };
    __shared__ float redS[64][4], redQ[64][4], mus[64], rss[64];
    int tid = threadIdx.x, wid = tid >> 5, lane = tid & 31;
    int wm = wid & 1, wn = wid >> 1;
    int gid = lane >> 2, tig = lane & 3;
    int row0 = blockIdx.x * 64, n0 = blockIdx.y * 128;
    constexpr int NST = KT / 128;

    uint32_t aoff[2], boff[2];
#pragma unroll
    for (int mf = 0; mf < 2; mf++)
        aoff[mf] = (uint32_t)(((wm * 32 + mf * 16 + (lane & 15)) * LDAh + ((lane >> 4) << 3)) * 2);
#pragma unroll
    for (int p = 0; p < 2; p++) {
        int n = wn * 32 + p * 16 + (lane & 7) + ((lane >> 4) << 3);
        int koff = ((lane >> 3) & 1) << 3;
        boff[p] = (uint32_t)((n * LDAh + koff) * 2);
    }
    uint32_t sWsb[2] = { (uint32_t)__cvta_generic_to_shared(sWb[0]),
                         (uint32_t)__cvta_generic_to_shared(sWb[1]) };
    uint32_t sAsb[2] = { (uint32_t)__cvta_generic_to_shared(sAb[0]),
                         (uint32_t)__cvta_generic_to_shared(sAb[1]) };

    float acc[2][4][4];
#pragma unroll
    for (int a0 = 0; a0 < 2; a0++)
#pragma unroll
        for (int a1 = 0; a1 < 4; a1++)
#pragma unroll
            for (int a2 = 0; a2 < 4; a2++) acc[a0][a1][a2] = 0.f;

    if (ASRC == 0) {
        const __half* A = (const __half*)Av;
        for (int u = tid; u < 2048; u += 256) {
            int n = u >> 4, j = u & 15;
            cpa16(sWb[0] + n * LDAh + j * 8, Wg + (size_t)(n0 + n) * KT + j * 8);
        }
        for (int u = tid; u < 1024; u += 256) {
            int r = u >> 4, j = u & 15;
            cpa16(sAb[0] + r * LDAh + j * 8, A + (size_t)(row0 + r) * KT + j * 8);
        }
        asm volatile("cp.async.commit_group;\n");
#pragma unroll
        for (int s = 0; s < NST; s++) {
            if (s + 1 < NST) {
                int kc = (s + 1) * 128, bi = (s + 1) & 1;
                for (int u = tid; u < 2048; u += 256) {
                    int n = u >> 4, j = u & 15;
                    cpa16(sWb[bi] + n * LDAh + j * 8, Wg + (size_t)(n0 + n) * KT + kc + j * 8);
                }
                for (int u = tid; u < 1024; u += 256) {
                    int r = u >> 4, j = u & 15;
                    cpa16(sAb[bi] + r * LDAh + j * 8, A + (size_t)(row0 + r) * KT + kc + j * 8);
                }
                asm volatile("cp.async.commit_group;\n");
                asm volatile("cp.async.wait_group 1;\n");
            } else {
                asm volatile("cp.async.wait_group 0;\n");
            }
            __syncthreads();
            uint32_t wb = sWsb[s & 1], ab = sAsb[s & 1];
#pragma unroll
            for (int ks = 0; ks < 128; ks += 16) {
                unsigned af[2][4], bf[4][2];
#pragma unroll
                for (int mf = 0; mf < 2; mf++)
                    ldsm4(af[mf][0], af[mf][1], af[mf][2], af[mf][3], ab + aoff[mf] + ks * 2);
#pragma unroll
                for (int p = 0; p < 2; p++)
                    ldsm4(bf[p * 2][0], bf[p * 2][1], bf[p * 2 + 1][0], bf[p * 2 + 1][1],
                          wb + boff[p] + ks * 2);
#pragma unroll
                for (int mf = 0; mf < 2; mf++)
#pragma unroll
                    for (int nf = 0; nf < 4; nf++)
                        mmaf16(acc[mf][nf], af[mf], bf[nf][0], bf[nf][1]);
            }
            __syncthreads();
        }
    } else {
        const int* X = (const int*)Av;
        for (int kc = 0; kc < KT; kc += 128) {
            for (int u = tid; u < 2048; u += 256) {
                int n = u >> 4, j = u & 15;
                ((uint4*)(sWb[0] + n * LDAh))[j] = ((const uint4*)(Wg + (size_t)(n0 + n) * KT + kc))[j];
            }
            for (int u = tid; u < 2048; u += 256) {
                int r = u >> 5, j = u & 31;
                int gr = row0 + r, bb = gr / 15, tt = gr - bb * 15;
                int4 v = ((const int4*)(X + ((size_t)bb * 16 + tt + 1) * 512 + kc))[j];
                __half2* d = (__half2*)(sAb[0] + r * LDAh + j * 4);
                d[0] = __floats2half2_rn((float)v.x, (float)v.y);
                d[1] = __floats2half2_rn((float)v.z, (float)v.w);
            }
            __syncthreads();
#pragma unroll
            for (int ks = 0; ks < 128; ks += 16) {
                unsigned af[2][4], bf[4][2];
#pragma unroll
                for (int mf = 0; mf < 2; mf++)
                    ldsm4(af[mf][0], af[mf][1], af[mf][2], af[mf][3], sAsb[0] + aoff[mf] + ks * 2);
#pragma unroll
                for (int p = 0; p < 2; p++)
                    ldsm4(bf[p * 2][0], bf[p * 2][1], bf[p * 2 + 1][0], bf[p * 2 + 1][1],
                          sWsb[0] + boff[p] + ks * 2);
#pragma unroll
                for (int mf = 0; mf < 2; mf++)
#pragma unroll
                    for (int nf = 0; nf < 4; nf++)
                        mmaf16(acc[mf][nf], af[mf], bf[nf][0], bf[nf][1]);
            }
            __syncthreads();
        }
    }

    int gnb = n0 + wn * 32 + tig * 2;
    float2 b2[4];
#pragma unroll
    for (int nf = 0; nf < 4; nf++) b2[nf] = *(const float2*)(bias + gnb + nf * 8);

    if (EPI == 0) {
        __half* out = (__half*)outv;
#pragma unroll
        for (int mf = 0; mf < 2; mf++)
#pragma unroll
            for (int rp = 0; rp < 2; rp++) {
                int gm = row0 + wm * 32 + mf * 16 + rp * 8 + gid;
#pragma unroll
                for (int nf = 0; nf < 4; nf++)
                    *(__half2*)(out + (size_t)gm * NT + gnb + nf * 8) =
                        __floats2half2_rn(acc[mf][nf][rp * 2] + b2[nf].x, acc[mf][nf][rp * 2 + 1] + b2[nf].y);
            }
    } else if (EPI == 1) {
        __half* out = (__half*)outv;
#pragma unroll
        for (int mf = 0; mf < 2; mf++)
#pragma unroll
            for (int rp = 0; rp < 2; rp++) {
                int gm = row0 + wm * 32 + mf * 16 + rp * 8 + gid;
#pragma unroll
                for (int nf = 0; nf < 4; nf++) {
                    float v0 = fmaxf(acc[mf][nf][rp * 2] + b2[nf].x, 0.f);
                    float v1 = fmaxf(acc[mf][nf][rp * 2 + 1] + b2[nf].y, 0.f);
                    *(__half2*)(out + (size_t)gm * NT + gnb + nf * 8) = __floats2half2_rn(v0, v1);
                }
            }
    } else if (EPI == 4) {
        float* out = (float*)outv;
#pragma unroll
        for (int mf = 0; mf < 2; mf++)
#pragma unroll
            for (int rp = 0; rp < 2; rp++) {
                int gm = row0 + wm * 32 + mf * 16 + rp * 8 + gid;
                int bb = gm / 15;
                float* dst = out + ((size_t)bb * 26 + 24) * 128 + gnb;
#pragma unroll
                for (int nf = 0; nf < 4; nf++) {
                    float2 r2 = *(const float2*)(res + (size_t)gm * 128 + gnb + nf * 8);
                    float v0 = acc[mf][nf][rp * 2] + b2[nf].x + r2.x;
                    float v1 = acc[mf][nf][rp * 2 + 1] + b2[nf].y + r2.y;
                    atomicAdd(dst + nf * 8, v0 * (1.0f / 15.0f));
                    atomicAdd(dst + nf * 8 + 1, v1 * (1.0f / 15.0f));
                }
            }
    } else {
        float* aout = (float*)outv;
        float2 lg2[4], lb2[4];
#pragma unroll
        for (int nf = 0; nf < 4; nf++) {
            lg2[nf] = *(const float2*)(lng + gnb + nf * 8);
            lb2[nf] = *(const float2*)(lnb + gnb + nf * 8);
        }
#pragma unroll
        for (int mf = 0; mf < 2; mf++)
#pragma unroll
            for (int rp = 0; rp < 2; rp++) {
                int gm = row0 + wm * 32 + mf * 16 + rp * 8 + gid;
#pragma unroll
                for (int nf = 0; nf < 4; nf++) {
                    float rx = 0.f, ry = 0.f;
                    if (EPI == 2) {
                        float2 r2 = *(const float2*)(res + (size_t)gm * 128 + gnb + nf * 8);
                        rx = r2.x; ry = r2.y;
                    }
                    float v0 = acc[mf][nf][rp * 2] + b2[nf].x + rx;
                    float v1 = acc[mf][nf][rp * 2 + 1] + b2[nf].y + ry;
                    acc[mf][nf][rp * 2] = v0;
                    acc[mf][nf][rp * 2 + 1] = v1;
                    *(float2*)(aout + (size_t)gm * 128 + gnb + nf * 8) = make_float2(v0, v1);
                }
            }
#pragma unroll
        for (int mf = 0; mf < 2; mf++)
#pragma unroll
            for (int rp = 0; rp < 2; rp++) {
                float s = 0.f, q = 0.f;
#pragma unroll
                for (int nf = 0; nf < 4; nf++) {
                    float v0 = acc[mf][nf][rp * 2], v1 = acc[mf][nf][rp * 2 + 1];
                    s += v0 + v1; q += v0 * v0 + v1 * v1;
                }
                s = shred2(s); q = shred2(q);
                if (tig == 0) {
                    int r = wm * 32 + mf * 16 + rp * 8 + gid;
                    redS[r][wn] = s; redQ[r][wn] = q;
                }
            }
        __syncthreads();
        if (tid < 64) {
            float s = redS[tid][0] + redS[tid][1] + redS[tid][2] + redS[tid][3];
            float q = redQ[tid][0] + redQ[tid][1] + redQ[tid][2] + redQ[tid][3];
            float mu = s * (1.0f / 128.0f);
            float var = fmaxf(q * (1.0f / 128.0f) - mu * mu, 0.f);
            mus[tid] = mu; rss[tid] = rsqrtf(var + EPSL);
        }
        __syncthreads();
#pragma unroll
        for (int mf = 0; mf < 2; mf++)
#pragma unroll
            for (int rp = 0; rp < 2; rp++) {
                int r = wm * 32 + mf * 16 + rp * 8 + gid;
                int gm = row0 + r;
                float mu = mus[r], rs = rss[r];
#pragma unroll
                for (int nf = 0; nf < 4; nf++) {
                    float x0 = (acc[mf][nf][rp * 2] - mu) * rs * lg2[nf].x + lb2[nf].x;
                    float x1 = (acc[mf][nf][rp * 2 + 1] - mu) * rs * lg2[nf].y + lb2[nf].y;
                    *(__half2*)(hout + (size_t)gm * 128 + gnb + nf * 8) = __floats2half2_rn(x0, x1);
                }
            }
    }
}

// ======================================================================
// K_attn
// ======================================================================
__global__ void k_attn(const __half* __restrict__ qkv, __half* __restrict__ o) {
    __shared__ float sq[4][15 * 33], sk[4][15 * 33], sv[4][15 * 33];
    int b = blockIdx.x, w = threadIdx.x >> 5, lane = threadIdx.x & 31;
    for (int idx = lane; idx < 480; idx += 32) {
        int t = idx >> 5, d = idx & 31;
        const __half* base = qkv + (size_t)(b * 15 + t) * 384 + w * 32 + d;
        sq[w][t * 33 + d] = __half2float(base[0]);
        sk[w][t * 33 + d] = __half2float(base[128]);
        sv[w][t * 33 + d] = __half2float(base[256]);
    }
    __syncwarp();
    if (lane < 15) {
        float qr[32];
#pragma unroll
        for (int d = 0; d < 32; d++) qr[d] = sq[w][lane * 33 + d];
        float sc[15];
        float mx = -1e30f;
#pragma unroll
        for (int tk = 0; tk < 15; tk++) {
            float a = 0.f;
#pragma unroll
            for (int d = 0; d < 32; d++) a += qr[d] * sk[w][tk * 33 + d];
            sc[tk] = a * 0.17677669529663687f;
            mx = fmaxf(mx, sc[tk]);
        }
        float ssum = 0.f;
#pragma unroll
        for (int tk = 0; tk < 15; tk++) { sc[tk] = expf(sc[tk] - mx); ssum += sc[tk]; }
        float inv = 1.0f / ssum;
        float od[32];
#pragma unroll
        for (int d = 0; d < 32; d++) od[d] = 0.f;
#pragma unroll
        for (int tk = 0; tk < 15; tk++) {
            float p = sc[tk] * inv;
#pragma unroll
            for (int d = 0; d < 32; d++) od[d] += p * sv[w][tk * 33 + d];
        }
        __half* op = o + (size_t)(b * 15 + lane) * 128 + w * 32;
#pragma unroll
        for (int d2 = 0; d2 < 16; d2++)
            ((__half2*)op)[d2] = __floats2half2_rn(od[d2 * 2], od[d2 * 2 + 1]);
    }
}

// ======================================================================
// host launcher
// ======================================================================
extern "C" void kernel_launch(void* const* d_in, const int* in_sizes, int n_in,
                              void* d_out, int out_size) {
    const int*   xx    = (const int*)d_in[0];
    const float* ss    = (const float*)d_in[1];
    const float* Win   = (const float*)d_in[2];
    const float* b_in  = (const float*)d_in[3];
    const float* Wl    = (const float*)d_in[4];
    const float* bl    = (const float*)d_in[5];
    const float* Wr    = (const float*)d_in[6];
    const float* ln_g  = (const float*)d_in[7];
    const float* ln_b  = (const float*)d_in[8];
    const float* Wqkv  = (const float*)d_in[9];
    const float* bqkv  = (const float*)d_in[10];
    const float* Wo    = (const float*)d_in[11];
    const float* bo    = (const float*)d_in[12];
    const float* ln1_g = (const float*)d_in[13];
    const float* ln1_b = (const float*)d_in[14];
    const float* ln2_g = (const float*)d_in[15];
    const float* ln2_b = (const float*)d_in[16];
    const float* W1    = (const float*)d_in[17];
    const float* b1    = (const float*)d_in[18];
    const float* W2    = (const float*)d_in[19];
    const float* b2    = (const float*)d_in[20];
    const float* Wact  = (const float*)d_in[21];
    const float* bact  = (const float*)d_in[22];
    const float* Wsc   = (const float*)d_in[23];
    const float* bsc   = (const float*)d_in[24];
    float* out = (float*)d_out;

    void *pxh0, *pxh1, *pWqkvh, *pWoh, *pW1h, *pW2h, *pWacth;
    void *ps0, *ps1, *ps2, *pa, *ph, *pqkv, *po, *pf;
    cudaGetSymbolAddress(&pxh0, g_xh0);
    cudaGetSymbolAddress(&pxh1, g_xh1);
    cudaGetSymbolAddress(&pWqkvh, g_Wqkvh);
    cudaGetSymbolAddress(&pWoh, g_Woh);
    cudaGetSymbolAddress(&pW1h, g_W1h);
    cudaGetSymbolAddress(&pW2h, g_W2h);
    cudaGetSymbolAddress(&pWacth, g_Wacth);
    cudaGetSymbolAddress(&ps0, g_s0);
    cudaGetSymbolAddress(&ps1, g_s1);
    cudaGetSymbolAddress(&ps2, g_s2);
    cudaGetSymbolAddress(&pa, g_a);
    cudaGetSymbolAddress(&ph, g_h);
    cudaGetSymbolAddress(&pqkv, g_qkv);
    cudaGetSymbolAddress(&po, g_o);
    cudaGetSymbolAddress(&pf, g_f);

    cudaFuncSetAttribute(k_gnn, cudaFuncAttributeMaxDynamicSharedMemorySize, GNN_DSMEM);
    cudaFuncSetAttribute(k_gemm<128, 512, 3, 1>, cudaFuncAttributeMaxDynamicSharedMemorySize, GEMM_DSMEM);
    cudaFuncSetAttribute(k_gemm<384, 128, 0, 0>, cudaFuncAttributeMaxDynamicSharedMemorySize, GEMM_DSMEM);
    cudaFuncSetAttribute(k_gemm<128, 128, 2, 0>, cudaFuncAttributeMaxDynamicSharedMemorySize, GEMM_DSMEM);
    cudaFuncSetAttribute(k_gemm<512, 128, 1, 0>, cudaFuncAttributeMaxDynamicSharedMemorySize, GEMM_DSMEM);
    cudaFuncSetAttribute(k_gemm<128, 512, 2, 0>, cudaFuncAttributeMaxDynamicSharedMemorySize, GEMM_DSMEM);
    cudaFuncSetAttribute(k_gemm<128, 512, 4, 0>, cudaFuncAttributeMaxDynamicSharedMemorySize, GEMM_DSMEM);

    __half* Xh[2] = {(__half*)pxh0, (__half*)pxh1};
    float* Sv[3] = {(float*)ps0, (float*)ps1, (float*)ps2};
    float* a = (float*)pa; __half* h = (__half*)ph; __half* qkv = (__half*)pqkv;
    __half* o = (__half*)po; __half* f = (__half*)pf;

    k_wtf<<<448, 256>>>(Wqkv, Wo, W1, W2, Wact);                         // 1
    k_init<<<Bsz, 512>>>(xx, ss, Win, b_in, out);                        // 2
    k_weff<<<Bsz, 256>>>(Wr, Wl, bl, Sv[0]);                             // 3
    k_gnn<<<296, 256, GNN_DSMEM>>>(Xh[0], ln_g, ln_b, Xh[1], Sv[1], 0);  // 4 <- profiled
    k_weff<<<Bsz, 256>>>(Wr + 16384, Wl + 16384, bl + 128, Sv[1]);
    k_gnn<<<296, 256, GNN_DSMEM>>>(Xh[1], ln_g, ln_b, Xh[0], Sv[2], 0);
    k_weff<<<Bsz, 256>>>(Wr + 32768, Wl + 32768, bl + 256, Sv[2]);
    k_gnn<<<296, 256, GNN_DSMEM>>>(Xh[0], ln_g, ln_b, Xh[1], nullptr, 1);
    k_pool<<<Bsz, 128>>>(ss, Wsc, bsc, out);
    k_gemm<128, 512, 3, 1><<<dim3(120, 1), 256, GEMM_DSMEM>>>(
        xx, (const __half*)pWacth, bact, nullptr, a, h, ln1_g, ln1_b);

    for (int l = 0; l < 2; l++) {
        const __half* wq = (const __half*)pWqkvh + l * 49152;
        const __half* wo = (const __half*)pWoh + l * 16384;
        const __half* w1 = (const __half*)pW1h + l * 65536;
        const __half* w2 = (const __half*)pW2h + l * 65536;
        k_gemm<384, 128, 0, 0><<<dim3(120, 3), 256, GEMM_DSMEM>>>(
            h, wq, bqkv + l * 384, nullptr, qkv, nullptr, nullptr, nullptr);
        k_attn<<<Bsz, 128>>>(qkv, o);
        k_gemm<128, 128, 2, 0><<<dim3(120, 1), 256, GEMM_DSMEM>>>(
            o, wo, bo + l * 128, a, a, h, ln2_g + l * 128, ln2_b + l * 128);
        k_gemm<512, 128, 1, 0><<<dim3(120, 4), 256, GEMM_DSMEM>>>(
            h, w1, b1 + l * 512, nullptr, f, nullptr, nullptr, nullptr);
        if (l == 0) {
            k_gemm<128, 512, 2, 0><<<dim3(120, 1), 256, GEMM_DSMEM>>>(
                f, w2, b2, a, a, h, ln1_g + 128, ln1_b + 128);
        } else {
            k_gemm<128, 512, 4, 0><<<dim3(120, 1), 256, GEMM_DSMEM>>>(
                f, w2, b2 + 128, a, out, nullptr, nullptr, nullptr);
        }
    }
}

// round 8
// speedup vs baseline: 2.8931x; 1.0701x over previous
#include <cuda_runtime.h>
#include <cuda_fp16.h>
#include <cstdint>
#include <cstddef>

#define Bsz  512
#define S3v  512
#define Cd   128
#define Mrows (Bsz * S3v)
#define EPSL 1e-5f
#define RT   7680
#define LDAh 136   // halves per staged row (272B, 16B aligned)

// ---------------- device scratch ----------------
__device__ __half g_xh0[(size_t)Mrows * Cd];
__device__ __half g_xh1[(size_t)Mrows * Cd];
__device__ __half g_Weff[(size_t)Bsz * 128 * 128];   // per-batch Wr - alpha*Wl
__device__ float  g_tvg[Bsz * 128];
__device__ __half g_Wqkvh[2 * 384 * 128];
__device__ __half g_Woh[2 * 128 * 128];
__device__ __half g_W1h[2 * 512 * 128];
__device__ __half g_W2h[2 * 128 * 512];
__device__ __half g_Wacth[128 * 512];
__device__ float g_s0[Bsz * Cd];
__device__ float g_s1[Bsz * Cd];
__device__ float g_s2[Bsz * Cd];
__device__ float g_alpha[Bsz];
__device__ float g_m[Mrows];

// ---------------- helpers ----------------
__device__ __forceinline__ void mmaf16(float* d, const unsigned* a, unsigned b0, unsigned b1) {
    asm("mma.sync.aligned.m16n8k16.row.col.f32.f16.f16.f32 "
        "{%0,%1,%2,%3},{%4,%5,%6,%7},{%8,%9},{%0,%1,%2,%3};"
        : "+f"(d[0]), "+f"(d[1]), "+f"(d[2]), "+f"(d[3])
        : "r"(a[0]), "r"(a[1]), "r"(a[2]), "r"(a[3]), "r"(b0), "r"(b1));
}
__device__ __forceinline__ void ldsm4(unsigned& r0, unsigned& r1, unsigned& r2, unsigned& r3,
                                      uint32_t addr) {
    asm volatile("ldmatrix.sync.aligned.m8n8.x4.shared.b16 {%0,%1,%2,%3}, [%4];"
                 : "=r"(r0), "=r"(r1), "=r"(r2), "=r"(r3) : "r"(addr));
}
__device__ __forceinline__ float shred2(float v) {
    v += __shfl_xor_sync(0xffffffffu, v, 1);
    v += __shfl_xor_sync(0xffffffffu, v, 2);
    return v;
}
__device__ __forceinline__ float shredg(float v) {
    v += __shfl_xor_sync(0xffffffffu, v, 4);
    v += __shfl_xor_sync(0xffffffffu, v, 8);
    v += __shfl_xor_sync(0xffffffffu, v, 16);
    return v;
}
__device__ __forceinline__ void cpa16(void* dst_smem, const void* src) {
    uint32_t d = (uint32_t)__cvta_generic_to_shared(dst_smem);
    asm volatile("cp.async.ca.shared.global [%0], [%1], 16;\n" :: "r"(d), "l"(src));
}

// ======================================================================
// K_wtf: weights fp32 -> fp16
// ======================================================================
__global__ void k_wtf(const float* __restrict__ Wqkv, const float* __restrict__ Wo,
                      const float* __restrict__ W1, const float* __restrict__ W2,
                      const float* __restrict__ Wact) {
    int idx = (blockIdx.x * 256 + threadIdx.x) * 4;
    const float* src;
    __half2* dst;
    if (idx < 98304)        { int j = idx;          src = Wqkv + j; dst = (__half2*)(g_Wqkvh + j); }
    else if (idx < 131072)  { int j = idx - 98304;  src = Wo + j;   dst = (__half2*)(g_Woh + j); }
    else if (idx < 262144)  { int j = idx - 131072; src = W1 + j;   dst = (__half2*)(g_W1h + j); }
    else if (idx < 393216)  { int j = idx - 262144; src = W2 + j;   dst = (__half2*)(g_W2h + j); }
    else                    { int j = idx - 393216; src = Wact + j; dst = (__half2*)(g_Wacth + j); }
    float4 v = *(const float4*)src;
    dst[0] = __floats2half2_rn(v.x, v.y);
    dst[1] = __floats2half2_rn(v.z, v.w);
}

// ======================================================================
// K_init
// ======================================================================
__global__ void k_init(const int* __restrict__ xx, const float* __restrict__ ss,
                       const float* __restrict__ Win, const float* __restrict__ b_in) {
    __shared__ float ssm4[4][128];
    __shared__ int nct[4];
    int b = blockIdx.x, tid = threadIdx.x;
    int ph = tid >> 7, c = tid & 127;
    float w0 = Win[c * 5 + 0], w1 = Win[c * 5 + 1], w2 = Win[c * 5 + 2];
    float w3 = Win[c * 5 + 3], w4 = Win[c * 5 + 4];
    float base = (ss[b] * 0.125f) * w4 + b_in[c];
    const int* fp = xx + (size_t)b * 16 * S3v;
    const float inv7 = 1.0f / 7.0f;
    float ssum = 0.f; int ncnt = 0;
    for (int i = 0; i < 128; i++) {
        int p = i * 4 + ph;
        int f = fp[p];
        int ii = p >> 6, jj = (p >> 3) & 7, kk = p & 7;
        float val = base + (float)ii * inv7 * w0 + (float)jj * inv7 * w1 +
                    (float)kk * inv7 * w2 + (float)f * 0.5f * w3;
        g_xh0[((size_t)b * S3v + p) * Cd + c] = __float2half_rn(val);
        if (f != 0) { ssum += val; ncnt++; }
        if (c == 0) g_m[b * S3v + p] = (f != 0) ? 1.0f : 0.0f;
    }
    ssm4[ph][c] = ssum;
    if (c == 0) nct[ph] = ncnt;
    __syncthreads();
    if (tid < 128) {
        float s = ssm4[0][tid] + ssm4[1][tid] + ssm4[2][tid] + ssm4[3][tid];
        g_s0[b * Cd + tid] = s;
        g_s1[b * Cd + tid] = 0.f;
        g_s2[b * Cd + tid] = 0.f;
    }
    if (tid == 0) {
        int n = nct[0] + nct[1] + nct[2] + nct[3];
        g_alpha[b] = (n > 1) ? 1.0f / (float)(n - 1) : 0.f;
    }
}

// ======================================================================
// K_weff: per-batch W_eff[b] = Wr - alpha_b*Wl (fp16) + tv
// ======================================================================
__global__ void k_weff(const float* __restrict__ Wr_l, const float* __restrict__ Wl_l,
                       const float* __restrict__ bl_l, const float* __restrict__ sin_) {
    __shared__ float ssm[128];
    int b = blockIdx.x, tid = threadIdx.x;
    float alpha = g_alpha[b];
    if (tid < 128) ssm[tid] = sin_[b * 128 + tid];
    __syncthreads();
    const float4* wr4 = (const float4*)Wr_l;
    const float4* wl4 = (const float4*)Wl_l;
    __half2* dst = (__half2*)(g_Weff + (size_t)b * 16384);
    for (int u = tid; u < 4096; u += 256) {
        float4 wr = wr4[u];
        float4 wl = wl4[u];
        dst[u * 2 + 0] = __floats2half2_rn(wr.x - alpha * wl.x, wr.y - alpha * wl.y);
        dst[u * 2 + 1] = __floats2half2_rn(wr.z - alpha * wl.z, wr.w - alpha * wl.w);
    }
    if (tid < 128) {
        const float4* wl = (const float4*)(Wl_l + tid * 128);
        float a0 = 0.f, a1 = 0.f, a2 = 0.f, a3 = 0.f;
#pragma unroll
        for (int k4 = 0; k4 < 32; k4 += 4) {
            float4 w0 = wl[k4], w1 = wl[k4 + 1], w2 = wl[k4 + 2], w3 = wl[k4 + 3];
            a0 += ssm[k4 * 4 + 0] * w0.x + ssm[k4 * 4 + 1] * w0.y + ssm[k4 * 4 + 2] * w0.z + ssm[k4 * 4 + 3] * w0.w;
            a1 += ssm[k4 * 4 + 4] * w1.x + ssm[k4 * 4 + 5] * w1.y + ssm[k4 * 4 + 6] * w1.z + ssm[k4 * 4 + 7] * w1.w;
            a2 += ssm[k4 * 4 + 8] * w2.x + ssm[k4 * 4 + 9] * w2.y + ssm[k4 * 4 + 10] * w2.z + ssm[k4 * 4 + 11] * w2.w;
            a3 += ssm[k4 * 4 + 12] * w3.x + ssm[k4 * 4 + 13] * w3.y + ssm[k4 * 4 + 14] * w3.z + ssm[k4 * 4 + 15] * w3.w;
        }
        g_tvg[b * 128 + tid] = alpha * (a0 + a1 + a2 + a3) + bl_l[tid];
    }
}

// ======================================================================
// K_gnn (unchanged from R7): CTA per batch, BM=128, BN=128 W_eff
// ======================================================================
#define GNN_DSMEM (34816 * 3 + 5632)
__global__ void __launch_bounds__(256, 2)
k_gnn(const __half* __restrict__ xin, const float* __restrict__ ln_g,
      const float* __restrict__ ln_b, __half* __restrict__ xout,
      float* __restrict__ snext, int last) {
    extern __shared__ char smc[];
    __half* W = (__half*)smc;
    __half* Ab0 = (__half*)(smc + 34816);
    float* fx = (float*)(smc + 34816 * 3);
    float* tvs = fx;        float* gsh = fx + 128;
    float* bsh = fx + 256;  float* msk = fx + 384;
    float* sacc = fx + 512; float* mus = fx + 640;
    float* rss = fx + 768;  float* redS = fx + 896;
    float* redQ = fx + 1152;

    int tid = threadIdx.x, wid = tid >> 5, lane = tid & 31;
    int wm = wid >> 1, wn = wid & 1;
    int gid = lane >> 2, tig = lane & 3;

    if (tid < 128) { gsh[tid] = ln_g[tid]; bsh[tid] = ln_b[tid]; sacc[tid] = 0.f; }

    uint32_t Wsb = (uint32_t)__cvta_generic_to_shared(W);
    uint32_t Asb = (uint32_t)__cvta_generic_to_shared(Ab0);
    uint32_t aoff[2], boff[4];
#pragma unroll
    for (int mf = 0; mf < 2; mf++)
        aoff[mf] = (uint32_t)(((wm * 32 + mf * 16 + (lane & 15)) * LDAh + ((lane >> 4) << 3)) * 2);
#pragma unroll
    for (int p = 0; p < 4; p++) {
        int n = wn * 64 + p * 16 + (lane & 7) + ((lane >> 4) << 3);
        int koff = ((lane >> 3) & 1) << 3;
        boff[p] = Wsb + (uint32_t)((n * LDAh + koff) * 2);
    }

    for (int rep = 0; rep < 2; rep++) {
        int b = blockIdx.x + rep * 296;
        if (b >= Bsz) break;
        {
            const uint4* wsrc = (const uint4*)(g_Weff + (size_t)b * 16384);
            for (int u = tid; u < 2048; u += 256) {
                int n = u >> 4, j = u & 15;
                cpa16(W + n * LDAh + j * 8, wsrc + u);
            }
            const __half* asrc = xin + (size_t)b * 512 * Cd;
            for (int u = tid; u < 2048; u += 256) {
                int r = u >> 4, j = u & 15;
                cpa16(Ab0 + r * LDAh + j * 8, asrc + r * Cd + j * 8);
            }
            asm volatile("cp.async.commit_group;\n");
        }
        if (tid < 128) tvs[tid] = g_tvg[b * 128 + tid];

        int bufi = 0;
        for (int tt = 0; tt < 4; tt++) {
            int row0 = b * 512 + tt * 128;
            bool havenext = (tt < 3);
            if (havenext) {
                const __half* asrc = xin + (size_t)(row0 + 128) * Cd;
                __half* dst = Ab0 + (bufi ^ 1) * (128 * LDAh);
                for (int u = tid; u < 2048; u += 256) {
                    int r = u >> 4, j = u & 15;
                    cpa16(dst + r * LDAh + j * 8, asrc + r * Cd + j * 8);
                }
                asm volatile("cp.async.commit_group;\n");
            }
            if (tid < 128) msk[tid] = g_m[row0 + tid];
            if (havenext) asm volatile("cp.async.wait_group 1;\n");
            else          asm volatile("cp.async.wait_group 0;\n");
            __syncthreads();

            uint32_t ab = Asb + (uint32_t)(bufi * (128 * LDAh * 2));
            float acc[2][8][4];
#pragma unroll
            for (int a0 = 0; a0 < 2; a0++)
#pragma unroll
                for (int a1 = 0; a1 < 8; a1++)
#pragma unroll
                    for (int a2 = 0; a2 < 4; a2++) acc[a0][a1][a2] = 0.f;

#pragma unroll
            for (int ks = 0; ks < 128; ks += 16) {
                unsigned af[2][4], bf[8][2];
#pragma unroll
                for (int mf = 0; mf < 2; mf++)
                    ldsm4(af[mf][0], af[mf][1], af[mf][2], af[mf][3], ab + aoff[mf] + ks * 2);
#pragma unroll
                for (int p = 0; p < 4; p++)
                    ldsm4(bf[p * 2][0], bf[p * 2][1], bf[p * 2 + 1][0], bf[p * 2 + 1][1],
                          boff[p] + ks * 2);
#pragma unroll
                for (int mf = 0; mf < 2; mf++)
#pragma unroll
                    for (int nf = 0; nf < 8; nf++)
                        mmaf16(acc[mf][nf], af[mf], bf[nf][0], bf[nf][1]);
            }
            __syncthreads();

#pragma unroll
            for (int mf = 0; mf < 2; mf++)
#pragma unroll
                for (int nf = 0; nf < 8; nf++) {
                    int col = wn * 64 + nf * 8 + 2 * tig;
                    float tv0 = tvs[col], tv1 = tvs[col + 1];
#pragma unroll
                    for (int rp = 0; rp < 2; rp++) {
                        acc[mf][nf][rp * 2]     = fmaxf(acc[mf][nf][rp * 2]     + tv0, 0.f);
                        acc[mf][nf][rp * 2 + 1] = fmaxf(acc[mf][nf][rp * 2 + 1] + tv1, 0.f);
                    }
                }
#pragma unroll
            for (int mf = 0; mf < 2; mf++)
#pragma unroll
                for (int rp = 0; rp < 2; rp++) {
                    float s = 0.f, q = 0.f;
#pragma unroll
                    for (int nf = 0; nf < 8; nf++) {
                        float v0 = acc[mf][nf][rp * 2], v1 = acc[mf][nf][rp * 2 + 1];
                        s += v0 + v1; q += v0 * v0 + v1 * v1;
                    }
                    s = shred2(s); q = shred2(q);
                    if (tig == 0) {
                        int r = wm * 32 + mf * 16 + rp * 8 + gid;
                        redS[r * 2 + wn] = s;
                        redQ[r * 2 + wn] = q;
                    }
                }
            __syncthreads();
            if (tid < 128) {
                float s = redS[tid * 2] + redS[tid * 2 + 1];
                float q = redQ[tid * 2] + redQ[tid * 2 + 1];
                float mu = s * (1.0f / 128.0f);
                float var = fmaxf(q * (1.0f / 128.0f) - mu * mu, 0.f);
                mus[tid] = mu;
                rss[tid] = rsqrtf(var + EPSL);
            }
            __syncthreads();
            float csum[8][2];
#pragma unroll
            for (int nf = 0; nf < 8; nf++) { csum[nf][0] = 0.f; csum[nf][1] = 0.f; }
#pragma unroll
            for (int mf = 0; mf < 2; mf++)
#pragma unroll
                for (int rp = 0; rp < 2; rp++) {
                    int r = wm * 32 + mf * 16 + rp * 8 + gid;
                    float mu = mus[r], rs = rss[r], mk = msk[r];
#pragma unroll
                    for (int nf = 0; nf < 8; nf++) {
                        int col = wn * 64 + nf * 8 + 2 * tig;
                        float x0 = (acc[mf][nf][rp * 2]     - mu) * rs * gsh[col] + bsh[col];
                        float x1 = (acc[mf][nf][rp * 2 + 1] - mu) * rs * gsh[col + 1] + bsh[col + 1];
                        *(__half2*)(xout + (size_t)(row0 + r) * Cd + col) = __floats2half2_rn(x0, x1);
                        csum[nf][0] += mk * x0;
                        csum[nf][1] += mk * x1;
                    }
                }
            if (!last) {
#pragma unroll
                for (int nf = 0; nf < 8; nf++) {
                    csum[nf][0] = shredg(csum[nf][0]);
                    csum[nf][1] = shredg(csum[nf][1]);
                }
                if (gid == 0) {
#pragma unroll
                    for (int nf = 0; nf < 8; nf++) {
                        int col = wn * 64 + nf * 8 + 2 * tig;
                        atomicAdd(&sacc[col], csum[nf][0]);
                        atomicAdd(&sacc[col + 1], csum[nf][1]);
                    }
                }
            }
            __syncthreads();
            bufi ^= 1;
        }
        if (!last && tid < 128) {
            snext[b * Cd + tid] = sacc[tid];
            sacc[tid] = 0.f;
        }
    }
}

// ======================================================================
// K_pool
// ======================================================================
__global__ void k_pool(const float* __restrict__ ss, const float* __restrict__ Wsc,
                       const float* __restrict__ bsc, float* __restrict__ out) {
    __shared__ float ms[S3v];
    int b = blockIdx.x, c = threadIdx.x;
    for (int p = c; p < S3v; p += 128) ms[p] = g_m[b * S3v + p];
    __syncthreads();
    float aj[8], ak[8];
#pragma unroll
    for (int q = 0; q < 8; q++) { aj[q] = 0.f; ak[q] = 0.f; }
    const __half* xb = g_xh1 + (size_t)b * S3v * Cd + c;
    for (int i = 0; i < 8; i++) {
        float ai = 0.f;
#pragma unroll
        for (int jk = 0; jk < 64; jk++) {
            int p = i * 64 + jk;
            float v = ms[p] * __half2float(xb[(size_t)p * Cd]);
            ai += v; aj[jk >> 3] += v; ak[jk & 7] += v;
        }
        out[((size_t)b * 26 + i) * Cd + c] = ai * 0.015625f;
    }
#pragma unroll
    for (int q = 0; q < 8; q++) {
        out[((size_t)b * 26 + 8 + q) * Cd + c] = aj[q] * 0.015625f;
        out[((size_t)b * 26 + 16 + q) * Cd + c] = ak[q] * 0.015625f;
    }
    out[((size_t)b * 26 + 25) * Cd + c] = fmaxf(ss[b] * Wsc[c] + bsc[c], 0.f);
}

// ======================================================================
// K_tf: fully-fused transformer. grid=128 CTAs x 4 batches (60 rows),
// everything in smem; weights streamed via cp.async double-buffer.
// ======================================================================
#define TF_SMEM 190976
#define QLD 392
__global__ void __launch_bounds__(256, 1)
k_tf(const int* __restrict__ xx,
     const float* __restrict__ bact,
     const float* __restrict__ bqkv, const float* __restrict__ bo,
     const float* __restrict__ b1g, const float* __restrict__ b2g,
     const float* __restrict__ ln1_g, const float* __restrict__ ln1_b,
     const float* __restrict__ ln2_g, const float* __restrict__ ln2_b,
     float* __restrict__ out) {
    extern __shared__ char sm[];
    __half* sW0  = (__half*)sm;                      // 128 x LDAh
    __half* sW1  = (__half*)(sm + 34816);
    __half* buf1 = (__half*)(sm + 69632);            // 64 x LDAh (xx / attn-o / f)
    __half* hS   = (__half*)(sm + 87040);            // 64 x LDAh
    __half* qkvS = (__half*)(sm + 104448);           // 64 x QLD
    float*  aS   = (float*)(sm + 154624);            // 64 x 132
    float*  redS = (float*)(sm + 188416);            // [64][4]
    float*  redQ = redS + 256;
    float*  mus  = redQ + 256;
    float*  rss  = mus + 64;

    int tid = threadIdx.x, wid = tid >> 5, lane = tid & 31;
    int wm = wid & 1, wn = wid >> 1;
    int gid = lane >> 2, tig = lane & 3;
    int row0 = blockIdx.x * 60;
    int b0 = blockIdx.x * 4;

    uint32_t sWb[2] = { (uint32_t)__cvta_generic_to_shared(sW0),
                        (uint32_t)__cvta_generic_to_shared(sW1) };
    uint32_t bufB = (uint32_t)__cvta_generic_to_shared(buf1);
    uint32_t hSB  = (uint32_t)__cvta_generic_to_shared(hS);
    uint32_t aoff[2], boff[2];
#pragma unroll
    for (int mf = 0; mf < 2; mf++)
        aoff[mf] = (uint32_t)(((wm * 32 + mf * 16 + (lane & 15)) * LDAh + ((lane >> 4) << 3)) * 2);
#pragma unroll
    for (int p = 0; p < 2; p++) {
        int n = wn * 32 + p * 16 + (lane & 7) + ((lane >> 4) << 3);
        int koff = ((lane >> 3) & 1) << 3;
        boff[p] = (uint32_t)((n * LDAh + koff) * 2);
    }

    // weight staging schedule (28 entries)
    const __half* wptr[28]; int wstr[28];
    {
        int i = 0;
        for (int kc = 0; kc < 512; kc += 128) { wptr[i] = g_Wacth + kc; wstr[i++] = 512; }
        for (int l = 0; l < 2; l++) {
            for (int nt = 0; nt < 3; nt++) { wptr[i] = g_Wqkvh + l * 49152 + nt * 16384; wstr[i++] = 128; }
            wptr[i] = g_Woh + l * 16384; wstr[i++] = 128;
            for (int kt = 0; kt < 4; kt++) {
                wptr[i] = g_W1h + l * 65536 + kt * 16384; wstr[i++] = 128;
                wptr[i] = g_W2h + l * 65536 + kt * 128;  wstr[i++] = 512;
            }
        }
    }
    int ipre = 0, iuse = 0;
    auto PRE = [&]() {
        if (ipre >= 28) return;
        const __half* src = wptr[ipre];
        int st = wstr[ipre];
        __half* dst = (ipre & 1) ? sW1 : sW0;
        for (int u = tid; u < 2048; u += 256) {
            int n = u >> 4, j = u & 15;
            cpa16(dst + n * LDAh + j * 8, src + (size_t)n * st + j * 8);
        }
        asm volatile("cp.async.commit_group;\n");
        ipre++;
    };
    auto WAITW = [&]() {
        if (ipre - iuse > 1) asm volatile("cp.async.wait_group 1;\n");
        else                 asm volatile("cp.async.wait_group 0;\n");
    };
    auto MML = [&](uint32_t ab, float (&acc)[2][4][4]) {
        uint32_t wb = sWb[iuse & 1];
#pragma unroll
        for (int ks = 0; ks < 128; ks += 16) {
            unsigned af[2][4], bf[4][2];
#pragma unroll
            for (int mf = 0; mf < 2; mf++)
                ldsm4(af[mf][0], af[mf][1], af[mf][2], af[mf][3], ab + aoff[mf] + ks * 2);
#pragma unroll
            for (int p = 0; p < 2; p++)
                ldsm4(bf[p * 2][0], bf[p * 2][1], bf[p * 2 + 1][0], bf[p * 2 + 1][1],
                      wb + boff[p] + ks * 2);
#pragma unroll
            for (int mf = 0; mf < 2; mf++)
#pragma unroll
                for (int nf = 0; nf < 4; nf++)
                    mmaf16(acc[mf][nf], af[mf], bf[nf][0], bf[nf][1]);
        }
        iuse++;
    };
    auto ZA = [&](float (&acc)[2][4][4]) {
#pragma unroll
        for (int a0 = 0; a0 < 2; a0++)
#pragma unroll
            for (int a1 = 0; a1 < 4; a1++)
#pragma unroll
                for (int a2 = 0; a2 < 4; a2++) acc[a0][a1][a2] = 0.f;
    };
    // bias (+res) -> aS; optional LN -> hS. Ends with syncthreads.
    auto EPILN = [&](float (&acc)[2][4][4], const float* bias,
                     const float* lng, const float* lnb, int addRes, int doLN) {
        int gnb = wn * 32 + tig * 2;
#pragma unroll
        for (int mf = 0; mf < 2; mf++)
#pragma unroll
            for (int rp = 0; rp < 2; rp++) {
                int gm = wm * 32 + mf * 16 + rp * 8 + gid;
#pragma unroll
                for (int nf = 0; nf < 4; nf++) {
                    int c = gnb + nf * 8;
                    float v0 = acc[mf][nf][rp * 2] + bias[c];
                    float v1 = acc[mf][nf][rp * 2 + 1] + bias[c + 1];
                    if (addRes) { v0 += aS[gm * 132 + c]; v1 += aS[gm * 132 + c + 1]; }
                    acc[mf][nf][rp * 2] = v0;
                    acc[mf][nf][rp * 2 + 1] = v1;
                    aS[gm * 132 + c] = v0;
                    aS[gm * 132 + c + 1] = v1;
                }
            }
        if (!doLN) { __syncthreads(); return; }
#pragma unroll
        for (int mf = 0; mf < 2; mf++)
#pragma unroll
            for (int rp = 0; rp < 2; rp++) {
                float s = 0.f, q = 0.f;
#pragma unroll
                for (int nf = 0; nf < 4; nf++) {
                    float v0 = acc[mf][nf][rp * 2], v1 = acc[mf][nf][rp * 2 + 1];
                    s += v0 + v1; q += v0 * v0 + v1 * v1;
                }
                s = shred2(s); q = shred2(q);
                if (tig == 0) {
                    int r = wm * 32 + mf * 16 + rp * 8 + gid;
                    redS[r * 4 + wn] = s;
                    redQ[r * 4 + wn] = q;
                }
            }
        __syncthreads();
        if (tid < 64) {
            float s = redS[tid * 4] + redS[tid * 4 + 1] + redS[tid * 4 + 2] + redS[tid * 4 + 3];
            float q = redQ[tid * 4] + redQ[tid * 4 + 1] + redQ[tid * 4 + 2] + redQ[tid * 4 + 3];
            float mu = s * (1.0f / 128.0f);
            float var = fmaxf(q * (1.0f / 128.0f) - mu * mu, 0.f);
            mus[tid] = mu;
            rss[tid] = rsqrtf(var + EPSL);
        }
        __syncthreads();
#pragma unroll
        for (int mf = 0; mf < 2; mf++)
#pragma unroll
            for (int rp = 0; rp < 2; rp++) {
                int r = wm * 32 + mf * 16 + rp * 8 + gid;
                float mu = mus[r], rs = rss[r];
#pragma unroll
                for (int nf = 0; nf < 4; nf++) {
                    int c = gnb + nf * 8;
                    float x0 = (acc[mf][nf][rp * 2] - mu) * rs * lng[c] + lnb[c];
                    float x1 = (acc[mf][nf][rp * 2 + 1] - mu) * rs * lng[c + 1] + lnb[c + 1];
                    *(__half2*)(hS + r * LDAh + c) = __floats2half2_rn(x0, x1);
                }
            }
        __syncthreads();
    };

    float acc[2][4][4];

    // ---- stage 0: a = xx @ Wact^T (K=512), then LN1(l0) -> hS ----
    PRE();
    ZA(acc);
    for (int kc = 0; kc < 512; kc += 128) {
        PRE();
        // stage xx chunk into buf1 (int -> half)
        for (int u = tid; u < 2048; u += 256) {
            int r = u >> 5, j = u & 31;
            int gr = row0 + r;
            if (r >= 60) gr = row0;
            int bb = gr / 15, tt = gr - bb * 15;
            int4 v = ((const int4*)(xx + ((size_t)bb * 16 + tt + 1) * 512 + kc))[j];
            __half2* d = (__half2*)(buf1 + r * LDAh + j * 4);
            d[0] = __floats2half2_rn((float)v.x, (float)v.y);
            d[1] = __floats2half2_rn((float)v.z, (float)v.w);
        }
        WAITW();
        __syncthreads();
        MML(bufB, acc);
        __syncthreads();
    }
    EPILN(acc, bact, ln1_g, ln1_b, 0, 1);

    for (int l = 0; l < 2; l++) {
        // ---- qkv: 3 N-tiles ----
        for (int nt = 0; nt < 3; nt++) {
            PRE(); WAITW(); __syncthreads();
            ZA(acc);
            MML(hSB, acc);
            __syncthreads();
            {
                int gnb = wn * 32 + tig * 2;
                const float* bias = bqkv + l * 384 + nt * 128;
#pragma unroll
                for (int mf = 0; mf < 2; mf++)
#pragma unroll
                    for (int rp = 0; rp < 2; rp++) {
                        int gm = wm * 32 + mf * 16 + rp * 8 + gid;
#pragma unroll
                        for (int nf = 0; nf < 4; nf++) {
                            int c = gnb + nf * 8;
                            *(__half2*)(qkvS + gm * QLD + nt * 128 + c) =
                                __floats2half2_rn(acc[mf][nf][rp * 2] + bias[c],
                                                  acc[mf][nf][rp * 2 + 1] + bias[c + 1]);
                        }
                    }
            }
        }
        __syncthreads();
        // ---- attention: 16 (batch,head) tasks over 8 warps -> buf1 ----
        for (int task = wid; task < 16; task += 8) {
            int bloc = task >> 2, head = task & 3;
            if (lane < 15) {
                const __half2* qp = (const __half2*)(qkvS + (bloc * 15 + lane) * QLD + head * 32);
                float qr[32];
#pragma unroll
                for (int d2 = 0; d2 < 16; d2++) {
                    float2 f = __half22float2(qp[d2]);
                    qr[d2 * 2] = f.x; qr[d2 * 2 + 1] = f.y;
                }
                float sc[15], mx = -1e30f;
#pragma unroll
                for (int tk = 0; tk < 15; tk++) {
                    const __half2* kp = (const __half2*)(qkvS + (bloc * 15 + tk) * QLD + 128 + head * 32);
                    float a = 0.f;
#pragma unroll
                    for (int d2 = 0; d2 < 16; d2++) {
                        float2 f = __half22float2(kp[d2]);
                        a += qr[d2 * 2] * f.x + qr[d2 * 2 + 1] * f.y;
                    }
                    sc[tk] = a * 0.17677669529663687f;
                    mx = fmaxf(mx, sc[tk]);
                }
                float ssum = 0.f;
#pragma unroll
                for (int tk = 0; tk < 15; tk++) { sc[tk] = expf(sc[tk] - mx); ssum += sc[tk]; }
                float inv = 1.0f / ssum;
                float od[32];
#pragma unroll
                for (int d = 0; d < 32; d++) od[d] = 0.f;
#pragma unroll
                for (int tk = 0; tk < 15; tk++) {
                    float p = sc[tk] * inv;
                    const __half2* vp = (const __half2*)(qkvS + (bloc * 15 + tk) * QLD + 256 + head * 32);
#pragma unroll
                    for (int d2 = 0; d2 < 16; d2++) {
                        float2 f = __half22float2(vp[d2]);
                        od[d2 * 2] += p * f.x; od[d2 * 2 + 1] += p * f.y;
                    }
                }
                __half2* op = (__half2*)(buf1 + (bloc * 15 + lane) * LDAh + head * 32);
#pragma unroll
                for (int d2 = 0; d2 < 16; d2++)
                    op[d2] = __floats2half2_rn(od[d2 * 2], od[d2 * 2 + 1]);
            }
        }
        __syncthreads();
        // ---- Wo + residual + LN2 ----
        PRE(); WAITW(); __syncthreads();
        ZA(acc);
        MML(bufB, acc);
        __syncthreads();
        EPILN(acc, bo + l * 128, ln2_g + l * 128, ln2_b + l * 128, 1, 1);
        // ---- FFN: 4 k-tiles, acc2 accumulates W2 contributions ----
        float acc2[2][4][4];
        ZA(acc2);
        for (int kt = 0; kt < 4; kt++) {
            PRE(); WAITW(); __syncthreads();
            ZA(acc);
            MML(hSB, acc);
            __syncthreads();
            {   // f = relu(acc + b1) -> buf1
                int gnb = wn * 32 + tig * 2;
                const float* bias = b1g + l * 512 + kt * 128;
#pragma unroll
                for (int mf = 0; mf < 2; mf++)
#pragma unroll
                    for (int rp = 0; rp < 2; rp++) {
                        int gm = wm * 32 + mf * 16 + rp * 8 + gid;
#pragma unroll
                        for (int nf = 0; nf < 4; nf++) {
                            int c = gnb + nf * 8;
                            float v0 = fmaxf(acc[mf][nf][rp * 2] + bias[c], 0.f);
                            float v1 = fmaxf(acc[mf][nf][rp * 2 + 1] + bias[c + 1], 0.f);
                            *(__half2*)(buf1 + gm * LDAh + c) = __floats2half2_rn(v0, v1);
                        }
                    }
            }
            __syncthreads();
            PRE(); WAITW(); __syncthreads();
            MML(bufB, acc2);
            __syncthreads();
        }
        if (l == 0) {
            EPILN(acc2, b2g, ln1_g + 128, ln1_b + 128, 1, 1);
        } else {
            EPILN(acc2, b2g + 128, nullptr, nullptr, 1, 0);
            if (tid < 128) {
#pragma unroll
                for (int lb = 0; lb < 4; lb++) {
                    float s = 0.f;
#pragma unroll
                    for (int t = 0; t < 15; t++) s += aS[(lb * 15 + t) * 132 + tid];
                    out[((size_t)(b0 + lb) * 26 + 24) * 128 + tid] = s * (1.0f / 15.0f);
                }
            }
        }
    }
}

// ======================================================================
// host launcher
// ======================================================================
extern "C" void kernel_launch(void* const* d_in, const int* in_sizes, int n_in,
                              void* d_out, int out_size) {
    const int*   xx    = (const int*)d_in[0];
    const float* ss    = (const float*)d_in[1];
    const float* Win   = (const float*)d_in[2];
    const float* b_in  = (const float*)d_in[3];
    const float* Wl    = (const float*)d_in[4];
    const float* bl    = (const float*)d_in[5];
    const float* Wr    = (const float*)d_in[6];
    const float* ln_g  = (const float*)d_in[7];
    const float* ln_b  = (const float*)d_in[8];
    const float* Wqkv  = (const float*)d_in[9];
    const float* bqkv  = (const float*)d_in[10];
    const float* Wo    = (const float*)d_in[11];
    const float* bo    = (const float*)d_in[12];
    const float* ln1_g = (const float*)d_in[13];
    const float* ln1_b = (const float*)d_in[14];
    const float* ln2_g = (const float*)d_in[15];
    const float* ln2_b = (const float*)d_in[16];
    const float* W1    = (const float*)d_in[17];
    const float* b1    = (const float*)d_in[18];
    const float* W2    = (const float*)d_in[19];
    const float* b2    = (const float*)d_in[20];
    const float* Wact  = (const float*)d_in[21];
    const float* bact  = (const float*)d_in[22];
    const float* Wsc   = (const float*)d_in[23];
    const float* bsc   = (const float*)d_in[24];
    float* out = (float*)d_out;

    void *pxh0, *pxh1, *ps0, *ps1, *ps2;
    cudaGetSymbolAddress(&pxh0, g_xh0);
    cudaGetSymbolAddress(&pxh1, g_xh1);
    cudaGetSymbolAddress(&ps0, g_s0);
    cudaGetSymbolAddress(&ps1, g_s1);
    cudaGetSymbolAddress(&ps2, g_s2);

    cudaFuncSetAttribute(k_gnn, cudaFuncAttributeMaxDynamicSharedMemorySize, GNN_DSMEM);
    cudaFuncSetAttribute(k_tf, cudaFuncAttributeMaxDynamicSharedMemorySize, TF_SMEM);

    __half* Xh[2] = {(__half*)pxh0, (__half*)pxh1};
    float* Sv[3] = {(float*)ps0, (float*)ps1, (float*)ps2};

    k_wtf<<<448, 256>>>(Wqkv, Wo, W1, W2, Wact);                         // 1
    k_init<<<Bsz, 512>>>(xx, ss, Win, b_in);                             // 2
    k_weff<<<Bsz, 256>>>(Wr, Wl, bl, Sv[0]);                             // 3
    k_tf<<<128, 256, TF_SMEM>>>(xx, bact, bqkv, bo, b1, b2,              // 4 <- profiled
                                ln1_g, ln1_b, ln2_g, ln2_b, out);
    k_gnn<<<296, 256, GNN_DSMEM>>>(Xh[0], ln_g, ln_b, Xh[1], Sv[1], 0);  // 5
    k_weff<<<Bsz, 256>>>(Wr + 16384, Wl + 16384, bl + 128, Sv[1]);       // 6
    k_gnn<<<296, 256, GNN_DSMEM>>>(Xh[1], ln_g, ln_b, Xh[0], Sv[2], 0);  // 7
    k_weff<<<Bsz, 256>>>(Wr + 32768, Wl + 32768, bl + 256, Sv[2]);       // 8
    k_gnn<<<296, 256, GNN_DSMEM>>>(Xh[0], ln_g, ln_b, Xh[1], nullptr, 1);// 9
    k_pool<<<Bsz, 128>>>(ss, Wsc, bsc, out);                             // 10
}

// round 9
// speedup vs baseline: 3.2623x; 1.1276x over previous
#include <cuda_runtime.h>
#include <cuda_fp16.h>
#include <cstdint>
#include <cstddef>

#define Bsz  512
#define S3v  512
#define Cd   128
#define Mrows (Bsz * S3v)
#define EPSL 1e-5f
#define LDAh 136   // halves per staged row (272B, 16B aligned)

// ---------------- device scratch ----------------
__device__ __half g_xh0[(size_t)Mrows * Cd];
__device__ __half g_xh1[(size_t)Mrows * Cd];
__device__ __half g_Wqkvh[2 * 384 * 128];
__device__ __half g_Woh[2 * 128 * 128];
__device__ __half g_W1h[2 * 512 * 128];
__device__ __half g_W2h[2 * 128 * 512];
__device__ __half g_Wacth[128 * 512];
__device__ float g_s0[Bsz * Cd];
__device__ float g_alpha[Bsz];
__device__ float g_m[Mrows];

// ---------------- helpers ----------------
__device__ __forceinline__ void mmaf16(float* d, const unsigned* a, unsigned b0, unsigned b1) {
    asm("mma.sync.aligned.m16n8k16.row.col.f32.f16.f16.f32 "
        "{%0,%1,%2,%3},{%4,%5,%6,%7},{%8,%9},{%0,%1,%2,%3};"
        : "+f"(d[0]), "+f"(d[1]), "+f"(d[2]), "+f"(d[3])
        : "r"(a[0]), "r"(a[1]), "r"(a[2]), "r"(a[3]), "r"(b0), "r"(b1));
}
__device__ __forceinline__ void ldsm4(unsigned& r0, unsigned& r1, unsigned& r2, unsigned& r3,
                                      uint32_t addr) {
    asm volatile("ldmatrix.sync.aligned.m8n8.x4.shared.b16 {%0,%1,%2,%3}, [%4];"
                 : "=r"(r0), "=r"(r1), "=r"(r2), "=r"(r3) : "r"(addr));
}
__device__ __forceinline__ float shred2(float v) {
    v += __shfl_xor_sync(0xffffffffu, v, 1);
    v += __shfl_xor_sync(0xffffffffu, v, 2);
    return v;
}
__device__ __forceinline__ float shredg(float v) {
    v += __shfl_xor_sync(0xffffffffu, v, 4);
    v += __shfl_xor_sync(0xffffffffu, v, 8);
    v += __shfl_xor_sync(0xffffffffu, v, 16);
    return v;
}
__device__ __forceinline__ void cpa16(void* dst_smem, const void* src) {
    uint32_t d = (uint32_t)__cvta_generic_to_shared(dst_smem);
    asm volatile("cp.async.ca.shared.global [%0], [%1], 16;\n" :: "r"(d), "l"(src));
}

// ======================================================================
// K_wtf: transformer weights fp32 -> fp16
// ======================================================================
__global__ void k_wtf(const float* __restrict__ Wqkv, const float* __restrict__ Wo,
                      const float* __restrict__ W1, const float* __restrict__ W2,
                      const float* __restrict__ Wact) {
    int idx = (blockIdx.x * 256 + threadIdx.x) * 4;
    const float* src;
    __half2* dst;
    if (idx < 98304)        { int j = idx;          src = Wqkv + j; dst = (__half2*)(g_Wqkvh + j); }
    else if (idx < 131072)  { int j = idx - 98304;  src = Wo + j;   dst = (__half2*)(g_Woh + j); }
    else if (idx < 262144)  { int j = idx - 131072; src = W1 + j;   dst = (__half2*)(g_W1h + j); }
    else if (idx < 393216)  { int j = idx - 262144; src = W2 + j;   dst = (__half2*)(g_W2h + j); }
    else                    { int j = idx - 393216; src = Wact + j; dst = (__half2*)(g_Wacth + j); }
    float4 v = *(const float4*)src;
    dst[0] = __floats2half2_rn(v.x, v.y);
    dst[1] = __floats2half2_rn(v.z, v.w);
}

// ======================================================================
// K_init: features + lin_in (fp16) + mask + masked colsum + alpha
// ======================================================================
__global__ void k_init(const int* __restrict__ xx, const float* __restrict__ ss,
                       const float* __restrict__ Win, const float* __restrict__ b_in) {
    __shared__ float ssm4[4][128];
    __shared__ int nct[4];
    int b = blockIdx.x, tid = threadIdx.x;
    int ph = tid >> 7, c = tid & 127;
    float w0 = Win[c * 5 + 0], w1 = Win[c * 5 + 1], w2 = Win[c * 5 + 2];
    float w3 = Win[c * 5 + 3], w4 = Win[c * 5 + 4];
    float base = (ss[b] * 0.125f) * w4 + b_in[c];
    const int* fp = xx + (size_t)b * 16 * S3v;
    const float inv7 = 1.0f / 7.0f;
    float ssum = 0.f; int ncnt = 0;
    for (int i = 0; i < 128; i++) {
        int p = i * 4 + ph;
        int f = fp[p];
        int ii = p >> 6, jj = (p >> 3) & 7, kk = p & 7;
        float val = base + (float)ii * inv7 * w0 + (float)jj * inv7 * w1 +
                    (float)kk * inv7 * w2 + (float)f * 0.5f * w3;
        g_xh0[((size_t)b * S3v + p) * Cd + c] = __float2half_rn(val);
        if (f != 0) { ssum += val; ncnt++; }
        if (c == 0) g_m[b * S3v + p] = (f != 0) ? 1.0f : 0.0f;
    }
    ssm4[ph][c] = ssum;
    if (c == 0) nct[ph] = ncnt;
    __syncthreads();
    if (tid < 128) {
        float s = ssm4[0][tid] + ssm4[1][tid] + ssm4[2][tid] + ssm4[3][tid];
        g_s0[b * Cd + tid] = s;
    }
    if (tid == 0) {
        int n = nct[0] + nct[1] + nct[2] + nct[3];
        g_alpha[b] = (n > 1) ? 1.0f / (float)(n - 1) : 0.f;
    }
}

// ======================================================================
// K_gnn3: ALL 3 GNN layers + weff + tv + pool, one CTA per batch.
// grid=296 (2 reps), block=256, 2 CTAs/SM. BM=128, BN=128.
// ======================================================================
#define GNN3_DSMEM (34816 * 3 + 6144)
__global__ void __launch_bounds__(256, 2)
k_gnn3(const float* __restrict__ Wr, const float* __restrict__ Wl,
       const float* __restrict__ bl, const float* __restrict__ ln_g,
       const float* __restrict__ ln_b, const float* __restrict__ ss,
       const float* __restrict__ Wsc, const float* __restrict__ bsc,
       float* __restrict__ out) {
    extern __shared__ char smc[];
    __half* W = (__half*)smc;                      // 128 x LDAh
    __half* Ab0 = (__half*)(smc + 34816);          // 2 x 128 x LDAh
    float* fx = (float*)(smc + 34816 * 3);
    float* tvs = fx;        float* gsh = fx + 128;
    float* bsh = fx + 256;  float* msk = fx + 384;
    float* sacc = fx + 512; float* mus = fx + 640;
    float* rss = fx + 768;  float* redS = fx + 896;   // [128][2]
    float* redQ = fx + 1152;                          // [128][2]
    float* ssm = fx + 1408;                           // 128
    float* pm  = fx + 896;                            // pool mask overlay (512)

    int tid = threadIdx.x, wid = tid >> 5, lane = tid & 31;
    int wm = wid >> 1, wn = wid & 1;
    int gid = lane >> 2, tig = lane & 3;

    if (tid < 128) { gsh[tid] = ln_g[tid]; bsh[tid] = ln_b[tid]; }

    uint32_t Wsb = (uint32_t)__cvta_generic_to_shared(W);
    uint32_t Asb = (uint32_t)__cvta_generic_to_shared(Ab0);
    uint32_t aoff[2], boff[4];
#pragma unroll
    for (int mf = 0; mf < 2; mf++)
        aoff[mf] = (uint32_t)(((wm * 32 + mf * 16 + (lane & 15)) * LDAh + ((lane >> 4) << 3)) * 2);
#pragma unroll
    for (int p = 0; p < 4; p++) {
        int n = wn * 64 + p * 16 + (lane & 7) + ((lane >> 4) << 3);
        int koff = ((lane >> 3) & 1) << 3;
        boff[p] = Wsb + (uint32_t)((n * LDAh + koff) * 2);
    }

    __half* XB[2];
    XB[0] = g_xh0; XB[1] = g_xh1;

    for (int rep = 0; rep < 2; rep++) {
        int b = blockIdx.x + rep * 296;
        if (b >= Bsz) break;
        float alpha = g_alpha[b];

        // prefetch layer-0 tile 0
        {
            const __half* asrc = g_xh0 + (size_t)b * 512 * Cd;
            for (int u = tid; u < 2048; u += 256) {
                int r = u >> 4, j = u & 15;
                cpa16(Ab0 + r * LDAh + j * 8, asrc + r * Cd + j * 8);
            }
            asm volatile("cp.async.commit_group;\n");
        }
        if (tid < 128) { ssm[tid] = g_s0[b * Cd + tid]; sacc[tid] = 0.f; }
        __syncthreads();

        int bufi = 0;
        for (int l = 0; l < 3; l++) {
            const float* Wr_l = Wr + l * 16384;
            const float* Wl_l = Wl + l * 16384;
            // ---- stage W_eff = Wr - alpha*Wl into smem (fp32 -> fp16) ----
            for (int u = tid; u < 2048; u += 256) {
                int n = u >> 4, j = u & 15;                      // 8 floats
                const float4* wr4 = (const float4*)(Wr_l + n * 128 + j * 8);
                const float4* wl4 = (const float4*)(Wl_l + n * 128 + j * 8);
                float4 a0 = wr4[0], a1 = wr4[1];
                float4 c0 = wl4[0], c1 = wl4[1];
                __half2* d = (__half2*)(W + n * LDAh + j * 8);
                d[0] = __floats2half2_rn(a0.x - alpha * c0.x, a0.y - alpha * c0.y);
                d[1] = __floats2half2_rn(a0.z - alpha * c0.z, a0.w - alpha * c0.w);
                d[2] = __floats2half2_rn(a1.x - alpha * c1.x, a1.y - alpha * c1.y);
                d[3] = __floats2half2_rn(a1.z - alpha * c1.z, a1.w - alpha * c1.w);
            }
            // ---- tv[c] = alpha*(s . Wl[c]) + bl[c]  (fp32) ----
            if (tid < 128) {
                const float4* wl4 = (const float4*)(Wl_l + tid * 128);
                float a0 = 0.f, a1 = 0.f, a2 = 0.f, a3 = 0.f;
#pragma unroll
                for (int k4 = 0; k4 < 32; k4 += 4) {
                    float4 w0 = wl4[k4], w1 = wl4[k4 + 1], w2 = wl4[k4 + 2], w3 = wl4[k4 + 3];
                    a0 += ssm[k4 * 4 + 0] * w0.x + ssm[k4 * 4 + 1] * w0.y + ssm[k4 * 4 + 2] * w0.z + ssm[k4 * 4 + 3] * w0.w;
                    a1 += ssm[k4 * 4 + 4] * w1.x + ssm[k4 * 4 + 5] * w1.y + ssm[k4 * 4 + 6] * w1.z + ssm[k4 * 4 + 7] * w1.w;
                    a2 += ssm[k4 * 4 + 8] * w2.x + ssm[k4 * 4 + 9] * w2.y + ssm[k4 * 4 + 10] * w2.z + ssm[k4 * 4 + 11] * w2.w;
                    a3 += ssm[k4 * 4 + 12] * w3.x + ssm[k4 * 4 + 13] * w3.y + ssm[k4 * 4 + 14] * w3.z + ssm[k4 * 4 + 15] * w3.w;
                }
                tvs[tid] = alpha * (a0 + a1 + a2 + a3) + bl[l * 128 + tid];
            }
            __syncthreads();

            const __half* xin = XB[(l == 1) ? 1 : 0];
            __half* xout = XB[(l == 1) ? 0 : 1];
            int last = (l == 2);

            for (int tt = 0; tt < 4; tt++) {
                int row0 = b * 512 + tt * 128;
                // next tile to prefetch (within rep): same layer or next layer tile 0
                bool havenext;
                const __half* nsrc;
                if (tt < 3) { havenext = true; nsrc = xin + (size_t)(row0 + 128) * Cd; }
                else if (l < 2) {
                    havenext = true;
                    const __half* nin = XB[(l + 1 == 1) ? 1 : 0];
                    nsrc = nin + (size_t)b * 512 * Cd;
                } else havenext = false;
                if (havenext) {
                    __half* dst = Ab0 + (bufi ^ 1) * (128 * LDAh);
                    for (int u = tid; u < 2048; u += 256) {
                        int r = u >> 4, j = u & 15;
                        cpa16(dst + r * LDAh + j * 8, nsrc + r * Cd + j * 8);
                    }
                    asm volatile("cp.async.commit_group;\n");
                }
                if (tid < 128) msk[tid] = g_m[row0 + tid];
                if (havenext) asm volatile("cp.async.wait_group 1;\n");
                else          asm volatile("cp.async.wait_group 0;\n");
                __syncthreads();

                uint32_t ab = Asb + (uint32_t)(bufi * (128 * LDAh * 2));
                float acc[2][8][4];
#pragma unroll
                for (int a0 = 0; a0 < 2; a0++)
#pragma unroll
                    for (int a1 = 0; a1 < 8; a1++)
#pragma unroll
                        for (int a2 = 0; a2 < 4; a2++) acc[a0][a1][a2] = 0.f;

#pragma unroll
                for (int ks = 0; ks < 128; ks += 16) {
                    unsigned af[2][4], bf[8][2];
#pragma unroll
                    for (int mf = 0; mf < 2; mf++)
                        ldsm4(af[mf][0], af[mf][1], af[mf][2], af[mf][3], ab + aoff[mf] + ks * 2);
#pragma unroll
                    for (int p = 0; p < 4; p++)
                        ldsm4(bf[p * 2][0], bf[p * 2][1], bf[p * 2 + 1][0], bf[p * 2 + 1][1],
                              boff[p] + ks * 2);
#pragma unroll
                    for (int mf = 0; mf < 2; mf++)
#pragma unroll
                        for (int nf = 0; nf < 8; nf++)
                            mmaf16(acc[mf][nf], af[mf], bf[nf][0], bf[nf][1]);
                }
                __syncthreads();

                // relu(y + tv)
#pragma unroll
                for (int mf = 0; mf < 2; mf++)
#pragma unroll
                    for (int nf = 0; nf < 8; nf++) {
                        int col = wn * 64 + nf * 8 + 2 * tig;
                        float tv0 = tvs[col], tv1 = tvs[col + 1];
#pragma unroll
                        for (int rp = 0; rp < 2; rp++) {
                            acc[mf][nf][rp * 2]     = fmaxf(acc[mf][nf][rp * 2]     + tv0, 0.f);
                            acc[mf][nf][rp * 2 + 1] = fmaxf(acc[mf][nf][rp * 2 + 1] + tv1, 0.f);
                        }
                    }
                // row partial sums
#pragma unroll
                for (int mf = 0; mf < 2; mf++)
#pragma unroll
                    for (int rp = 0; rp < 2; rp++) {
                        float s = 0.f, q = 0.f;
#pragma unroll
                        for (int nf = 0; nf < 8; nf++) {
                            float v0 = acc[mf][nf][rp * 2], v1 = acc[mf][nf][rp * 2 + 1];
                            s += v0 + v1; q += v0 * v0 + v1 * v1;
                        }
                        s = shred2(s); q = shred2(q);
                        if (tig == 0) {
                            int r = wm * 32 + mf * 16 + rp * 8 + gid;
                            redS[r * 2 + wn] = s;
                            redQ[r * 2 + wn] = q;
                        }
                    }
                __syncthreads();
                if (tid < 128) {
                    float s = redS[tid * 2] + redS[tid * 2 + 1];
                    float q = redQ[tid * 2] + redQ[tid * 2 + 1];
                    float mu = s * (1.0f / 128.0f);
                    float var = fmaxf(q * (1.0f / 128.0f) - mu * mu, 0.f);
                    mus[tid] = mu;
                    rss[tid] = rsqrtf(var + EPSL);
                }
                __syncthreads();
                float csum[8][2];
#pragma unroll
                for (int nf = 0; nf < 8; nf++) { csum[nf][0] = 0.f; csum[nf][1] = 0.f; }
#pragma unroll
                for (int mf = 0; mf < 2; mf++)
#pragma unroll
                    for (int rp = 0; rp < 2; rp++) {
                        int r = wm * 32 + mf * 16 + rp * 8 + gid;
                        float mu = mus[r], rs = rss[r], mk = msk[r];
#pragma unroll
                        for (int nf = 0; nf < 8; nf++) {
                            int col = wn * 64 + nf * 8 + 2 * tig;
                            float x0 = (acc[mf][nf][rp * 2]     - mu) * rs * gsh[col] + bsh[col];
                            float x1 = (acc[mf][nf][rp * 2 + 1] - mu) * rs * gsh[col + 1] + bsh[col + 1];
                            *(__half2*)(xout + (size_t)(row0 + r) * Cd + col) = __floats2half2_rn(x0, x1);
                            csum[nf][0] += mk * x0;
                            csum[nf][1] += mk * x1;
                        }
                    }
                if (!last) {
#pragma unroll
                    for (int nf = 0; nf < 8; nf++) {
                        csum[nf][0] = shredg(csum[nf][0]);
                        csum[nf][1] = shredg(csum[nf][1]);
                    }
                    if (gid == 0) {
#pragma unroll
                        for (int nf = 0; nf < 8; nf++) {
                            int col = wn * 64 + nf * 8 + 2 * tig;
                            atomicAdd(&sacc[col], csum[nf][0]);
                            atomicAdd(&sacc[col + 1], csum[nf][1]);
                        }
                    }
                }
                __syncthreads();
                bufi ^= 1;
            }
            // s for next layer
            if (l < 2) {
                if (tid < 128) { ssm[tid] = sacc[tid]; sacc[tid] = 0.f; }
                __syncthreads();
            }
        }

        // ---- fused pooling + mv_emb for batch b (x in g_xh1, L2-hot) ----
        for (int p = tid; p < 512; p += 256) pm[p] = g_m[b * 512 + p];
        __syncthreads();
        if (tid < 128) {
            int c = tid;
            float aj[8], ak[8];
#pragma unroll
            for (int q = 0; q < 8; q++) { aj[q] = 0.f; ak[q] = 0.f; }
            const __half* xb = g_xh1 + (size_t)b * 512 * Cd + c;
            for (int i = 0; i < 8; i++) {
                float ai = 0.f;
#pragma unroll
                for (int jk = 0; jk < 64; jk++) {
                    int p = i * 64 + jk;
                    float v = pm[p] * __half2float(xb[(size_t)p * Cd]);
                    ai += v; aj[jk >> 3] += v; ak[jk & 7] += v;
                }
                out[((size_t)b * 26 + i) * Cd + c] = ai * 0.015625f;
            }
#pragma unroll
            for (int q = 0; q < 8; q++) {
                out[((size_t)b * 26 + 8 + q) * Cd + c] = aj[q] * 0.015625f;
                out[((size_t)b * 26 + 16 + q) * Cd + c] = ak[q] * 0.015625f;
            }
            out[((size_t)b * 26 + 25) * Cd + c] = fmaxf(ss[b] * Wsc[c] + bsc[c], 0.f);
        }
        __syncthreads();
    }
}

// ======================================================================
// K_tf: fully-fused transformer (unchanged from R8)
// ======================================================================
#define TF_SMEM 190976
#define QLD 392
__global__ void __launch_bounds__(256, 1)
k_tf(const int* __restrict__ xx,
     const float* __restrict__ bact,
     const float* __restrict__ bqkv, const float* __restrict__ bo,
     const float* __restrict__ b1g, const float* __restrict__ b2g,
     const float* __restrict__ ln1_g, const float* __restrict__ ln1_b,
     const float* __restrict__ ln2_g, const float* __restrict__ ln2_b,
     float* __restrict__ out) {
    extern __shared__ char sm[];
    __half* sW0  = (__half*)sm;
    __half* sW1  = (__half*)(sm + 34816);
    __half* buf1 = (__half*)(sm + 69632);
    __half* hS   = (__half*)(sm + 87040);
    __half* qkvS = (__half*)(sm + 104448);
    float*  aS   = (float*)(sm + 154624);
    float*  redS = (float*)(sm + 188416);
    float*  redQ = redS + 256;
    float*  mus  = redQ + 256;
    float*  rss  = mus + 64;

    int tid = threadIdx.x, wid = tid >> 5, lane = tid & 31;
    int wm = wid & 1, wn = wid >> 1;
    int gid = lane >> 2, tig = lane & 3;
    int row0 = blockIdx.x * 60;
    int b0 = blockIdx.x * 4;

    uint32_t sWb[2] = { (uint32_t)__cvta_generic_to_shared(sW0),
                        (uint32_t)__cvta_generic_to_shared(sW1) };
    uint32_t bufB = (uint32_t)__cvta_generic_to_shared(buf1);
    uint32_t hSB  = (uint32_t)__cvta_generic_to_shared(hS);
    uint32_t aoff[2], boff[2];
#pragma unroll
    for (int mf = 0; mf < 2; mf++)
        aoff[mf] = (uint32_t)(((wm * 32 + mf * 16 + (lane & 15)) * LDAh + ((lane >> 4) << 3)) * 2);
#pragma unroll
    for (int p = 0; p < 2; p++) {
        int n = wn * 32 + p * 16 + (lane & 7) + ((lane >> 4) << 3);
        int koff = ((lane >> 3) & 1) << 3;
        boff[p] = (uint32_t)((n * LDAh + koff) * 2);
    }

    const __half* wptr[28]; int wstr[28];
    {
        int i = 0;
        for (int kc = 0; kc < 512; kc += 128) { wptr[i] = g_Wacth + kc; wstr[i++] = 512; }
        for (int l = 0; l < 2; l++) {
            for (int nt = 0; nt < 3; nt++) { wptr[i] = g_Wqkvh + l * 49152 + nt * 16384; wstr[i++] = 128; }
            wptr[i] = g_Woh + l * 16384; wstr[i++] = 128;
            for (int kt = 0; kt < 4; kt++) {
                wptr[i] = g_W1h + l * 65536 + kt * 16384; wstr[i++] = 128;
                wptr[i] = g_W2h + l * 65536 + kt * 128;  wstr[i++] = 512;
            }
        }
    }
    int ipre = 0, iuse = 0;
    auto PRE = [&]() {
        if (ipre >= 28) return;
        const __half* src = wptr[ipre];
        int st = wstr[ipre];
        __half* dst = (ipre & 1) ? sW1 : sW0;
        for (int u = tid; u < 2048; u += 256) {
            int n = u >> 4, j = u & 15;
            cpa16(dst + n * LDAh + j * 8, src + (size_t)n * st + j * 8);
        }
        asm volatile("cp.async.commit_group;\n");
        ipre++;
    };
    auto WAITW = [&]() {
        if (ipre - iuse > 1) asm volatile("cp.async.wait_group 1;\n");
        else                 asm volatile("cp.async.wait_group 0;\n");
    };
    auto MML = [&](uint32_t ab, float (&acc)[2][4][4]) {
        uint32_t wb = sWb[iuse & 1];
#pragma unroll
        for (int ks = 0; ks < 128; ks += 16) {
            unsigned af[2][4], bf[4][2];
#pragma unroll
            for (int mf = 0; mf < 2; mf++)
                ldsm4(af[mf][0], af[mf][1], af[mf][2], af[mf][3], ab + aoff[mf] + ks * 2);
#pragma unroll
            for (int p = 0; p < 2; p++)
                ldsm4(bf[p * 2][0], bf[p * 2][1], bf[p * 2 + 1][0], bf[p * 2 + 1][1],
                      wb + boff[p] + ks * 2);
#pragma unroll
            for (int mf = 0; mf < 2; mf++)
#pragma unroll
                for (int nf = 0; nf < 4; nf++)
                    mmaf16(acc[mf][nf], af[mf], bf[nf][0], bf[nf][1]);
        }
        iuse++;
    };
    auto ZA = [&](float (&acc)[2][4][4]) {
#pragma unroll
        for (int a0 = 0; a0 < 2; a0++)
#pragma unroll
            for (int a1 = 0; a1 < 4; a1++)
#pragma unroll
                for (int a2 = 0; a2 < 4; a2++) acc[a0][a1][a2] = 0.f;
    };
    auto EPILN = [&](float (&acc)[2][4][4], const float* bias,
                     const float* lng, const float* lnb, int addRes, int doLN) {
        int gnb = wn * 32 + tig * 2;
#pragma unroll
        for (int mf = 0; mf < 2; mf++)
#pragma unroll
            for (int rp = 0; rp < 2; rp++) {
                int gm = wm * 32 + mf * 16 + rp * 8 + gid;
#pragma unroll
                for (int nf = 0; nf < 4; nf++) {
                    int c = gnb + nf * 8;
                    float v0 = acc[mf][nf][rp * 2] + bias[c];
                    float v1 = acc[mf][nf][rp * 2 + 1] + bias[c + 1];
                    if (addRes) { v0 += aS[gm * 132 + c]; v1 += aS[gm * 132 + c + 1]; }
                    acc[mf][nf][rp * 2] = v0;
                    acc[mf][nf][rp * 2 + 1] = v1;
                    aS[gm * 132 + c] = v0;
                    aS[gm * 132 + c + 1] = v1;
                }
            }
        if (!doLN) { __syncthreads(); return; }
#pragma unroll
        for (int mf = 0; mf < 2; mf++)
#pragma unroll
            for (int rp = 0; rp < 2; rp++) {
                float s = 0.f, q = 0.f;
#pragma unroll
                for (int nf = 0; nf < 4; nf++) {
                    float v0 = acc[mf][nf][rp * 2], v1 = acc[mf][nf][rp * 2 + 1];
                    s += v0 + v1; q += v0 * v0 + v1 * v1;
                }
                s = shred2(s); q = shred2(q);
                if (tig == 0) {
                    int r = wm * 32 + mf * 16 + rp * 8 + gid;
                    redS[r * 4 + wn] = s;
                    redQ[r * 4 + wn] = q;
                }
            }
        __syncthreads();
        if (tid < 64) {
            float s = redS[tid * 4] + redS[tid * 4 + 1] + redS[tid * 4 + 2] + redS[tid * 4 + 3];
            float q = redQ[tid * 4] + redQ[tid * 4 + 1] + redQ[tid * 4 + 2] + redQ[tid * 4 + 3];
            float mu = s * (1.0f / 128.0f);
            float var = fmaxf(q * (1.0f / 128.0f) - mu * mu, 0.f);
            mus[tid] = mu;
            rss[tid] = rsqrtf(var + EPSL);
        }
        __syncthreads();
#pragma unroll
        for (int mf = 0; mf < 2; mf++)
#pragma unroll
            for (int rp = 0; rp < 2; rp++) {
                int r = wm * 32 + mf * 16 + rp * 8 + gid;
                float mu = mus[r], rs = rss[r];
#pragma unroll
                for (int nf = 0; nf < 4; nf++) {
                    int c = gnb + nf * 8;
                    float x0 = (acc[mf][nf][rp * 2] - mu) * rs * lng[c] + lnb[c];
                    float x1 = (acc[mf][nf][rp * 2 + 1] - mu) * rs * lng[c + 1] + lnb[c + 1];
                    *(__half2*)(hS + r * LDAh + c) = __floats2half2_rn(x0, x1);
                }
            }
        __syncthreads();
    };

    float acc[2][4][4];

    PRE();
    ZA(acc);
    for (int kc = 0; kc < 512; kc += 128) {
        PRE();
        for (int u = tid; u < 2048; u += 256) {
            int r = u >> 5, j = u & 31;
            int gr = row0 + r;
            if (r >= 60) gr = row0;
            int bb = gr / 15, tt = gr - bb * 15;
            int4 v = ((const int4*)(xx + ((size_t)bb * 16 + tt + 1) * 512 + kc))[j];
            __half2* d = (__half2*)(buf1 + r * LDAh + j * 4);
            d[0] = __floats2half2_rn((float)v.x, (float)v.y);
            d[1] = __floats2half2_rn((float)v.z, (float)v.w);
        }
        WAITW();
        __syncthreads();
        MML(bufB, acc);
        __syncthreads();
    }
    EPILN(acc, bact, ln1_g, ln1_b, 0, 1);

    for (int l = 0; l < 2; l++) {
        for (int nt = 0; nt < 3; nt++) {
            PRE(); WAITW(); __syncthreads();
            ZA(acc);
            MML(hSB, acc);
            __syncthreads();
            {
                int gnb = wn * 32 + tig * 2;
                const float* bias = bqkv + l * 384 + nt * 128;
#pragma unroll
                for (int mf = 0; mf < 2; mf++)
#pragma unroll
                    for (int rp = 0; rp < 2; rp++) {
                        int gm = wm * 32 + mf * 16 + rp * 8 + gid;
#pragma unroll
                        for (int nf = 0; nf < 4; nf++) {
                            int c = gnb + nf * 8;
                            *(__half2*)(qkvS + gm * QLD + nt * 128 + c) =
                                __floats2half2_rn(acc[mf][nf][rp * 2] + bias[c],
                                                  acc[mf][nf][rp * 2 + 1] + bias[c + 1]);
                        }
                    }
            }
        }
        __syncthreads();
        for (int task = wid; task < 16; task += 8) {
            int bloc = task >> 2, head = task & 3;
            if (lane < 15) {
                const __half2* qp = (const __half2*)(qkvS + (bloc * 15 + lane) * QLD + head * 32);
                float qr[32];
#pragma unroll
                for (int d2 = 0; d2 < 16; d2++) {
                    float2 f = __half22float2(qp[d2]);
                    qr[d2 * 2] = f.x; qr[d2 * 2 + 1] = f.y;
                }
                float sc[15], mx = -1e30f;
#pragma unroll
                for (int tk = 0; tk < 15; tk++) {
                    const __half2* kp = (const __half2*)(qkvS + (bloc * 15 + tk) * QLD + 128 + head * 32);
                    float a = 0.f;
#pragma unroll
                    for (int d2 = 0; d2 < 16; d2++) {
                        float2 f = __half22float2(kp[d2]);
                        a += qr[d2 * 2] * f.x + qr[d2 * 2 + 1] * f.y;
                    }
                    sc[tk] = a * 0.17677669529663687f;
                    mx = fmaxf(mx, sc[tk]);
                }
                float ssum = 0.f;
#pragma unroll
                for (int tk = 0; tk < 15; tk++) { sc[tk] = expf(sc[tk] - mx); ssum += sc[tk]; }
                float inv = 1.0f / ssum;
                float od[32];
#pragma unroll
                for (int d = 0; d < 32; d++) od[d] = 0.f;
#pragma unroll
                for (int tk = 0; tk < 15; tk++) {
                    float p = sc[tk] * inv;
                    const __half2* vp = (const __half2*)(qkvS + (bloc * 15 + tk) * QLD + 256 + head * 32);
#pragma unroll
                    for (int d2 = 0; d2 < 16; d2++) {
                        float2 f = __half22float2(vp[d2]);
                        od[d2 * 2] += p * f.x; od[d2 * 2 + 1] += p * f.y;
                    }
                }
                __half2* op = (__half2*)(buf1 + (bloc * 15 + lane) * LDAh + head * 32);
#pragma unroll
                for (int d2 = 0; d2 < 16; d2++)
                    op[d2] = __floats2half2_rn(od[d2 * 2], od[d2 * 2 + 1]);
            }
        }
        __syncthreads();
        PRE(); WAITW(); __syncthreads();
        ZA(acc);
        MML(bufB, acc);
        __syncthreads();
        EPILN(acc, bo + l * 128, ln2_g + l * 128, ln2_b + l * 128, 1, 1);
        float acc2[2][4][4];
        ZA(acc2);
        for (int kt = 0; kt < 4; kt++) {
            PRE(); WAITW(); __syncthreads();
            ZA(acc);
            MML(hSB, acc);
            __syncthreads();
            {
                int gnb = wn * 32 + tig * 2;
                const float* bias = b1g + l * 512 + kt * 128;
#pragma unroll
                for (int mf = 0; mf < 2; mf++)
#pragma unroll
                    for (int rp = 0; rp < 2; rp++) {
                        int gm = wm * 32 + mf * 16 + rp * 8 + gid;
#pragma unroll
                        for (int nf = 0; nf < 4; nf++) {
                            int c = gnb + nf * 8;
                            float v0 = fmaxf(acc[mf][nf][rp * 2] + bias[c], 0.f);
                            float v1 = fmaxf(acc[mf][nf][rp * 2 + 1] + bias[c + 1], 0.f);
                            *(__half2*)(buf1 + gm * LDAh + c) = __floats2half2_rn(v0, v1);
                        }
                    }
            }
            __syncthreads();
            PRE(); WAITW(); __syncthreads();
            MML(bufB, acc2);
            __syncthreads();
        }
        if (l == 0) {
            EPILN(acc2, b2g, ln1_g + 128, ln1_b + 128, 1, 1);
        } else {
            EPILN(acc2, b2g + 128, nullptr, nullptr, 1, 0);
            if (tid < 128) {
#pragma unroll
                for (int lb = 0; lb < 4; lb++) {
                    float s = 0.f;
#pragma unroll
                    for (int t = 0; t < 15; t++) s += aS[(lb * 15 + t) * 132 + tid];
                    out[((size_t)(b0 + lb) * 26 + 24) * 128 + tid] = s * (1.0f / 15.0f);
                }
            }
        }
    }
}

// ======================================================================
// host launcher — 4 launches total
// ======================================================================
extern "C" void kernel_launch(void* const* d_in, const int* in_sizes, int n_in,
                              void* d_out, int out_size) {
    const int*   xx    = (const int*)d_in[0];
    const float* ss    = (const float*)d_in[1];
    const float* Win   = (const float*)d_in[2];
    const float* b_in  = (const float*)d_in[3];
    const float* Wl    = (const float*)d_in[4];
    const float* bl    = (const float*)d_in[5];
    const float* Wr    = (const float*)d_in[6];
    const float* ln_g  = (const float*)d_in[7];
    const float* ln_b  = (const float*)d_in[8];
    const float* Wqkv  = (const float*)d_in[9];
    const float* bqkv  = (const float*)d_in[10];
    const float* Wo    = (const float*)d_in[11];
    const float* bo    = (const float*)d_in[12];
    const float* ln1_g = (const float*)d_in[13];
    const float* ln1_b = (const float*)d_in[14];
    const float* ln2_g = (const float*)d_in[15];
    const float* ln2_b = (const float*)d_in[16];
    const float* W1    = (const float*)d_in[17];
    const float* b1    = (const float*)d_in[18];
    const float* W2    = (const float*)d_in[19];
    const float* b2    = (const float*)d_in[20];
    const float* Wact  = (const float*)d_in[21];
    const float* bact  = (const float*)d_in[22];
    const float* Wsc   = (const float*)d_in[23];
    const float* bsc   = (const float*)d_in[24];
    float* out = (float*)d_out;

    cudaFuncSetAttribute(k_gnn3, cudaFuncAttributeMaxDynamicSharedMemorySize, GNN3_DSMEM);
    cudaFuncSetAttribute(k_tf, cudaFuncAttributeMaxDynamicSharedMemorySize, TF_SMEM);

    k_wtf<<<448, 256>>>(Wqkv, Wo, W1, W2, Wact);                          // 1
    k_init<<<Bsz, 512>>>(xx, ss, Win, b_in);                              // 2
    k_tf<<<128, 256, TF_SMEM>>>(xx, bact, bqkv, bo, b1, b2,               // 3
                                ln1_g, ln1_b, ln2_g, ln2_b, out);
    k_gnn3<<<296, 256, GNN3_DSMEM>>>(Wr, Wl, bl, ln_g, ln_b,              // 4 <- profiled
                                     ss, Wsc, bsc, out);
}

// round 10
// speedup vs baseline: 3.3969x; 1.0412x over previous
#include <cuda_runtime.h>
#include <cuda_fp16.h>
#include <cstdint>
#include <cstddef>

#define Bsz  512
#define S3v  512
#define Cd   128
#define Mrows (Bsz * S3v)
#define EPSL 1e-5f
#define LDAh 136   // halves per staged row (272B, 16B aligned)

// ---------------- device scratch ----------------
__device__ __half g_xh0[(size_t)Mrows * Cd];
__device__ __half g_xh1[(size_t)Mrows * Cd];
__device__ __half g_Wqkvh[2 * 384 * 128];
__device__ __half g_Woh[2 * 128 * 128];
__device__ __half g_W1h[2 * 512 * 128];
__device__ __half g_W2h[2 * 128 * 512];
__device__ __half g_Wacth[128 * 512];
__device__ float g_s0[Bsz * Cd];
__device__ float g_alpha[Bsz];
__device__ float g_m[Mrows];

// ---------------- helpers ----------------
__device__ __forceinline__ void mmaf16(float* d, const unsigned* a, unsigned b0, unsigned b1) {
    asm("mma.sync.aligned.m16n8k16.row.col.f32.f16.f16.f32 "
        "{%0,%1,%2,%3},{%4,%5,%6,%7},{%8,%9},{%0,%1,%2,%3};"
        : "+f"(d[0]), "+f"(d[1]), "+f"(d[2]), "+f"(d[3])
        : "r"(a[0]), "r"(a[1]), "r"(a[2]), "r"(a[3]), "r"(b0), "r"(b1));
}
__device__ __forceinline__ void ldsm4(unsigned& r0, unsigned& r1, unsigned& r2, unsigned& r3,
                                      uint32_t addr) {
    asm volatile("ldmatrix.sync.aligned.m8n8.x4.shared.b16 {%0,%1,%2,%3}, [%4];"
                 : "=r"(r0), "=r"(r1), "=r"(r2), "=r"(r3) : "r"(addr));
}
__device__ __forceinline__ float shred2(float v) {
    v += __shfl_xor_sync(0xffffffffu, v, 1);
    v += __shfl_xor_sync(0xffffffffu, v, 2);
    return v;
}
__device__ __forceinline__ float shredg(float v) {
    v += __shfl_xor_sync(0xffffffffu, v, 4);
    v += __shfl_xor_sync(0xffffffffu, v, 8);
    v += __shfl_xor_sync(0xffffffffu, v, 16);
    return v;
}
__device__ __forceinline__ void cpa16(void* dst_smem, const void* src) {
    uint32_t d = (uint32_t)__cvta_generic_to_shared(dst_smem);
    asm volatile("cp.async.ca.shared.global [%0], [%1], 16;\n" :: "r"(d), "l"(src));
}
__device__ __forceinline__ void barn(int id, int cnt) {
    asm volatile("bar.sync %0, %1;" :: "r"(id), "r"(cnt) : "memory");
}

// ======================================================================
// K_wtf: transformer weights fp32 -> fp16
// ======================================================================
__global__ void k_wtf(const float* __restrict__ Wqkv, const float* __restrict__ Wo,
                      const float* __restrict__ W1, const float* __restrict__ W2,
                      const float* __restrict__ Wact) {
    int idx = (blockIdx.x * 256 + threadIdx.x) * 4;
    const float* src;
    __half2* dst;
    if (idx < 98304)        { int j = idx;          src = Wqkv + j; dst = (__half2*)(g_Wqkvh + j); }
    else if (idx < 131072)  { int j = idx - 98304;  src = Wo + j;   dst = (__half2*)(g_Woh + j); }
    else if (idx < 262144)  { int j = idx - 131072; src = W1 + j;   dst = (__half2*)(g_W1h + j); }
    else if (idx < 393216)  { int j = idx - 262144; src = W2 + j;   dst = (__half2*)(g_W2h + j); }
    else                    { int j = idx - 393216; src = Wact + j; dst = (__half2*)(g_Wacth + j); }
    float4 v = *(const float4*)src;
    dst[0] = __floats2half2_rn(v.x, v.y);
    dst[1] = __floats2half2_rn(v.z, v.w);
}

// ======================================================================
// K_init
// ======================================================================
__global__ void k_init(const int* __restrict__ xx, const float* __restrict__ ss,
                       const float* __restrict__ Win, const float* __restrict__ b_in) {
    __shared__ float ssm4[4][128];
    __shared__ int nct[4];
    int b = blockIdx.x, tid = threadIdx.x;
    int ph = tid >> 7, c = tid & 127;
    float w0 = Win[c * 5 + 0], w1 = Win[c * 5 + 1], w2 = Win[c * 5 + 2];
    float w3 = Win[c * 5 + 3], w4 = Win[c * 5 + 4];
    float base = (ss[b] * 0.125f) * w4 + b_in[c];
    const int* fp = xx + (size_t)b * 16 * S3v;
    const float inv7 = 1.0f / 7.0f;
    float ssum = 0.f; int ncnt = 0;
    for (int i = 0; i < 128; i++) {
        int p = i * 4 + ph;
        int f = fp[p];
        int ii = p >> 6, jj = (p >> 3) & 7, kk = p & 7;
        float val = base + (float)ii * inv7 * w0 + (float)jj * inv7 * w1 +
                    (float)kk * inv7 * w2 + (float)f * 0.5f * w3;
        g_xh0[((size_t)b * S3v + p) * Cd + c] = __float2half_rn(val);
        if (f != 0) { ssum += val; ncnt++; }
        if (c == 0) g_m[b * S3v + p] = (f != 0) ? 1.0f : 0.0f;
    }
    ssm4[ph][c] = ssum;
    if (c == 0) nct[ph] = ncnt;
    __syncthreads();
    if (tid < 128) {
        float s = ssm4[0][tid] + ssm4[1][tid] + ssm4[2][tid] + ssm4[3][tid];
        g_s0[b * Cd + tid] = s;
    }
    if (tid == 0) {
        int n = nct[0] + nct[1] + nct[2] + nct[3];
        g_alpha[b] = (n > 1) ? 1.0f / (float)(n - 1) : 0.f;
    }
}

// ======================================================================
// K_gnn3: 3 GNN layers + weff + tv + pool, CTA per batch, 1 bar/tile.
// ======================================================================
#define GNN3_DSMEM (34816 * 3 + 6144)
__global__ void __launch_bounds__(256, 2)
k_gnn3(const float* __restrict__ Wr, const float* __restrict__ Wl,
       const float* __restrict__ bl, const float* __restrict__ ln_g,
       const float* __restrict__ ln_b, const float* __restrict__ ss,
       const float* __restrict__ Wsc, const float* __restrict__ bsc,
       float* __restrict__ out) {
    extern __shared__ char smc[];
    __half* W = (__half*)smc;                      // 128 x LDAh
    __half* Ab0 = (__half*)(smc + 34816);          // 2 x 128 x LDAh
    float* fx = (float*)(smc + 34816 * 3);
    float* tvs = fx;        float* gsh = fx + 128;
    float* bsh = fx + 256;  float* msk = fx + 384;
    float* sacc = fx + 512; float* redS = fx + 640;   // [128][2]
    float* redQ = fx + 896;                           // [128][2]
    float* ssm = fx + 1152;                           // 128
    float* pm  = fx + 640;                            // pool mask overlay (512)

    int tid = threadIdx.x, wid = tid >> 5, lane = tid & 31;
    int wm = wid >> 1, wn = wid & 1;
    int gid = lane >> 2, tig = lane & 3;

    if (tid < 128) { gsh[tid] = ln_g[tid]; bsh[tid] = ln_b[tid]; }

    uint32_t Wsb = (uint32_t)__cvta_generic_to_shared(W);
    uint32_t Asb = (uint32_t)__cvta_generic_to_shared(Ab0);
    uint32_t aoff[2], boff[4];
#pragma unroll
    for (int mf = 0; mf < 2; mf++)
        aoff[mf] = (uint32_t)(((wm * 32 + mf * 16 + (lane & 15)) * LDAh + ((lane >> 4) << 3)) * 2);
#pragma unroll
    for (int p = 0; p < 4; p++) {
        int n = wn * 64 + p * 16 + (lane & 7) + ((lane >> 4) << 3);
        int koff = ((lane >> 3) & 1) << 3;
        boff[p] = Wsb + (uint32_t)((n * LDAh + koff) * 2);
    }

    __half* XB[2];
    XB[0] = g_xh0; XB[1] = g_xh1;

    for (int rep = 0; rep < 2; rep++) {
        int b = blockIdx.x + rep * 296;
        if (b >= Bsz) break;
        float alpha = g_alpha[b];

        // prefetch layer-0 tile 0
        {
            const __half* asrc = g_xh0 + (size_t)b * 512 * Cd;
            for (int u = tid; u < 2048; u += 256) {
                int r = u >> 4, j = u & 15;
                cpa16(Ab0 + r * LDAh + j * 8, asrc + r * Cd + j * 8);
            }
            asm volatile("cp.async.commit_group;\n");
        }
        if (tid < 128) { ssm[tid] = g_s0[b * Cd + tid]; sacc[tid] = 0.f; }
        __syncthreads();

        int bufi = 0;
        for (int l = 0; l < 3; l++) {
            const float* Wr_l = Wr + l * 16384;
            const float* Wl_l = Wl + l * 16384;
            // W_eff = Wr - alpha*Wl -> smem fp16 (W reads of prev layer done:
            // covered by end-of-layer barrier)
            for (int u = tid; u < 2048; u += 256) {
                int n = u >> 4, j = u & 15;
                const float4* wr4 = (const float4*)(Wr_l + n * 128 + j * 8);
                const float4* wl4 = (const float4*)(Wl_l + n * 128 + j * 8);
                float4 a0 = wr4[0], a1 = wr4[1];
                float4 c0 = wl4[0], c1 = wl4[1];
                __half2* d = (__half2*)(W + n * LDAh + j * 8);
                d[0] = __floats2half2_rn(a0.x - alpha * c0.x, a0.y - alpha * c0.y);
                d[1] = __floats2half2_rn(a0.z - alpha * c0.z, a0.w - alpha * c0.w);
                d[2] = __floats2half2_rn(a1.x - alpha * c1.x, a1.y - alpha * c1.y);
                d[3] = __floats2half2_rn(a1.z - alpha * c1.z, a1.w - alpha * c1.w);
            }
            // tv[c] = alpha*(s . Wl[c]) + bl[c]
            if (tid < 128) {
                const float4* wl4 = (const float4*)(Wl_l + tid * 128);
                float a0 = 0.f, a1 = 0.f, a2 = 0.f, a3 = 0.f;
#pragma unroll
                for (int k4 = 0; k4 < 32; k4 += 4) {
                    float4 w0 = wl4[k4], w1 = wl4[k4 + 1], w2 = wl4[k4 + 2], w3 = wl4[k4 + 3];
                    a0 += ssm[k4 * 4 + 0] * w0.x + ssm[k4 * 4 + 1] * w0.y + ssm[k4 * 4 + 2] * w0.z + ssm[k4 * 4 + 3] * w0.w;
                    a1 += ssm[k4 * 4 + 4] * w1.x + ssm[k4 * 4 + 5] * w1.y + ssm[k4 * 4 + 6] * w1.z + ssm[k4 * 4 + 7] * w1.w;
                    a2 += ssm[k4 * 4 + 8] * w2.x + ssm[k4 * 4 + 9] * w2.y + ssm[k4 * 4 + 10] * w2.z + ssm[k4 * 4 + 11] * w2.w;
                    a3 += ssm[k4 * 4 + 12] * w3.x + ssm[k4 * 4 + 13] * w3.y + ssm[k4 * 4 + 14] * w3.z + ssm[k4 * 4 + 15] * w3.w;
                }
                tvs[tid] = alpha * (a0 + a1 + a2 + a3) + bl[l * 128 + tid];
            }

            const __half* xin = XB[(l == 1) ? 1 : 0];
            __half* xout = XB[(l == 1) ? 0 : 1];
            int last = (l == 2);

            for (int tt = 0; tt < 4; tt++) {
                int row0 = b * 512 + tt * 128;
                if (tid < 128) msk[tid] = g_m[row0 + tid];
                asm volatile("cp.async.wait_group 0;\n");
                __syncthreads();   // A tile + W + tvs + msk visible; prev reads done

                uint32_t ab = Asb + (uint32_t)(bufi * (128 * LDAh * 2));
                float acc[2][8][4];
#pragma unroll
                for (int a0 = 0; a0 < 2; a0++)
#pragma unroll
                    for (int a1 = 0; a1 < 8; a1++)
#pragma unroll
                        for (int a2 = 0; a2 < 4; a2++) acc[a0][a1][a2] = 0.f;

#pragma unroll
                for (int ks = 0; ks < 128; ks += 16) {
                    unsigned af[2][4], bf[8][2];
#pragma unroll
                    for (int mf = 0; mf < 2; mf++)
                        ldsm4(af[mf][0], af[mf][1], af[mf][2], af[mf][3], ab + aoff[mf] + ks * 2);
#pragma unroll
                    for (int p = 0; p < 4; p++)
                        ldsm4(bf[p * 2][0], bf[p * 2][1], bf[p * 2 + 1][0], bf[p * 2 + 1][1],
                              boff[p] + ks * 2);
#pragma unroll
                    for (int mf = 0; mf < 2; mf++)
#pragma unroll
                        for (int nf = 0; nf < 8; nf++)
                            mmaf16(acc[mf][nf], af[mf], bf[nf][0], bf[nf][1]);
                }

                // prefetch next tile AFTER mainloop (buffer bufi^1 free:
                // everyone past previous tile's mainloop via this tile's bar)
                {
                    bool havenext;
                    const __half* nsrc = nullptr;
                    if (tt < 3) { havenext = true; nsrc = xin + (size_t)(row0 + 128) * Cd; }
                    else if (l < 2) {
                        havenext = true;
                        const __half* nin = XB[(l + 1 == 1) ? 1 : 0];
                        nsrc = nin + (size_t)b * 512 * Cd;
                    } else havenext = false;
                    if (havenext) {
                        __half* dst = Ab0 + (bufi ^ 1) * (128 * LDAh);
                        for (int u = tid; u < 2048; u += 256) {
                            int r = u >> 4, j = u & 15;
                            cpa16(dst + r * LDAh + j * 8, nsrc + r * Cd + j * 8);
                        }
                        asm volatile("cp.async.commit_group;\n");
                    }
                }

                // ---- epilogue: relu+tv, rowsum partials, pair-group LN ----
#pragma unroll
                for (int mf = 0; mf < 2; mf++)
#pragma unroll
                    for (int nf = 0; nf < 8; nf++) {
                        int col = wn * 64 + nf * 8 + 2 * tig;
                        float tv0 = tvs[col], tv1 = tvs[col + 1];
#pragma unroll
                        for (int rp = 0; rp < 2; rp++) {
                            acc[mf][nf][rp * 2]     = fmaxf(acc[mf][nf][rp * 2]     + tv0, 0.f);
                            acc[mf][nf][rp * 2 + 1] = fmaxf(acc[mf][nf][rp * 2 + 1] + tv1, 0.f);
                        }
                    }
#pragma unroll
                for (int mf = 0; mf < 2; mf++)
#pragma unroll
                    for (int rp = 0; rp < 2; rp++) {
                        float s = 0.f, q = 0.f;
#pragma unroll
                        for (int nf = 0; nf < 8; nf++) {
                            float v0 = acc[mf][nf][rp * 2], v1 = acc[mf][nf][rp * 2 + 1];
                            s += v0 + v1; q += v0 * v0 + v1 * v1;
                        }
                        s = shred2(s); q = shred2(q);
                        if (tig == 0) {
                            int r = wm * 32 + mf * 16 + rp * 8 + gid;
                            redS[r * 2 + wn] = s;
                            redQ[r * 2 + wn] = q;
                        }
                    }
                barn(1 + wm, 64);   // only the 2 warps sharing these rows
                float csum[8][2];
#pragma unroll
                for (int nf = 0; nf < 8; nf++) { csum[nf][0] = 0.f; csum[nf][1] = 0.f; }
#pragma unroll
                for (int mf = 0; mf < 2; mf++)
#pragma unroll
                    for (int rp = 0; rp < 2; rp++) {
                        int r = wm * 32 + mf * 16 + rp * 8 + gid;
                        float s = redS[r * 2] + redS[r * 2 + 1];
                        float q = redQ[r * 2] + redQ[r * 2 + 1];
                        float mu = s * (1.0f / 128.0f);
                        float var = fmaxf(q * (1.0f / 128.0f) - mu * mu, 0.f);
                        float rs = rsqrtf(var + EPSL);
                        float mk = msk[r];
#pragma unroll
                        for (int nf = 0; nf < 8; nf++) {
                            int col = wn * 64 + nf * 8 + 2 * tig;
                            float x0 = (acc[mf][nf][rp * 2]     - mu) * rs * gsh[col] + bsh[col];
                            float x1 = (acc[mf][nf][rp * 2 + 1] - mu) * rs * gsh[col + 1] + bsh[col + 1];
                            *(__half2*)(xout + (size_t)(row0 + r) * Cd + col) = __floats2half2_rn(x0, x1);
                            if (!last) {
                                csum[nf][0] += mk * x0;
                                csum[nf][1] += mk * x1;
                            }
                        }
                    }
                if (!last) {
#pragma unroll
                    for (int nf = 0; nf < 8; nf++) {
                        csum[nf][0] = shredg(csum[nf][0]);
                        csum[nf][1] = shredg(csum[nf][1]);
                    }
                    if (gid == 0) {
#pragma unroll
                        for (int nf = 0; nf < 8; nf++) {
                            int col = wn * 64 + nf * 8 + 2 * tig;
                            atomicAdd(&sacc[col], csum[nf][0]);
                            atomicAdd(&sacc[col + 1], csum[nf][1]);
                        }
                    }
                }
                bufi ^= 1;
            }
            // end-of-layer: order atomics + mainloop reads before W restage
            __syncthreads();
            if (l < 2) {
                if (tid < 128) { ssm[tid] = sacc[tid]; sacc[tid] = 0.f; }
                __syncthreads();
            }
        }

        // ---- fused pooling + mv_emb (x in g_xh1, L2-hot) ----
        for (int p = tid; p < 512; p += 256) pm[p] = g_m[b * 512 + p];
        __syncthreads();
        if (tid < 128) {
            int c = tid;
            float aj[8], ak[8];
#pragma unroll
            for (int q = 0; q < 8; q++) { aj[q] = 0.f; ak[q] = 0.f; }
            const __half* xb = g_xh1 + (size_t)b * 512 * Cd + c;
            for (int i = 0; i < 8; i++) {
                float ai = 0.f;
#pragma unroll
                for (int jk = 0; jk < 64; jk++) {
                    int p = i * 64 + jk;
                    float v = pm[p] * __half2float(xb[(size_t)p * Cd]);
                    ai += v; aj[jk >> 3] += v; ak[jk & 7] += v;
                }
                out[((size_t)b * 26 + i) * Cd + c] = ai * 0.015625f;
            }
#pragma unroll
            for (int q = 0; q < 8; q++) {
                out[((size_t)b * 26 + 8 + q) * Cd + c] = aj[q] * 0.015625f;
                out[((size_t)b * 26 + 16 + q) * Cd + c] = ak[q] * 0.015625f;
            }
            out[((size_t)b * 26 + 25) * Cd + c] = fmaxf(ss[b] * Wsc[c] + bsc[c], 0.f);
        }
        __syncthreads();
    }
}

// ======================================================================
// K_tf: fused transformer (named-barrier LN)
// ======================================================================
#define TF_SMEM 190976
#define QLD 392
__global__ void __launch_bounds__(256, 1)
k_tf(const int* __restrict__ xx,
     const float* __restrict__ bact,
     const float* __restrict__ bqkv, const float* __restrict__ bo,
     const float* __restrict__ b1g, const float* __restrict__ b2g,
     const float* __restrict__ ln1_g, const float* __restrict__ ln1_b,
     const float* __restrict__ ln2_g, const float* __restrict__ ln2_b,
     float* __restrict__ out) {
    extern __shared__ char sm[];
    __half* sW0  = (__half*)sm;
    __half* sW1  = (__half*)(sm + 34816);
    __half* buf1 = (__half*)(sm + 69632);
    __half* hS   = (__half*)(sm + 87040);
    __half* qkvS = (__half*)(sm + 104448);
    float*  aS   = (float*)(sm + 154624);
    float*  redS = (float*)(sm + 188416);
    float*  redQ = redS + 256;

    int tid = threadIdx.x, wid = tid >> 5, lane = tid & 31;
    int wm = wid & 1, wn = wid >> 1;
    int gid = lane >> 2, tig = lane & 3;
    int row0 = blockIdx.x * 60;
    int b0 = blockIdx.x * 4;

    uint32_t sWb[2] = { (uint32_t)__cvta_generic_to_shared(sW0),
                        (uint32_t)__cvta_generic_to_shared(sW1) };
    uint32_t bufB = (uint32_t)__cvta_generic_to_shared(buf1);
    uint32_t hSB  = (uint32_t)__cvta_generic_to_shared(hS);
    uint32_t aoff[2], boff[2];
#pragma unroll
    for (int mf = 0; mf < 2; mf++)
        aoff[mf] = (uint32_t)(((wm * 32 + mf * 16 + (lane & 15)) * LDAh + ((lane >> 4) << 3)) * 2);
#pragma unroll
    for (int p = 0; p < 2; p++) {
        int n = wn * 32 + p * 16 + (lane & 7) + ((lane >> 4) << 3);
        int koff = ((lane >> 3) & 1) << 3;
        boff[p] = (uint32_t)((n * LDAh + koff) * 2);
    }

    const __half* wptr[28]; int wstr[28];
    {
        int i = 0;
        for (int kc = 0; kc < 512; kc += 128) { wptr[i] = g_Wacth + kc; wstr[i++] = 512; }
        for (int l = 0; l < 2; l++) {
            for (int nt = 0; nt < 3; nt++) { wptr[i] = g_Wqkvh + l * 49152 + nt * 16384; wstr[i++] = 128; }
            wptr[i] = g_Woh + l * 16384; wstr[i++] = 128;
            for (int kt = 0; kt < 4; kt++) {
                wptr[i] = g_W1h + l * 65536 + kt * 16384; wstr[i++] = 128;
                wptr[i] = g_W2h + l * 65536 + kt * 128;  wstr[i++] = 512;
            }
        }
    }
    int ipre = 0, iuse = 0;
    auto PRE = [&]() {
        if (ipre >= 28) return;
        const __half* src = wptr[ipre];
        int st = wstr[ipre];
        __half* dst = (ipre & 1) ? sW1 : sW0;
        for (int u = tid; u < 2048; u += 256) {
            int n = u >> 4, j = u & 15;
            cpa16(dst + n * LDAh + j * 8, src + (size_t)n * st + j * 8);
        }
        asm volatile("cp.async.commit_group;\n");
        ipre++;
    };
    auto WAITW = [&]() {
        if (ipre - iuse > 1) asm volatile("cp.async.wait_group 1;\n");
        else                 asm volatile("cp.async.wait_group 0;\n");
    };
    auto MML = [&](uint32_t ab, float (&acc)[2][4][4]) {
        uint32_t wb = sWb[iuse & 1];
#pragma unroll
        for (int ks = 0; ks < 128; ks += 16) {
            unsigned af[2][4], bf[4][2];
#pragma unroll
            for (int mf = 0; mf < 2; mf++)
                ldsm4(af[mf][0], af[mf][1], af[mf][2], af[mf][3], ab + aoff[mf] + ks * 2);
#pragma unroll
            for (int p = 0; p < 2; p++)
                ldsm4(bf[p * 2][0], bf[p * 2][1], bf[p * 2 + 1][0], bf[p * 2 + 1][1],
                      wb + boff[p] + ks * 2);
#pragma unroll
            for (int mf = 0; mf < 2; mf++)
#pragma unroll
                for (int nf = 0; nf < 4; nf++)
                    mmaf16(acc[mf][nf], af[mf], bf[nf][0], bf[nf][1]);
        }
        iuse++;
    };
    auto ZA = [&](float (&acc)[2][4][4]) {
#pragma unroll
        for (int a0 = 0; a0 < 2; a0++)
#pragma unroll
            for (int a1 = 0; a1 < 4; a1++)
#pragma unroll
                for (int a2 = 0; a2 < 4; a2++) acc[a0][a1][a2] = 0.f;
    };
    auto EPILN = [&](float (&acc)[2][4][4], const float* bias,
                     const float* lng, const float* lnb, int addRes, int doLN) {
        int gnb = wn * 32 + tig * 2;
#pragma unroll
        for (int mf = 0; mf < 2; mf++)
#pragma unroll
            for (int rp = 0; rp < 2; rp++) {
                int gm = wm * 32 + mf * 16 + rp * 8 + gid;
#pragma unroll
                for (int nf = 0; nf < 4; nf++) {
                    int c = gnb + nf * 8;
                    float v0 = acc[mf][nf][rp * 2] + bias[c];
                    float v1 = acc[mf][nf][rp * 2 + 1] + bias[c + 1];
                    if (addRes) { v0 += aS[gm * 132 + c]; v1 += aS[gm * 132 + c + 1]; }
                    acc[mf][nf][rp * 2] = v0;
                    acc[mf][nf][rp * 2 + 1] = v1;
                    aS[gm * 132 + c] = v0;
                    aS[gm * 132 + c + 1] = v1;
                }
            }
        if (!doLN) { __syncthreads(); return; }
#pragma unroll
        for (int mf = 0; mf < 2; mf++)
#pragma unroll
            for (int rp = 0; rp < 2; rp++) {
                float s = 0.f, q = 0.f;
#pragma unroll
                for (int nf = 0; nf < 4; nf++) {
                    float v0 = acc[mf][nf][rp * 2], v1 = acc[mf][nf][rp * 2 + 1];
                    s += v0 + v1; q += v0 * v0 + v1 * v1;
                }
                s = shred2(s); q = shred2(q);
                if (tig == 0) {
                    int r = wm * 32 + mf * 16 + rp * 8 + gid;
                    redS[r * 4 + wn] = s;
                    redQ[r * 4 + wn] = q;
                }
            }
        barn(1 + wm, 128);   // the 4 n-warps sharing this wm's rows
#pragma unroll
        for (int mf = 0; mf < 2; mf++)
#pragma unroll
            for (int rp = 0; rp < 2; rp++) {
                int r = wm * 32 + mf * 16 + rp * 8 + gid;
                float s = redS[r * 4] + redS[r * 4 + 1] + redS[r * 4 + 2] + redS[r * 4 + 3];
                float q = redQ[r * 4] + redQ[r * 4 + 1] + redQ[r * 4 + 2] + redQ[r * 4 + 3];
                float mu = s * (1.0f / 128.0f);
                float var = fmaxf(q * (1.0f / 128.0f) - mu * mu, 0.f);
                float rs = rsqrtf(var + EPSL);
#pragma unroll
                for (int nf = 0; nf < 4; nf++) {
                    int c = gnb + nf * 8;
                    float x0 = (acc[mf][nf][rp * 2] - mu) * rs * lng[c] + lnb[c];
                    float x1 = (acc[mf][nf][rp * 2 + 1] - mu) * rs * lng[c + 1] + lnb[c + 1];
                    *(__half2*)(hS + r * LDAh + c) = __floats2half2_rn(x0, x1);
                }
            }
        __syncthreads();
    };

    float acc[2][4][4];

    PRE();
    ZA(acc);
    for (int kc = 0; kc < 512; kc += 128) {
        PRE();
        for (int u = tid; u < 2048; u += 256) {
            int r = u >> 5, j = u & 31;
            int gr = row0 + r;
            if (r >= 60) gr = row0;
            int bb = gr / 15, tt = gr - bb * 15;
            int4 v = ((const int4*)(xx + ((size_t)bb * 16 + tt + 1) * 512 + kc))[j];
            __half2* d = (__half2*)(buf1 + r * LDAh + j * 4);
            d[0] = __floats2half2_rn((float)v.x, (float)v.y);
            d[1] = __floats2half2_rn((float)v.z, (float)v.w);
        }
        WAITW();
        __syncthreads();
        MML(bufB, acc);
        __syncthreads();
    }
    EPILN(acc, bact, ln1_g, ln1_b, 0, 1);

    for (int l = 0; l < 2; l++) {
        for (int nt = 0; nt < 3; nt++) {
            PRE(); WAITW(); __syncthreads();
            ZA(acc);
            MML(hSB, acc);
            __syncthreads();
            {
                int gnb = wn * 32 + tig * 2;
                const float* bias = bqkv + l * 384 + nt * 128;
#pragma unroll
                for (int mf = 0; mf < 2; mf++)
#pragma unroll
                    for (int rp = 0; rp < 2; rp++) {
                        int gm = wm * 32 + mf * 16 + rp * 8 + gid;
#pragma unroll
                        for (int nf = 0; nf < 4; nf++) {
                            int c = gnb + nf * 8;
                            *(__half2*)(qkvS + gm * QLD + nt * 128 + c) =
                                __floats2half2_rn(acc[mf][nf][rp * 2] + bias[c],
                                                  acc[mf][nf][rp * 2 + 1] + bias[c + 1]);
                        }
                    }
            }
        }
        __syncthreads();
        for (int task = wid; task < 16; task += 8) {
            int bloc = task >> 2, head = task & 3;
            if (lane < 15) {
                const __half2* qp = (const __half2*)(qkvS + (bloc * 15 + lane) * QLD + head * 32);
                float qr[32];
#pragma unroll
                for (int d2 = 0; d2 < 16; d2++) {
                    float2 f = __half22float2(qp[d2]);
                    qr[d2 * 2] = f.x; qr[d2 * 2 + 1] = f.y;
                }
                float sc[15], mx = -1e30f;
#pragma unroll
                for (int tk = 0; tk < 15; tk++) {
                    const __half2* kp = (const __half2*)(qkvS + (bloc * 15 + tk) * QLD + 128 + head * 32);
                    float a = 0.f;
#pragma unroll
                    for (int d2 = 0; d2 < 16; d2++) {
                        float2 f = __half22float2(kp[d2]);
                        a += qr[d2 * 2] * f.x + qr[d2 * 2 + 1] * f.y;
                    }
                    sc[tk] = a * 0.17677669529663687f;
                    mx = fmaxf(mx, sc[tk]);
                }
                float ssum = 0.f;
#pragma unroll
                for (int tk = 0; tk < 15; tk++) { sc[tk] = expf(sc[tk] - mx); ssum += sc[tk]; }
                float inv = 1.0f / ssum;
                float od[32];
#pragma unroll
                for (int d = 0; d < 32; d++) od[d] = 0.f;
#pragma unroll
                for (int tk = 0; tk < 15; tk++) {
                    float p = sc[tk] * inv;
                    const __half2* vp = (const __half2*)(qkvS + (bloc * 15 + tk) * QLD + 256 + head * 32);
#pragma unroll
                    for (int d2 = 0; d2 < 16; d2++) {
                        float2 f = __half22float2(vp[d2]);
                        od[d2 * 2] += p * f.x; od[d2 * 2 + 1] += p * f.y;
                    }
                }
                __half2* op = (__half2*)(buf1 + (bloc * 15 + lane) * LDAh + head * 32);
#pragma unroll
                for (int d2 = 0; d2 < 16; d2++)
                    op[d2] = __floats2half2_rn(od[d2 * 2], od[d2 * 2 + 1]);
            }
        }
        __syncthreads();
        PRE(); WAITW(); __syncthreads();
        ZA(acc);
        MML(bufB, acc);
        __syncthreads();
        EPILN(acc, bo + l * 128, ln2_g + l * 128, ln2_b + l * 128, 1, 1);
        float acc2[2][4][4];
        ZA(acc2);
        for (int kt = 0; kt < 4; kt++) {
            PRE(); WAITW(); __syncthreads();
            ZA(acc);
            MML(hSB, acc);
            __syncthreads();
            {
                int gnb = wn * 32 + tig * 2;
                const float* bias = b1g + l * 512 + kt * 128;
#pragma unroll
                for (int mf = 0; mf < 2; mf++)
#pragma unroll
                    for (int rp = 0; rp < 2; rp++) {
                        int gm = wm * 32 + mf * 16 + rp * 8 + gid;
#pragma unroll
                        for (int nf = 0; nf < 4; nf++) {
                            int c = gnb + nf * 8;
                            float v0 = fmaxf(acc[mf][nf][rp * 2] + bias[c], 0.f);
                            float v1 = fmaxf(acc[mf][nf][rp * 2 + 1] + bias[c + 1], 0.f);
                            *(__half2*)(buf1 + gm * LDAh + c) = __floats2half2_rn(v0, v1);
                        }
                    }
            }
            __syncthreads();
            PRE(); WAITW(); __syncthreads();
            MML(bufB, acc2);
            __syncthreads();
        }
        if (l == 0) {
            EPILN(acc2, b2g, ln1_g + 128, ln1_b + 128, 1, 1);
        } else {
            EPILN(acc2, b2g + 128, nullptr, nullptr, 1, 0);
            if (tid < 128) {
#pragma unroll
                for (int lb = 0; lb < 4; lb++) {
                    float s = 0.f;
#pragma unroll
                    for (int t = 0; t < 15; t++) s += aS[(lb * 15 + t) * 132 + tid];
                    out[((size_t)(b0 + lb) * 26 + 24) * 128 + tid] = s * (1.0f / 15.0f);
                }
            }
        }
    }
}

// ======================================================================
// host launcher — 4 launches
// ======================================================================
extern "C" void kernel_launch(void* const* d_in, const int* in_sizes, int n_in,
                              void* d_out, int out_size) {
    const int*   xx    = (const int*)d_in[0];
    const float* ss    = (const float*)d_in[1];
    const float* Win   = (const float*)d_in[2];
    const float* b_in  = (const float*)d_in[3];
    const float* Wl    = (const float*)d_in[4];
    const float* bl    = (const float*)d_in[5];
    const float* Wr    = (const float*)d_in[6];
    const float* ln_g  = (const float*)d_in[7];
    const float* ln_b  = (const float*)d_in[8];
    const float* Wqkv  = (const float*)d_in[9];
    const float* bqkv  = (const float*)d_in[10];
    const float* Wo    = (const float*)d_in[11];
    const float* bo    = (const float*)d_in[12];
    const float* ln1_g = (const float*)d_in[13];
    const float* ln1_b = (const float*)d_in[14];
    const float* ln2_g = (const float*)d_in[15];
    const float* ln2_b = (const float*)d_in[16];
    const float* W1    = (const float*)d_in[17];
    const float* b1    = (const float*)d_in[18];
    const float* W2    = (const float*)d_in[19];
    const float* b2    = (const float*)d_in[20];
    const float* Wact  = (const float*)d_in[21];
    const float* bact  = (const float*)d_in[22];
    const float* Wsc   = (const float*)d_in[23];
    const float* bsc   = (const float*)d_in[24];
    float* out = (float*)d_out;

    cudaFuncSetAttribute(k_gnn3, cudaFuncAttributeMaxDynamicSharedMemorySize, GNN3_DSMEM);
    cudaFuncSetAttribute(k_tf, cudaFuncAttributeMaxDynamicSharedMemorySize, TF_SMEM);

    k_wtf<<<448, 256>>>(Wqkv, Wo, W1, W2, Wact);                          // 1
    k_init<<<Bsz, 512>>>(xx, ss, Win, b_in);                              // 2
    k_tf<<<128, 256, TF_SMEM>>>(xx, bact, bqkv, bo, b1, b2,               // 3
                                ln1_g, ln1_b, ln2_g, ln2_b, out);
    k_gnn3<<<296, 256, GNN3_DSMEM>>>(Wr, Wl, bl, ln_g, ln_b,              // 4 <- profiled
                                     ss, Wsc, bsc, out);
}

// round 12
// speedup vs baseline: 3.4375x; 1.0120x over previous
#include <cuda_runtime.h>
#include <cuda_fp16.h>
#include <cstdint>
#include <cstddef>

#define Bsz  512
#define S3v  512
#define Cd   128
#define Mrows (Bsz * S3v)
#define EPSL 1e-5f
#define LDAh 136   // halves per staged row (272B, 16B aligned)

// ---------------- device scratch ----------------
__device__ __half g_xh0[(size_t)Mrows * Cd];
__device__ __half g_xh1[(size_t)Mrows * Cd];
__device__ __half g_Wqkvh[2 * 384 * 128];
__device__ __half g_Woh[2 * 128 * 128];
__device__ __half g_W1h[2 * 512 * 128];
__device__ __half g_W2h[2 * 128 * 512];
__device__ __half g_Wacth[128 * 512];
__device__ float g_s0[Bsz * Cd];
__device__ float g_alpha[Bsz];
__device__ float g_m[Mrows];

// ---------------- helpers ----------------
__device__ __forceinline__ void mmaf16(float* d, const unsigned* a, unsigned b0, unsigned b1) {
    asm("mma.sync.aligned.m16n8k16.row.col.f32.f16.f16.f32 "
        "{%0,%1,%2,%3},{%4,%5,%6,%7},{%8,%9},{%0,%1,%2,%3};"
        : "+f"(d[0]), "+f"(d[1]), "+f"(d[2]), "+f"(d[3])
        : "r"(a[0]), "r"(a[1]), "r"(a[2]), "r"(a[3]), "r"(b0), "r"(b1));
}
__device__ __forceinline__ void ldsm4(unsigned& r0, unsigned& r1, unsigned& r2, unsigned& r3,
                                      uint32_t addr) {
    asm volatile("ldmatrix.sync.aligned.m8n8.x4.shared.b16 {%0,%1,%2,%3}, [%4];"
                 : "=r"(r0), "=r"(r1), "=r"(r2), "=r"(r3) : "r"(addr));
}
__device__ __forceinline__ float shred2(float v) {
    v += __shfl_xor_sync(0xffffffffu, v, 1);
    v += __shfl_xor_sync(0xffffffffu, v, 2);
    return v;
}
__device__ __forceinline__ float shredg(float v) {
    v += __shfl_xor_sync(0xffffffffu, v, 4);
    v += __shfl_xor_sync(0xffffffffu, v, 8);
    v += __shfl_xor_sync(0xffffffffu, v, 16);
    return v;
}
__device__ __forceinline__ void cpa16(void* dst_smem, const void* src) {
    uint32_t d = (uint32_t)__cvta_generic_to_shared(dst_smem);
    asm volatile("cp.async.ca.shared.global [%0], [%1], 16;\n" :: "r"(d), "l"(src));
}
__device__ __forceinline__ void barn(int id, int cnt) {
    asm volatile("bar.sync %0, %1;" :: "r"(id), "r"(cnt) : "memory");
}

// ======================================================================
// K_wtf: transformer weights fp32 -> fp16
// ======================================================================
__global__ void k_wtf(const float* __restrict__ Wqkv, const float* __restrict__ Wo,
                      const float* __restrict__ W1, const float* __restrict__ W2,
                      const float* __restrict__ Wact) {
    int idx = (blockIdx.x * 256 + threadIdx.x) * 4;
    const float* src;
    __half2* dst;
    if (idx < 98304)        { int j = idx;          src = Wqkv + j; dst = (__half2*)(g_Wqkvh + j); }
    else if (idx < 131072)  { int j = idx - 98304;  src = Wo + j;   dst = (__half2*)(g_Woh + j); }
    else if (idx < 262144)  { int j = idx - 131072; src = W1 + j;   dst = (__half2*)(g_W1h + j); }
    else if (idx < 393216)  { int j = idx - 262144; src = W2 + j;   dst = (__half2*)(g_W2h + j); }
    else                    { int j = idx - 393216; src = Wact + j; dst = (__half2*)(g_Wacth + j); }
    float4 v = *(const float4*)src;
    dst[0] = __floats2half2_rn(v.x, v.y);
    dst[1] = __floats2half2_rn(v.z, v.w);
}

// ======================================================================
// K_init
// ======================================================================
__global__ void k_init(const int* __restrict__ xx, const float* __restrict__ ss,
                       const float* __restrict__ Win, const float* __restrict__ b_in) {
    __shared__ float ssm4[4][128];
    __shared__ int nct[4];
    int b = blockIdx.x, tid = threadIdx.x;
    int ph = tid >> 7, c = tid & 127;
    float w0 = Win[c * 5 + 0], w1 = Win[c * 5 + 1], w2 = Win[c * 5 + 2];
    float w3 = Win[c * 5 + 3], w4 = Win[c * 5 + 4];
    float base = (ss[b] * 0.125f) * w4 + b_in[c];
    const int* fp = xx + (size_t)b * 16 * S3v;
    const float inv7 = 1.0f / 7.0f;
    float ssum = 0.f; int ncnt = 0;
    for (int i = 0; i < 128; i++) {
        int p = i * 4 + ph;
        int f = fp[p];
        int ii = p >> 6, jj = (p >> 3) & 7, kk = p & 7;
        float val = base + (float)ii * inv7 * w0 + (float)jj * inv7 * w1 +
                    (float)kk * inv7 * w2 + (float)f * 0.5f * w3;
        g_xh0[((size_t)b * S3v + p) * Cd + c] = __float2half_rn(val);
        if (f != 0) { ssum += val; ncnt++; }
        if (c == 0) g_m[b * S3v + p] = (f != 0) ? 1.0f : 0.0f;
    }
    ssm4[ph][c] = ssum;
    if (c == 0) nct[ph] = ncnt;
    __syncthreads();
    if (tid < 128) {
        float s = ssm4[0][tid] + ssm4[1][tid] + ssm4[2][tid] + ssm4[3][tid];
        g_s0[b * Cd + tid] = s;
    }
    if (tid == 0) {
        int n = nct[0] + nct[1] + nct[2] + nct[3];
        g_alpha[b] = (n > 1) ? 1.0f / (float)(n - 1) : 0.f;
    }
}

// ======================================================================
// K_gnn3: 3 GNN layers + weff + tv + pool; ONE batch per CTA (grid=512),
// 2 CTAs/SM, 1 block-barrier per tile, named-barrier LN.
// ======================================================================
#define GNN3_DSMEM (34816 * 3 + 6144)
__global__ void __launch_bounds__(256, 2)
k_gnn3(const float* __restrict__ Wr, const float* __restrict__ Wl,
       const float* __restrict__ bl, const float* __restrict__ ln_g,
       const float* __restrict__ ln_b, const float* __restrict__ ss,
       const float* __restrict__ Wsc, const float* __restrict__ bsc,
       float* __restrict__ out) {
    extern __shared__ char smc[];
    __half* W = (__half*)smc;                      // 128 x LDAh
    __half* Ab0 = (__half*)(smc + 34816);          // 2 x 128 x LDAh
    float* fx = (float*)(smc + 34816 * 3);
    float* tvs = fx;        float* gsh = fx + 128;
    float* bsh = fx + 256;  float* msk = fx + 384;
    float* sacc = fx + 512; float* redS = fx + 640;   // [128][2]
    float* redQ = fx + 896;                           // [128][2]
    float* ssm = fx + 1152;                           // 128
    float* pm  = fx + 640;                            // pool mask overlay (512)

    int tid = threadIdx.x, wid = tid >> 5, lane = tid & 31;
    int wm = wid >> 1, wn = wid & 1;
    int gid = lane >> 2, tig = lane & 3;

    if (tid < 128) { gsh[tid] = ln_g[tid]; bsh[tid] = ln_b[tid]; }

    uint32_t Wsb = (uint32_t)__cvta_generic_to_shared(W);
    uint32_t Asb = (uint32_t)__cvta_generic_to_shared(Ab0);
    uint32_t aoff[2], boff[4];
#pragma unroll
    for (int mf = 0; mf < 2; mf++)
        aoff[mf] = (uint32_t)(((wm * 32 + mf * 16 + (lane & 15)) * LDAh + ((lane >> 4) << 3)) * 2);
#pragma unroll
    for (int p = 0; p < 4; p++) {
        int n = wn * 64 + p * 16 + (lane & 7) + ((lane >> 4) << 3);
        int koff = ((lane >> 3) & 1) << 3;
        boff[p] = Wsb + (uint32_t)((n * LDAh + koff) * 2);
    }

    __half* XB[2];
    XB[0] = g_xh0; XB[1] = g_xh1;

    int b = blockIdx.x;
    float alpha = g_alpha[b];

    // prefetch layer-0 tile 0
    {
        const __half* asrc = g_xh0 + (size_t)b * 512 * Cd;
        for (int u = tid; u < 2048; u += 256) {
            int r = u >> 4, j = u & 15;
            cpa16(Ab0 + r * LDAh + j * 8, asrc + r * Cd + j * 8);
        }
        asm volatile("cp.async.commit_group;\n");
    }
    if (tid < 128) { ssm[tid] = g_s0[b * Cd + tid]; sacc[tid] = 0.f; }
    __syncthreads();

    int bufi = 0;
    for (int l = 0; l < 3; l++) {
        const float* Wr_l = Wr + l * 16384;
        const float* Wl_l = Wl + l * 16384;
        // W_eff = Wr - alpha*Wl -> smem fp16
        for (int u = tid; u < 2048; u += 256) {
            int n = u >> 4, j = u & 15;
            const float4* wr4 = (const float4*)(Wr_l + n * 128 + j * 8);
            const float4* wl4 = (const float4*)(Wl_l + n * 128 + j * 8);
            float4 a0 = wr4[0], a1 = wr4[1];
            float4 c0 = wl4[0], c1 = wl4[1];
            __half2* d = (__half2*)(W + n * LDAh + j * 8);
            d[0] = __floats2half2_rn(a0.x - alpha * c0.x, a0.y - alpha * c0.y);
            d[1] = __floats2half2_rn(a0.z - alpha * c0.z, a0.w - alpha * c0.w);
            d[2] = __floats2half2_rn(a1.x - alpha * c1.x, a1.y - alpha * c1.y);
            d[3] = __floats2half2_rn(a1.z - alpha * c1.z, a1.w - alpha * c1.w);
        }
        // tv[c] = alpha*(s . Wl[c]) + bl[c]
        if (tid < 128) {
            const float4* wl4 = (const float4*)(Wl_l + tid * 128);
            float a0 = 0.f, a1 = 0.f, a2 = 0.f, a3 = 0.f;
#pragma unroll
            for (int k4 = 0; k4 < 32; k4 += 4) {
                float4 w0 = wl4[k4], w1 = wl4[k4 + 1], w2 = wl4[k4 + 2], w3 = wl4[k4 + 3];
                a0 += ssm[k4 * 4 + 0] * w0.x + ssm[k4 * 4 + 1] * w0.y + ssm[k4 * 4 + 2] * w0.z + ssm[k4 * 4 + 3] * w0.w;
                a1 += ssm[k4 * 4 + 4] * w1.x + ssm[k4 * 4 + 5] * w1.y + ssm[k4 * 4 + 6] * w1.z + ssm[k4 * 4 + 7] * w1.w;
                a2 += ssm[k4 * 4 + 8] * w2.x + ssm[k4 * 4 + 9] * w2.y + ssm[k4 * 4 + 10] * w2.z + ssm[k4 * 4 + 11] * w2.w;
                a3 += ssm[k4 * 4 + 12] * w3.x + ssm[k4 * 4 + 13] * w3.y + ssm[k4 * 4 + 14] * w3.z + ssm[k4 * 4 + 15] * w3.w;
            }
            tvs[tid] = alpha * (a0 + a1 + a2 + a3) + bl[l * 128 + tid];
        }

        const __half* xin = XB[(l == 1) ? 1 : 0];
        __half* xout = XB[(l == 1) ? 0 : 1];
        int last = (l == 2);

        for (int tt = 0; tt < 4; tt++) {
            int row0 = b * 512 + tt * 128;
            if (tid < 128) msk[tid] = g_m[row0 + tid];
            asm volatile("cp.async.wait_group 0;\n");
            __syncthreads();   // A tile + W + tvs + msk visible; prev reads done

            uint32_t ab = Asb + (uint32_t)(bufi * (128 * LDAh * 2));
            float acc[2][8][4];
#pragma unroll
            for (int a0 = 0; a0 < 2; a0++)
#pragma unroll
                for (int a1 = 0; a1 < 8; a1++)
#pragma unroll
                    for (int a2 = 0; a2 < 4; a2++) acc[a0][a1][a2] = 0.f;

#pragma unroll
            for (int ks = 0; ks < 128; ks += 16) {
                unsigned af[2][4], bf[8][2];
#pragma unroll
                for (int mf = 0; mf < 2; mf++)
                    ldsm4(af[mf][0], af[mf][1], af[mf][2], af[mf][3], ab + aoff[mf] + ks * 2);
#pragma unroll
                for (int p = 0; p < 4; p++)
                    ldsm4(bf[p * 2][0], bf[p * 2][1], bf[p * 2 + 1][0], bf[p * 2 + 1][1],
                          boff[p] + ks * 2);
#pragma unroll
                for (int mf = 0; mf < 2; mf++)
#pragma unroll
                    for (int nf = 0; nf < 8; nf++)
                        mmaf16(acc[mf][nf], af[mf], bf[nf][0], bf[nf][1]);
            }

            // prefetch next tile AFTER mainloop
            {
                bool havenext;
                const __half* nsrc = nullptr;
                if (tt < 3) { havenext = true; nsrc = xin + (size_t)(row0 + 128) * Cd; }
                else if (l < 2) {
                    havenext = true;
                    const __half* nin = XB[(l + 1 == 1) ? 1 : 0];
                    nsrc = nin + (size_t)b * 512 * Cd;
                } else havenext = false;
                if (havenext) {
                    __half* dst = Ab0 + (bufi ^ 1) * (128 * LDAh);
                    for (int u = tid; u < 2048; u += 256) {
                        int r = u >> 4, j = u & 15;
                        cpa16(dst + r * LDAh + j * 8, nsrc + r * Cd + j * 8);
                    }
                    asm volatile("cp.async.commit_group;\n");
                }
            }

            // ---- epilogue: relu+tv, rowsum partials, pair-group LN ----
#pragma unroll
            for (int mf = 0; mf < 2; mf++)
#pragma unroll
                for (int nf = 0; nf < 8; nf++) {
                    int col = wn * 64 + nf * 8 + 2 * tig;
                    float tv0 = tvs[col], tv1 = tvs[col + 1];
#pragma unroll
                    for (int rp = 0; rp < 2; rp++) {
                        acc[mf][nf][rp * 2]     = fmaxf(acc[mf][nf][rp * 2]     + tv0, 0.f);
                        acc[mf][nf][rp * 2 + 1] = fmaxf(acc[mf][nf][rp * 2 + 1] + tv1, 0.f);
                    }
                }
#pragma unroll
            for (int mf = 0; mf < 2; mf++)
#pragma unroll
                for (int rp = 0; rp < 2; rp++) {
                    float s = 0.f, q = 0.f;
#pragma unroll
                    for (int nf = 0; nf < 8; nf++) {
                        float v0 = acc[mf][nf][rp * 2], v1 = acc[mf][nf][rp * 2 + 1];
                        s += v0 + v1; q += v0 * v0 + v1 * v1;
                    }
                    s = shred2(s); q = shred2(q);
                    if (tig == 0) {
                        int r = wm * 32 + mf * 16 + rp * 8 + gid;
                        redS[r * 2 + wn] = s;
                        redQ[r * 2 + wn] = q;
                    }
                }
            barn(1 + wm, 64);   // only the 2 warps sharing these rows
            float csum[8][2];
#pragma unroll
            for (int nf = 0; nf < 8; nf++) { csum[nf][0] = 0.f; csum[nf][1] = 0.f; }
#pragma unroll
            for (int mf = 0; mf < 2; mf++)
#pragma unroll
                for (int rp = 0; rp < 2; rp++) {
                    int r = wm * 32 + mf * 16 + rp * 8 + gid;
                    float s = redS[r * 2] + redS[r * 2 + 1];
                    float q = redQ[r * 2] + redQ[r * 2 + 1];
                    float mu = s * (1.0f / 128.0f);
                    float var = fmaxf(q * (1.0f / 128.0f) - mu * mu, 0.f);
                    float rs = rsqrtf(var + EPSL);
                    float mk = msk[r];
#pragma unroll
                    for (int nf = 0; nf < 8; nf++) {
                        int col = wn * 64 + nf * 8 + 2 * tig;
                        float x0 = (acc[mf][nf][rp * 2]     - mu) * rs * gsh[col] + bsh[col];
                        float x1 = (acc[mf][nf][rp * 2 + 1] - mu) * rs * gsh[col + 1] + bsh[col + 1];
                        *(__half2*)(xout + (size_t)(row0 + r) * Cd + col) = __floats2half2_rn(x0, x1);
                        if (!last) {
                            csum[nf][0] += mk * x0;
                            csum[nf][1] += mk * x1;
                        }
                    }
                }
            if (!last) {
#pragma unroll
                for (int nf = 0; nf < 8; nf++) {
                    csum[nf][0] = shredg(csum[nf][0]);
                    csum[nf][1] = shredg(csum[nf][1]);
                }
                if (gid == 0) {
#pragma unroll
                    for (int nf = 0; nf < 8; nf++) {
                        int col = wn * 64 + nf * 8 + 2 * tig;
                        atomicAdd(&sacc[col], csum[nf][0]);
                        atomicAdd(&sacc[col + 1], csum[nf][1]);
                    }
                }
            }
            bufi ^= 1;
        }
        // end-of-layer: order atomics + mainloop reads before W restage
        __syncthreads();
        if (l < 2) {
            if (tid < 128) { ssm[tid] = sacc[tid]; sacc[tid] = 0.f; }
            __syncthreads();
        }
    }

    // ---- fused pooling + mv_emb (x in g_xh1, L2-hot) ----
    for (int p = tid; p < 512; p += 256) pm[p] = g_m[b * 512 + p];
    __syncthreads();
    if (tid < 128) {
        int c = tid;
        float aj[8], ak[8];
#pragma unroll
        for (int q = 0; q < 8; q++) { aj[q] = 0.f; ak[q] = 0.f; }
        const __half* xb = g_xh1 + (size_t)b * 512 * Cd + c;
        for (int i = 0; i < 8; i++) {
            float ai = 0.f;
#pragma unroll
            for (int jk = 0; jk < 64; jk++) {
                int p = i * 64 + jk;
                float v = pm[p] * __half2float(xb[(size_t)p * Cd]);
                ai += v; aj[jk >> 3] += v; ak[jk & 7] += v;
            }
            out[((size_t)b * 26 + i) * Cd + c] = ai * 0.015625f;
        }
#pragma unroll
        for (int q = 0; q < 8; q++) {
            out[((size_t)b * 26 + 8 + q) * Cd + c] = aj[q] * 0.015625f;
            out[((size_t)b * 26 + 16 + q) * Cd + c] = ak[q] * 0.015625f;
        }
        out[((size_t)b * 26 + 25) * Cd + c] = fmaxf(ss[b] * Wsc[c] + bsc[c], 0.f);
    }
}

// ======================================================================
// K_tf: fused transformer (named-barrier LN) — unchanged from R10 pass
// ======================================================================
#define TF_SMEM 190976
#define QLD 392
__global__ void __launch_bounds__(256, 1)
k_tf(const int* __restrict__ xx,
     const float* __restrict__ bact,
     const float* __restrict__ bqkv, const float* __restrict__ bo,
     const float* __restrict__ b1g, const float* __restrict__ b2g,
     const float* __restrict__ ln1_g, const float* __restrict__ ln1_b,
     const float* __restrict__ ln2_g, const float* __restrict__ ln2_b,
     float* __restrict__ out) {
    extern __shared__ char sm[];
    __half* sW0  = (__half*)sm;
    __half* sW1  = (__half*)(sm + 34816);
    __half* buf1 = (__half*)(sm + 69632);
    __half* hS   = (__half*)(sm + 87040);
    __half* qkvS = (__half*)(sm + 104448);
    float*  aS   = (float*)(sm + 154624);
    float*  redS = (float*)(sm + 188416);
    float*  redQ = redS + 256;

    int tid = threadIdx.x, wid = tid >> 5, lane = tid & 31;
    int wm = wid & 1, wn = wid >> 1;
    int gid = lane >> 2, tig = lane & 3;
    int row0 = blockIdx.x * 60;
    int b0 = blockIdx.x * 4;

    uint32_t sWb[2] = { (uint32_t)__cvta_generic_to_shared(sW0),
                        (uint32_t)__cvta_generic_to_shared(sW1) };
    uint32_t bufB = (uint32_t)__cvta_generic_to_shared(buf1);
    uint32_t hSB  = (uint32_t)__cvta_generic_to_shared(hS);
    uint32_t aoff[2], boff[2];
#pragma unroll
    for (int mf = 0; mf < 2; mf++)
        aoff[mf] = (uint32_t)(((wm * 32 + mf * 16 + (lane & 15)) * LDAh + ((lane >> 4) << 3)) * 2);
#pragma unroll
    for (int p = 0; p < 2; p++) {
        int n = wn * 32 + p * 16 + (lane & 7) + ((lane >> 4) << 3);
        int koff = ((lane >> 3) & 1) << 3;
        boff[p] = (uint32_t)((n * LDAh + koff) * 2);
    }

    const __half* wptr[28]; int wstr[28];
    {
        int i = 0;
        for (int kc = 0; kc < 512; kc += 128) { wptr[i] = g_Wacth + kc; wstr[i++] = 512; }
        for (int l = 0; l < 2; l++) {
            for (int nt = 0; nt < 3; nt++) { wptr[i] = g_Wqkvh + l * 49152 + nt * 16384; wstr[i++] = 128; }
            wptr[i] = g_Woh + l * 16384; wstr[i++] = 128;
            for (int kt = 0; kt < 4; kt++) {
                wptr[i] = g_W1h + l * 65536 + kt * 16384; wstr[i++] = 128;
                wptr[i] = g_W2h + l * 65536 + kt * 128;  wstr[i++] = 512;
            }
        }
    }
    int ipre = 0, iuse = 0;
    auto PRE = [&]() {
        if (ipre >= 28) return;
        const __half* src = wptr[ipre];
        int st = wstr[ipre];
        __half* dst = (ipre & 1) ? sW1 : sW0;
        for (int u = tid; u < 2048; u += 256) {
            int n = u >> 4, j = u & 15;
            cpa16(dst + n * LDAh + j * 8, src + (size_t)n * st + j * 8);
        }
        asm volatile("cp.async.commit_group;\n");
        ipre++;
    };
    auto WAITW = [&]() {
        if (ipre - iuse > 1) asm volatile("cp.async.wait_group 1;\n");
        else                 asm volatile("cp.async.wait_group 0;\n");
    };
    auto MML = [&](uint32_t ab, float (&acc)[2][4][4]) {
        uint32_t wb = sWb[iuse & 1];
#pragma unroll
        for (int ks = 0; ks < 128; ks += 16) {
            unsigned af[2][4], bf[4][2];
#pragma unroll
            for (int mf = 0; mf < 2; mf++)
                ldsm4(af[mf][0], af[mf][1], af[mf][2], af[mf][3], ab + aoff[mf] + ks * 2);
#pragma unroll
            for (int p = 0; p < 2; p++)
                ldsm4(bf[p * 2][0], bf[p * 2][1], bf[p * 2 + 1][0], bf[p * 2 + 1][1],
                      wb + boff[p] + ks * 2);
#pragma unroll
            for (int mf = 0; mf < 2; mf++)
#pragma unroll
                for (int nf = 0; nf < 4; nf++)
                    mmaf16(acc[mf][nf], af[mf], bf[nf][0], bf[nf][1]);
        }
        iuse++;
    };
    auto ZA = [&](float (&acc)[2][4][4]) {
#pragma unroll
        for (int a0 = 0; a0 < 2; a0++)
#pragma unroll
            for (int a1 = 0; a1 < 4; a1++)
#pragma unroll
                for (int a2 = 0; a2 < 4; a2++) acc[a0][a1][a2] = 0.f;
    };
    auto EPILN = [&](float (&acc)[2][4][4], const float* bias,
                     const float* lng, const float* lnb, int addRes, int doLN) {
        int gnb = wn * 32 + tig * 2;
#pragma unroll
        for (int mf = 0; mf < 2; mf++)
#pragma unroll
            for (int rp = 0; rp < 2; rp++) {
                int gm = wm * 32 + mf * 16 + rp * 8 + gid;
#pragma unroll
                for (int nf = 0; nf < 4; nf++) {
                    int c = gnb + nf * 8;
                    float v0 = acc[mf][nf][rp * 2] + bias[c];
                    float v1 = acc[mf][nf][rp * 2 + 1] + bias[c + 1];
                    if (addRes) { v0 += aS[gm * 132 + c]; v1 += aS[gm * 132 + c + 1]; }
                    acc[mf][nf][rp * 2] = v0;
                    acc[mf][nf][rp * 2 + 1] = v1;
                    aS[gm * 132 + c] = v0;
                    aS[gm * 132 + c + 1] = v1;
                }
            }
        if (!doLN) { __syncthreads(); return; }
#pragma unroll
        for (int mf = 0; mf < 2; mf++)
#pragma unroll
            for (int rp = 0; rp < 2; rp++) {
                float s = 0.f, q = 0.f;
#pragma unroll
                for (int nf = 0; nf < 4; nf++) {
                    float v0 = acc[mf][nf][rp * 2], v1 = acc[mf][nf][rp * 2 + 1];
                    s += v0 + v1; q += v0 * v0 + v1 * v1;
                }
                s = shred2(s); q = shred2(q);
                if (tig == 0) {
                    int r = wm * 32 + mf * 16 + rp * 8 + gid;
                    redS[r * 4 + wn] = s;
                    redQ[r * 4 + wn] = q;
                }
            }
        barn(1 + wm, 128);
#pragma unroll
        for (int mf = 0; mf < 2; mf++)
#pragma unroll
            for (int rp = 0; rp < 2; rp++) {
                int r = wm * 32 + mf * 16 + rp * 8 + gid;
                float s = redS[r * 4] + redS[r * 4 + 1] + redS[r * 4 + 2] + redS[r * 4 + 3];
                float q = redQ[r * 4] + redQ[r * 4 + 1] + redQ[r * 4 + 2] + redQ[r * 4 + 3];
                float mu = s * (1.0f / 128.0f);
                float var = fmaxf(q * (1.0f / 128.0f) - mu * mu, 0.f);
                float rs = rsqrtf(var + EPSL);
#pragma unroll
                for (int nf = 0; nf < 4; nf++) {
                    int c = gnb + nf * 8;
                    float x0 = (acc[mf][nf][rp * 2] - mu) * rs * lng[c] + lnb[c];
                    float x1 = (acc[mf][nf][rp * 2 + 1] - mu) * rs * lng[c + 1] + lnb[c + 1];
                    *(__half2*)(hS + r * LDAh + c) = __floats2half2_rn(x0, x1);
                }
            }
        __syncthreads();
    };

    float acc[2][4][4];

    PRE();
    ZA(acc);
    for (int kc = 0; kc < 512; kc += 128) {
        PRE();
        for (int u = tid; u < 2048; u += 256) {
            int r = u >> 5, j = u & 31;
            int gr = row0 + r;
            if (r >= 60) gr = row0;
            int bb = gr / 15, tt = gr - bb * 15;
            int4 v = ((const int4*)(xx + ((size_t)bb * 16 + tt + 1) * 512 + kc))[j];
            __half2* d = (__half2*)(buf1 + r * LDAh + j * 4);
            d[0] = __floats2half2_rn((float)v.x, (float)v.y);
            d[1] = __floats2half2_rn((float)v.z, (float)v.w);
        }
        WAITW();
        __syncthreads();
        MML(bufB, acc);
        __syncthreads();
    }
    EPILN(acc, bact, ln1_g, ln1_b, 0, 1);

    for (int l = 0; l < 2; l++) {
        for (int nt = 0; nt < 3; nt++) {
            PRE(); WAITW(); __syncthreads();
            ZA(acc);
            MML(hSB, acc);
            __syncthreads();
            {
                int gnb = wn * 32 + tig * 2;
                const float* bias = bqkv + l * 384 + nt * 128;
#pragma unroll
                for (int mf = 0; mf < 2; mf++)
#pragma unroll
                    for (int rp = 0; rp < 2; rp++) {
                        int gm = wm * 32 + mf * 16 + rp * 8 + gid;
#pragma unroll
                        for (int nf = 0; nf < 4; nf++) {
                            int c = gnb + nf * 8;
                            *(__half2*)(qkvS + gm * QLD + nt * 128 + c) =
                                __floats2half2_rn(acc[mf][nf][rp * 2] + bias[c],
                                                  acc[mf][nf][rp * 2 + 1] + bias[c + 1]);
                        }
                    }
            }
        }
        __syncthreads();
        for (int task = wid; task < 16; task += 8) {
            int bloc = task >> 2, head = task & 3;
            if (lane < 15) {
                const __half2* qp = (const __half2*)(qkvS + (bloc * 15 + lane) * QLD + head * 32);
                float qr[32];
#pragma unroll
                for (int d2 = 0; d2 < 16; d2++) {
                    float2 f = __half22float2(qp[d2]);
                    qr[d2 * 2] = f.x; qr[d2 * 2 + 1] = f.y;
                }
                float sc[15], mx = -1e30f;
#pragma unroll
                for (int tk = 0; tk < 15; tk++) {
                    const __half2* kp = (const __half2*)(qkvS + (bloc * 15 + tk) * QLD + 128 + head * 32);
                    float a = 0.f;
#pragma unroll
                    for (int d2 = 0; d2 < 16; d2++) {
                        float2 f = __half22float2(kp[d2]);
                        a += qr[d2 * 2] * f.x + qr[d2 * 2 + 1] * f.y;
                    }
                    sc[tk] = a * 0.17677669529663687f;
                    mx = fmaxf(mx, sc[tk]);
                }
                float ssum = 0.f;
#pragma unroll
                for (int tk = 0; tk < 15; tk++) { sc[tk] = expf(sc[tk] - mx); ssum += sc[tk]; }
                float inv = 1.0f / ssum;
                float od[32];
#pragma unroll
                for (int d = 0; d < 32; d++) od[d] = 0.f;
#pragma unroll
                for (int tk = 0; tk < 15; tk++) {
                    float p = sc[tk] * inv;
                    const __half2* vp = (const __half2*)(qkvS + (bloc * 15 + tk) * QLD + 256 + head * 32);
#pragma unroll
                    for (int d2 = 0; d2 < 16; d2++) {
                        float2 f = __half22float2(vp[d2]);
                        od[d2 * 2] += p * f.x; od[d2 * 2 + 1] += p * f.y;
                    }
                }
                __half2* op = (__half2*)(buf1 + (bloc * 15 + lane) * LDAh + head * 32);
#pragma unroll
                for (int d2 = 0; d2 < 16; d2++)
                    op[d2] = __floats2half2_rn(od[d2 * 2], od[d2 * 2 + 1]);
            }
        }
        __syncthreads();
        PRE(); WAITW(); __syncthreads();
        ZA(acc);
        MML(bufB, acc);
        __syncthreads();
        EPILN(acc, bo + l * 128, ln2_g + l * 128, ln2_b + l * 128, 1, 1);
        float acc2[2][4][4];
        ZA(acc2);
        for (int kt = 0; kt < 4; kt++) {
            PRE(); WAITW(); __syncthreads();
            ZA(acc);
            MML(hSB, acc);
            __syncthreads();
            {
                int gnb = wn * 32 + tig * 2;
                const float* bias = b1g + l * 512 + kt * 128;
#pragma unroll
                for (int mf = 0; mf < 2; mf++)
#pragma unroll
                    for (int rp = 0; rp < 2; rp++) {
                        int gm = wm * 32 + mf * 16 + rp * 8 + gid;
#pragma unroll
                        for (int nf = 0; nf < 4; nf++) {
                            int c = gnb + nf * 8;
                            float v0 = fmaxf(acc[mf][nf][rp * 2] + bias[c], 0.f);
                            float v1 = fmaxf(acc[mf][nf][rp * 2 + 1] + bias[c + 1], 0.f);
                            *(__half2*)(buf1 + gm * LDAh + c) = __floats2half2_rn(v0, v1);
                        }
                    }
            }
            __syncthreads();
            PRE(); WAITW(); __syncthreads();
            MML(bufB, acc2);
            __syncthreads();
        }
        if (l == 0) {
            EPILN(acc2, b2g, ln1_g + 128, ln1_b + 128, 1, 1);
        } else {
            EPILN(acc2, b2g + 128, nullptr, nullptr, 1, 0);
            if (tid < 128) {
#pragma unroll
                for (int lb = 0; lb < 4; lb++) {
                    float s = 0.f;
#pragma unroll
                    for (int t = 0; t < 15; t++) s += aS[(lb * 15 + t) * 132 + tid];
                    out[((size_t)(b0 + lb) * 26 + 24) * 128 + tid] = s * (1.0f / 15.0f);
                }
            }
        }
    }
}

// ======================================================================
// host launcher — 4 launches
// ======================================================================
extern "C" void kernel_launch(void* const* d_in, const int* in_sizes, int n_in,
                              void* d_out, int out_size) {
    const int*   xx    = (const int*)d_in[0];
    const float* ss    = (const float*)d_in[1];
    const float* Win   = (const float*)d_in[2];
    const float* b_in  = (const float*)d_in[3];
    const float* Wl    = (const float*)d_in[4];
    const float* bl    = (const float*)d_in[5];
    const float* Wr    = (const float*)d_in[6];
    const float* ln_g  = (const float*)d_in[7];
    const float* ln_b  = (const float*)d_in[8];
    const float* Wqkv  = (const float*)d_in[9];
    const float* bqkv  = (const float*)d_in[10];
    const float* Wo    = (const float*)d_in[11];
    const float* bo    = (const float*)d_in[12];
    const float* ln1_g = (const float*)d_in[13];
    const float* ln1_b = (const float*)d_in[14];
    const float* ln2_g = (const float*)d_in[15];
    const float* ln2_b = (const float*)d_in[16];
    const float* W1    = (const float*)d_in[17];
    const float* b1    = (const float*)d_in[18];
    const float* W2    = (const float*)d_in[19];
    const float* b2    = (const float*)d_in[20];
    const float* Wact  = (const float*)d_in[21];
    const float* bact  = (const float*)d_in[22];
    const float* Wsc   = (const float*)d_in[23];
    const float* bsc   = (const float*)d_in[24];
    float* out = (float*)d_out;

    cudaFuncSetAttribute(k_gnn3, cudaFuncAttributeMaxDynamicSharedMemorySize, GNN3_DSMEM);
    cudaFuncSetAttribute(k_tf, cudaFuncAttributeMaxDynamicSharedMemorySize, TF_SMEM);

    k_wtf<<<448, 256>>>(Wqkv, Wo, W1, W2, Wact);                          // 1
    k_init<<<Bsz, 512>>>(xx, ss, Win, b_in);                              // 2
    k_tf<<<128, 256, TF_SMEM>>>(xx, bact, bqkv, bo, b1, b2,               // 3
                                ln1_g, ln1_b, ln2_g, ln2_b, out);
    k_gnn3<<<512, 256, GNN3_DSMEM>>>(Wr, Wl, bl, ln_g, ln_b,              // 4 <- profiled
                                     ss, Wsc, bsc, out);
}

// round 13
// speedup vs baseline: 3.5582x; 1.0351x over previous
#include <cuda_runtime.h>
#include <cuda_fp16.h>
#include <cstdint>
#include <cstddef>

#define Bsz  512
#define S3v  512
#define Cd   128
#define Mrows (Bsz * S3v)
#define EPSL 1e-5f
#define LDAh 136   // halves per staged row (272B, 16B aligned)

// ---------------- device scratch ----------------
__device__ __half g_xh0[(size_t)Mrows * Cd];
__device__ __half g_xh1[(size_t)Mrows * Cd];
__device__ __half g_Wqkvh[2 * 384 * 128];
__device__ __half g_Woh[2 * 128 * 128];
__device__ __half g_W1h[2 * 512 * 128];
__device__ __half g_W2h[2 * 128 * 512];
__device__ __half g_Wacth[128 * 512];
__device__ float g_s0[Bsz * Cd];
__device__ float g_alpha[Bsz];
__device__ float g_m[Mrows];

// ---------------- helpers ----------------
__device__ __forceinline__ void mmaf16(float* d, const unsigned* a, unsigned b0, unsigned b1) {
    asm("mma.sync.aligned.m16n8k16.row.col.f32.f16.f16.f32 "
        "{%0,%1,%2,%3},{%4,%5,%6,%7},{%8,%9},{%0,%1,%2,%3};"
        : "+f"(d[0]), "+f"(d[1]), "+f"(d[2]), "+f"(d[3])
        : "r"(a[0]), "r"(a[1]), "r"(a[2]), "r"(a[3]), "r"(b0), "r"(b1));
}
__device__ __forceinline__ void ldsm4(unsigned& r0, unsigned& r1, unsigned& r2, unsigned& r3,
                                      uint32_t addr) {
    asm volatile("ldmatrix.sync.aligned.m8n8.x4.shared.b16 {%0,%1,%2,%3}, [%4];"
                 : "=r"(r0), "=r"(r1), "=r"(r2), "=r"(r3) : "r"(addr));
}
__device__ __forceinline__ float shred2(float v) {
    v += __shfl_xor_sync(0xffffffffu, v, 1);
    v += __shfl_xor_sync(0xffffffffu, v, 2);
    return v;
}
__device__ __forceinline__ float shredg(float v) {
    v += __shfl_xor_sync(0xffffffffu, v, 4);
    v += __shfl_xor_sync(0xffffffffu, v, 8);
    v += __shfl_xor_sync(0xffffffffu, v, 16);
    return v;
}
__device__ __forceinline__ void cpa16(void* dst_smem, const void* src) {
    uint32_t d = (uint32_t)__cvta_generic_to_shared(dst_smem);
    asm volatile("cp.async.ca.shared.global [%0], [%1], 16;\n" :: "r"(d), "l"(src));
}
__device__ __forceinline__ void barn(int id, int cnt) {
    asm volatile("bar.sync %0, %1;" :: "r"(id), "r"(cnt) : "memory");
}

// ======================================================================
// K_wtf: transformer weights fp32 -> fp16
// ======================================================================
__global__ void k_wtf(const float* __restrict__ Wqkv, const float* __restrict__ Wo,
                      const float* __restrict__ W1, const float* __restrict__ W2,
                      const float* __restrict__ Wact) {
    int idx = (blockIdx.x * 256 + threadIdx.x) * 4;
    const float* src;
    __half2* dst;
    if (idx < 98304)        { int j = idx;          src = Wqkv + j; dst = (__half2*)(g_Wqkvh + j); }
    else if (idx < 131072)  { int j = idx - 98304;  src = Wo + j;   dst = (__half2*)(g_Woh + j); }
    else if (idx < 262144)  { int j = idx - 131072; src = W1 + j;   dst = (__half2*)(g_W1h + j); }
    else if (idx < 393216)  { int j = idx - 262144; src = W2 + j;   dst = (__half2*)(g_W2h + j); }
    else                    { int j = idx - 393216; src = Wact + j; dst = (__half2*)(g_Wacth + j); }
    float4 v = *(const float4*)src;
    dst[0] = __floats2half2_rn(v.x, v.y);
    dst[1] = __floats2half2_rn(v.z, v.w);
}

// ======================================================================
// K_init
// ======================================================================
__global__ void k_init(const int* __restrict__ xx, const float* __restrict__ ss,
                       const float* __restrict__ Win, const float* __restrict__ b_in) {
    __shared__ float ssm4[4][128];
    __shared__ int nct[4];
    int b = blockIdx.x, tid = threadIdx.x;
    int ph = tid >> 7, c = tid & 127;
    float w0 = Win[c * 5 + 0], w1 = Win[c * 5 + 1], w2 = Win[c * 5 + 2];
    float w3 = Win[c * 5 + 3], w4 = Win[c * 5 + 4];
    float base = (ss[b] * 0.125f) * w4 + b_in[c];
    const int* fp = xx + (size_t)b * 16 * S3v;
    const float inv7 = 1.0f / 7.0f;
    float ssum = 0.f; int ncnt = 0;
    for (int i = 0; i < 128; i++) {
        int p = i * 4 + ph;
        int f = fp[p];
        int ii = p >> 6, jj = (p >> 3) & 7, kk = p & 7;
        float val = base + (float)ii * inv7 * w0 + (float)jj * inv7 * w1 +
                    (float)kk * inv7 * w2 + (float)f * 0.5f * w3;
        g_xh0[((size_t)b * S3v + p) * Cd + c] = __float2half_rn(val);
        if (f != 0) { ssum += val; ncnt++; }
        if (c == 0) g_m[b * S3v + p] = (f != 0) ? 1.0f : 0.0f;
    }
    ssm4[ph][c] = ssum;
    if (c == 0) nct[ph] = ncnt;
    __syncthreads();
    if (tid < 128) {
        float s = ssm4[0][tid] + ssm4[1][tid] + ssm4[2][tid] + ssm4[3][tid];
        g_s0[b * Cd + tid] = s;
    }
    if (tid == 0) {
        int n = nct[0] + nct[1] + nct[2] + nct[3];
        g_alpha[b] = (n > 1) ? 1.0f / (float)(n - 1) : 0.f;
    }
}

// ======================================================================
// K_gnn3: 3 GNN layers + weff + tv + pool; ONE batch per CTA (grid=512),
// 2 CTAs/SM, 1 block-barrier per tile, named-barrier LN.
// ======================================================================
#define GNN3_DSMEM (34816 * 3 + 6144)
__global__ void __launch_bounds__(256, 2)
k_gnn3(const float* __restrict__ Wr, const float* __restrict__ Wl,
       const float* __restrict__ bl, const float* __restrict__ ln_g,
       const float* __restrict__ ln_b, const float* __restrict__ ss,
       const float* __restrict__ Wsc, const float* __restrict__ bsc,
       float* __restrict__ out) {
    extern __shared__ char smc[];
    __half* W = (__half*)smc;                      // 128 x LDAh
    __half* Ab0 = (__half*)(smc + 34816);          // 2 x 128 x LDAh
    float* fx = (float*)(smc + 34816 * 3);
    float* tvs = fx;        float* gsh = fx + 128;
    float* bsh = fx + 256;  float* msk = fx + 384;
    float* sacc = fx + 512; float* redS = fx + 640;   // [128][2]
    float* redQ = fx + 896;                           // [128][2]
    float* ssm = fx + 1152;                           // 128
    float* pm  = fx + 640;                            // pool mask overlay (512)

    int tid = threadIdx.x, wid = tid >> 5, lane = tid & 31;
    int wm = wid >> 1, wn = wid & 1;
    int gid = lane >> 2, tig = lane & 3;

    if (tid < 128) { gsh[tid] = ln_g[tid]; bsh[tid] = ln_b[tid]; }

    uint32_t Wsb = (uint32_t)__cvta_generic_to_shared(W);
    uint32_t Asb = (uint32_t)__cvta_generic_to_shared(Ab0);
    uint32_t aoff[2], boff[4];
#pragma unroll
    for (int mf = 0; mf < 2; mf++)
        aoff[mf] = (uint32_t)(((wm * 32 + mf * 16 + (lane & 15)) * LDAh + ((lane >> 4) << 3)) * 2);
#pragma unroll
    for (int p = 0; p < 4; p++) {
        int n = wn * 64 + p * 16 + (lane & 7) + ((lane >> 4) << 3);
        int koff = ((lane >> 3) & 1) << 3;
        boff[p] = Wsb + (uint32_t)((n * LDAh + koff) * 2);
    }

    __half* XB[2];
    XB[0] = g_xh0; XB[1] = g_xh1;

    int b = blockIdx.x;
    float alpha = g_alpha[b];

    // prefetch layer-0 tile 0
    {
        const __half* asrc = g_xh0 + (size_t)b * 512 * Cd;
        for (int u = tid; u < 2048; u += 256) {
            int r = u >> 4, j = u & 15;
            cpa16(Ab0 + r * LDAh + j * 8, asrc + r * Cd + j * 8);
        }
        asm volatile("cp.async.commit_group;\n");
    }
    if (tid < 128) { ssm[tid] = g_s0[b * Cd + tid]; sacc[tid] = 0.f; }
    __syncthreads();

    int bufi = 0;
    for (int l = 0; l < 3; l++) {
        const float* Wr_l = Wr + l * 16384;
        const float* Wl_l = Wl + l * 16384;
        // W_eff = Wr - alpha*Wl -> smem fp16
        for (int u = tid; u < 2048; u += 256) {
            int n = u >> 4, j = u & 15;
            const float4* wr4 = (const float4*)(Wr_l + n * 128 + j * 8);
            const float4* wl4 = (const float4*)(Wl_l + n * 128 + j * 8);
            float4 a0 = wr4[0], a1 = wr4[1];
            float4 c0 = wl4[0], c1 = wl4[1];
            __half2* d = (__half2*)(W + n * LDAh + j * 8);
            d[0] = __floats2half2_rn(a0.x - alpha * c0.x, a0.y - alpha * c0.y);
            d[1] = __floats2half2_rn(a0.z - alpha * c0.z, a0.w - alpha * c0.w);
            d[2] = __floats2half2_rn(a1.x - alpha * c1.x, a1.y - alpha * c1.y);
            d[3] = __floats2half2_rn(a1.z - alpha * c1.z, a1.w - alpha * c1.w);
        }
        // tv[c] = alpha*(s . Wl[c]) + bl[c]
        if (tid < 128) {
            const float4* wl4 = (const float4*)(Wl_l + tid * 128);
            float a0 = 0.f, a1 = 0.f, a2 = 0.f, a3 = 0.f;
#pragma unroll
            for (int k4 = 0; k4 < 32; k4 += 4) {
                float4 w0 = wl4[k4], w1 = wl4[k4 + 1], w2 = wl4[k4 + 2], w3 = wl4[k4 + 3];
                a0 += ssm[k4 * 4 + 0] * w0.x + ssm[k4 * 4 + 1] * w0.y + ssm[k4 * 4 + 2] * w0.z + ssm[k4 * 4 + 3] * w0.w;
                a1 += ssm[k4 * 4 + 4] * w1.x + ssm[k4 * 4 + 5] * w1.y + ssm[k4 * 4 + 6] * w1.z + ssm[k4 * 4 + 7] * w1.w;
                a2 += ssm[k4 * 4 + 8] * w2.x + ssm[k4 * 4 + 9] * w2.y + ssm[k4 * 4 + 10] * w2.z + ssm[k4 * 4 + 11] * w2.w;
                a3 += ssm[k4 * 4 + 12] * w3.x + ssm[k4 * 4 + 13] * w3.y + ssm[k4 * 4 + 14] * w3.z + ssm[k4 * 4 + 15] * w3.w;
            }
            tvs[tid] = alpha * (a0 + a1 + a2 + a3) + bl[l * 128 + tid];
        }

        const __half* xin = XB[(l == 1) ? 1 : 0];
        __half* xout = XB[(l == 1) ? 0 : 1];
        int last = (l == 2);

        for (int tt = 0; tt < 4; tt++) {
            int row0 = b * 512 + tt * 128;
            if (tid < 128) msk[tid] = g_m[row0 + tid];
            asm volatile("cp.async.wait_group 0;\n");
            __syncthreads();   // A tile + W + tvs + msk visible; prev reads done

            uint32_t ab = Asb + (uint32_t)(bufi * (128 * LDAh * 2));
            float acc[2][8][4];
#pragma unroll
            for (int a0 = 0; a0 < 2; a0++)
#pragma unroll
                for (int a1 = 0; a1 < 8; a1++)
#pragma unroll
                    for (int a2 = 0; a2 < 4; a2++) acc[a0][a1][a2] = 0.f;

#pragma unroll
            for (int ks = 0; ks < 128; ks += 16) {
                unsigned af[2][4], bf[8][2];
#pragma unroll
                for (int mf = 0; mf < 2; mf++)
                    ldsm4(af[mf][0], af[mf][1], af[mf][2], af[mf][3], ab + aoff[mf] + ks * 2);
#pragma unroll
                for (int p = 0; p < 4; p++)
                    ldsm4(bf[p * 2][0], bf[p * 2][1], bf[p * 2 + 1][0], bf[p * 2 + 1][1],
                          boff[p] + ks * 2);
#pragma unroll
                for (int mf = 0; mf < 2; mf++)
#pragma unroll
                    for (int nf = 0; nf < 8; nf++)
                        mmaf16(acc[mf][nf], af[mf], bf[nf][0], bf[nf][1]);
            }

            // prefetch next tile AFTER mainloop
            {
                bool havenext;
                const __half* nsrc = nullptr;
                if (tt < 3) { havenext = true; nsrc = xin + (size_t)(row0 + 128) * Cd; }
                else if (l < 2) {
                    havenext = true;
                    const __half* nin = XB[(l + 1 == 1) ? 1 : 0];
                    nsrc = nin + (size_t)b * 512 * Cd;
                } else havenext = false;
                if (havenext) {
                    __half* dst = Ab0 + (bufi ^ 1) * (128 * LDAh);
                    for (int u = tid; u < 2048; u += 256) {
                        int r = u >> 4, j = u & 15;
                        cpa16(dst + r * LDAh + j * 8, nsrc + r * Cd + j * 8);
                    }
                    asm volatile("cp.async.commit_group;\n");
                }
            }

            // ---- epilogue: relu+tv, rowsum partials, pair-group LN ----
#pragma unroll
            for (int mf = 0; mf < 2; mf++)
#pragma unroll
                for (int nf = 0; nf < 8; nf++) {
                    int col = wn * 64 + nf * 8 + 2 * tig;
                    float tv0 = tvs[col], tv1 = tvs[col + 1];
#pragma unroll
                    for (int rp = 0; rp < 2; rp++) {
                        acc[mf][nf][rp * 2]     = fmaxf(acc[mf][nf][rp * 2]     + tv0, 0.f);
                        acc[mf][nf][rp * 2 + 1] = fmaxf(acc[mf][nf][rp * 2 + 1] + tv1, 0.f);
                    }
                }
#pragma unroll
            for (int mf = 0; mf < 2; mf++)
#pragma unroll
                for (int rp = 0; rp < 2; rp++) {
                    float s = 0.f, q = 0.f;
#pragma unroll
                    for (int nf = 0; nf < 8; nf++) {
                        float v0 = acc[mf][nf][rp * 2], v1 = acc[mf][nf][rp * 2 + 1];
                        s += v0 + v1; q += v0 * v0 + v1 * v1;
                    }
                    s = shred2(s); q = shred2(q);
                    if (tig == 0) {
                        int r = wm * 32 + mf * 16 + rp * 8 + gid;
                        redS[r * 2 + wn] = s;
                        redQ[r * 2 + wn] = q;
                    }
                }
            barn(1 + wm, 64);   // only the 2 warps sharing these rows
            float csum[8][2];
#pragma unroll
            for (int nf = 0; nf < 8; nf++) { csum[nf][0] = 0.f; csum[nf][1] = 0.f; }
#pragma unroll
            for (int mf = 0; mf < 2; mf++)
#pragma unroll
                for (int rp = 0; rp < 2; rp++) {
                    int r = wm * 32 + mf * 16 + rp * 8 + gid;
                    float s = redS[r * 2] + redS[r * 2 + 1];
                    float q = redQ[r * 2] + redQ[r * 2 + 1];
                    float mu = s * (1.0f / 128.0f);
                    float var = fmaxf(q * (1.0f / 128.0f) - mu * mu, 0.f);
                    float rs = rsqrtf(var + EPSL);
                    float mk = msk[r];
#pragma unroll
                    for (int nf = 0; nf < 8; nf++) {
                        int col = wn * 64 + nf * 8 + 2 * tig;
                        float x0 = (acc[mf][nf][rp * 2]     - mu) * rs * gsh[col] + bsh[col];
                        float x1 = (acc[mf][nf][rp * 2 + 1] - mu) * rs * gsh[col + 1] + bsh[col + 1];
                        *(__half2*)(xout + (size_t)(row0 + r) * Cd + col) = __floats2half2_rn(x0, x1);
                        if (!last) {
                            csum[nf][0] += mk * x0;
                            csum[nf][1] += mk * x1;
                        }
                    }
                }
            if (!last) {
#pragma unroll
                for (int nf = 0; nf < 8; nf++) {
                    csum[nf][0] = shredg(csum[nf][0]);
                    csum[nf][1] = shredg(csum[nf][1]);
                }
                if (gid == 0) {
#pragma unroll
                    for (int nf = 0; nf < 8; nf++) {
                        int col = wn * 64 + nf * 8 + 2 * tig;
                        atomicAdd(&sacc[col], csum[nf][0]);
                        atomicAdd(&sacc[col + 1], csum[nf][1]);
                    }
                }
            }
            bufi ^= 1;
        }
        // end-of-layer: order atomics + mainloop reads before W restage
        __syncthreads();
        if (l < 2) {
            if (tid < 128) { ssm[tid] = sacc[tid]; sacc[tid] = 0.f; }
            __syncthreads();
        }
    }

    // ---- fused pooling + mv_emb (x in g_xh1, L2-hot) ----
    for (int p = tid; p < 512; p += 256) pm[p] = g_m[b * 512 + p];
    __syncthreads();
    if (tid < 128) {
        int c = tid;
        float aj[8], ak[8];
#pragma unroll
        for (int q = 0; q < 8; q++) { aj[q] = 0.f; ak[q] = 0.f; }
        const __half* xb = g_xh1 + (size_t)b * 512 * Cd + c;
        for (int i = 0; i < 8; i++) {
            float ai = 0.f;
#pragma unroll
            for (int jk = 0; jk < 64; jk++) {
                int p = i * 64 + jk;
                float v = pm[p] * __half2float(xb[(size_t)p * Cd]);
                ai += v; aj[jk >> 3] += v; ak[jk & 7] += v;
            }
            out[((size_t)b * 26 + i) * Cd + c] = ai * 0.015625f;
        }
#pragma unroll
        for (int q = 0; q < 8; q++) {
            out[((size_t)b * 26 + 8 + q) * Cd + c] = aj[q] * 0.015625f;
            out[((size_t)b * 26 + 16 + q) * Cd + c] = ak[q] * 0.015625f;
        }
        out[((size_t)b * 26 + 25) * Cd + c] = fmaxf(ss[b] * Wsc[c] + bsc[c], 0.f);
    }
}

// ======================================================================
// K_tf: fused transformer (named-barrier LN)
// ======================================================================
#define TF_SMEM 190976
#define QLD 392
__global__ void __launch_bounds__(256, 1)
k_tf(const int* __restrict__ xx,
     const float* __restrict__ bact,
     const float* __restrict__ bqkv, const float* __restrict__ bo,
     const float* __restrict__ b1g, const float* __restrict__ b2g,
     const float* __restrict__ ln1_g, const float* __restrict__ ln1_b,
     const float* __restrict__ ln2_g, const float* __restrict__ ln2_b,
     float* __restrict__ out) {
    extern __shared__ char sm[];
    __half* sW0  = (__half*)sm;
    __half* sW1  = (__half*)(sm + 34816);
    __half* buf1 = (__half*)(sm + 69632);
    __half* hS   = (__half*)(sm + 87040);
    __half* qkvS = (__half*)(sm + 104448);
    float*  aS   = (float*)(sm + 154624);
    float*  redS = (float*)(sm + 188416);
    float*  redQ = redS + 256;

    int tid = threadIdx.x, wid = tid >> 5, lane = tid & 31;
    int wm = wid & 1, wn = wid >> 1;
    int gid = lane >> 2, tig = lane & 3;
    int row0 = blockIdx.x * 60;
    int b0 = blockIdx.x * 4;

    uint32_t sWb[2] = { (uint32_t)__cvta_generic_to_shared(sW0),
                        (uint32_t)__cvta_generic_to_shared(sW1) };
    uint32_t bufB = (uint32_t)__cvta_generic_to_shared(buf1);
    uint32_t hSB  = (uint32_t)__cvta_generic_to_shared(hS);
    uint32_t aoff[2], boff[2];
#pragma unroll
    for (int mf = 0; mf < 2; mf++)
        aoff[mf] = (uint32_t)(((wm * 32 + mf * 16 + (lane & 15)) * LDAh + ((lane >> 4) << 3)) * 2);
#pragma unroll
    for (int p = 0; p < 2; p++) {
        int n = wn * 32 + p * 16 + (lane & 7) + ((lane >> 4) << 3);
        int koff = ((lane >> 3) & 1) << 3;
        boff[p] = (uint32_t)((n * LDAh + koff) * 2);
    }

    const __half* wptr[28]; int wstr[28];
    {
        int i = 0;
        for (int kc = 0; kc < 512; kc += 128) { wptr[i] = g_Wacth + kc; wstr[i++] = 512; }
        for (int l = 0; l < 2; l++) {
            for (int nt = 0; nt < 3; nt++) { wptr[i] = g_Wqkvh + l * 49152 + nt * 16384; wstr[i++] = 128; }
            wptr[i] = g_Woh + l * 16384; wstr[i++] = 128;
            for (int kt = 0; kt < 4; kt++) {
                wptr[i] = g_W1h + l * 65536 + kt * 16384; wstr[i++] = 128;
                wptr[i] = g_W2h + l * 65536 + kt * 128;  wstr[i++] = 512;
            }
        }
    }
    int ipre = 0, iuse = 0;
    auto PRE = [&]() {
        if (ipre >= 28) return;
        const __half* src = wptr[ipre];
        int st = wstr[ipre];
        __half* dst = (ipre & 1) ? sW1 : sW0;
        for (int u = tid; u < 2048; u += 256) {
            int n = u >> 4, j = u & 15;
            cpa16(dst + n * LDAh + j * 8, src + (size_t)n * st + j * 8);
        }
        asm volatile("cp.async.commit_group;\n");
        ipre++;
    };
    auto WAITW = [&]() {
        if (ipre - iuse > 1) asm volatile("cp.async.wait_group 1;\n");
        else                 asm volatile("cp.async.wait_group 0;\n");
    };
    auto MML = [&](uint32_t ab, float (&acc)[2][4][4]) {
        uint32_t wb = sWb[iuse & 1];
#pragma unroll
        for (int ks = 0; ks < 128; ks += 16) {
            unsigned af[2][4], bf[4][2];
#pragma unroll
            for (int mf = 0; mf < 2; mf++)
                ldsm4(af[mf][0], af[mf][1], af[mf][2], af[mf][3], ab + aoff[mf] + ks * 2);
#pragma unroll
            for (int p = 0; p < 2; p++)
                ldsm4(bf[p * 2][0], bf[p * 2][1], bf[p * 2 + 1][0], bf[p * 2 + 1][1],
                      wb + boff[p] + ks * 2);
#pragma unroll
            for (int mf = 0; mf < 2; mf++)
#pragma unroll
                for (int nf = 0; nf < 4; nf++)
                    mmaf16(acc[mf][nf], af[mf], bf[nf][0], bf[nf][1]);
        }
        iuse++;
    };
    auto ZA = [&](float (&acc)[2][4][4]) {
#pragma unroll
        for (int a0 = 0; a0 < 2; a0++)
#pragma unroll
            for (int a1 = 0; a1 < 4; a1++)
#pragma unroll
                for (int a2 = 0; a2 < 4; a2++) acc[a0][a1][a2] = 0.f;
    };
    auto EPILN = [&](float (&acc)[2][4][4], const float* bias,
                     const float* lng, const float* lnb, int addRes, int doLN) {
        int gnb = wn * 32 + tig * 2;
#pragma unroll
        for (int mf = 0; mf < 2; mf++)
#pragma unroll
            for (int rp = 0; rp < 2; rp++) {
                int gm = wm * 32 + mf * 16 + rp * 8 + gid;
#pragma unroll
                for (int nf = 0; nf < 4; nf++) {
                    int c = gnb + nf * 8;
                    float v0 = acc[mf][nf][rp * 2] + bias[c];
                    float v1 = acc[mf][nf][rp * 2 + 1] + bias[c + 1];
                    if (addRes) { v0 += aS[gm * 132 + c]; v1 += aS[gm * 132 + c + 1]; }
                    acc[mf][nf][rp * 2] = v0;
                    acc[mf][nf][rp * 2 + 1] = v1;
                    aS[gm * 132 + c] = v0;
                    aS[gm * 132 + c + 1] = v1;
                }
            }
        if (!doLN) { __syncthreads(); return; }
#pragma unroll
        for (int mf = 0; mf < 2; mf++)
#pragma unroll
            for (int rp = 0; rp < 2; rp++) {
                float s = 0.f, q = 0.f;
#pragma unroll
                for (int nf = 0; nf < 4; nf++) {
                    float v0 = acc[mf][nf][rp * 2], v1 = acc[mf][nf][rp * 2 + 1];
                    s += v0 + v1; q += v0 * v0 + v1 * v1;
                }
                s = shred2(s); q = shred2(q);
                if (tig == 0) {
                    int r = wm * 32 + mf * 16 + rp * 8 + gid;
                    redS[r * 4 + wn] = s;
                    redQ[r * 4 + wn] = q;
                }
            }
        barn(1 + wm, 128);
#pragma unroll
        for (int mf = 0; mf < 2; mf++)
#pragma unroll
            for (int rp = 0; rp < 2; rp++) {
                int r = wm * 32 + mf * 16 + rp * 8 + gid;
                float s = redS[r * 4] + redS[r * 4 + 1] + redS[r * 4 + 2] + redS[r * 4 + 3];
                float q = redQ[r * 4] + redQ[r * 4 + 1] + redQ[r * 4 + 2] + redQ[r * 4 + 3];
                float mu = s * (1.0f / 128.0f);
                float var = fmaxf(q * (1.0f / 128.0f) - mu * mu, 0.f);
                float rs = rsqrtf(var + EPSL);
#pragma unroll
                for (int nf = 0; nf < 4; nf++) {
                    int c = gnb + nf * 8;
                    float x0 = (acc[mf][nf][rp * 2] - mu) * rs * lng[c] + lnb[c];
                    float x1 = (acc[mf][nf][rp * 2 + 1] - mu) * rs * lng[c + 1] + lnb[c + 1];
                    *(__half2*)(hS + r * LDAh + c) = __floats2half2_rn(x0, x1);
                }
            }
        __syncthreads();
    };

    float acc[2][4][4];

    PRE();
    ZA(acc);
    for (int kc = 0; kc < 512; kc += 128) {
        PRE();
        for (int u = tid; u < 2048; u += 256) {
            int r = u >> 5, j = u & 31;
            int gr = row0 + r;
            if (r >= 60) gr = row0;
            int bb = gr / 15, tt = gr - bb * 15;
            int4 v = ((const int4*)(xx + ((size_t)bb * 16 + tt + 1) * 512 + kc))[j];
            __half2* d = (__half2*)(buf1 + r * LDAh + j * 4);
            d[0] = __floats2half2_rn((float)v.x, (float)v.y);
            d[1] = __floats2half2_rn((float)v.z, (float)v.w);
        }
        WAITW();
        __syncthreads();
        MML(bufB, acc);
        __syncthreads();
    }
    EPILN(acc, bact, ln1_g, ln1_b, 0, 1);

    for (int l = 0; l < 2; l++) {
        for (int nt = 0; nt < 3; nt++) {
            PRE(); WAITW(); __syncthreads();
            ZA(acc);
            MML(hSB, acc);
            __syncthreads();
            {
                int gnb = wn * 32 + tig * 2;
                const float* bias = bqkv + l * 384 + nt * 128;
#pragma unroll
                for (int mf = 0; mf < 2; mf++)
#pragma unroll
                    for (int rp = 0; rp < 2; rp++) {
                        int gm = wm * 32 + mf * 16 + rp * 8 + gid;
#pragma unroll
                        for (int nf = 0; nf < 4; nf++) {
                            int c = gnb + nf * 8;
                            *(__half2*)(qkvS + gm * QLD + nt * 128 + c) =
                                __floats2half2_rn(acc[mf][nf][rp * 2] + bias[c],
                                                  acc[mf][nf][rp * 2 + 1] + bias[c + 1]);
                        }
                    }
            }
        }
        __syncthreads();
        for (int task = wid; task < 16; task += 8) {
            int bloc = task >> 2, head = task & 3;
            if (lane < 15) {
                const __half2* qp = (const __half2*)(qkvS + (bloc * 15 + lane) * QLD + head * 32);
                float qr[32];
#pragma unroll
                for (int d2 = 0; d2 < 16; d2++) {
                    float2 f = __half22float2(qp[d2]);
                    qr[d2 * 2] = f.x; qr[d2 * 2 + 1] = f.y;
                }
                float sc[15], mx = -1e30f;
#pragma unroll
                for (int tk = 0; tk < 15; tk++) {
                    const __half2* kp = (const __half2*)(qkvS + (bloc * 15 + tk) * QLD + 128 + head * 32);
                    float a = 0.f;
#pragma unroll
                    for (int d2 = 0; d2 < 16; d2++) {
                        float2 f = __half22float2(kp[d2]);
                        a += qr[d2 * 2] * f.x + qr[d2 * 2 + 1] * f.y;
                    }
                    sc[tk] = a * 0.17677669529663687f;
                    mx = fmaxf(mx, sc[tk]);
                }
                float ssum = 0.f;
#pragma unroll
                for (int tk = 0; tk < 15; tk++) { sc[tk] = expf(sc[tk] - mx); ssum += sc[tk]; }
                float inv = 1.0f / ssum;
                float od[32];
#pragma unroll
                for (int d = 0; d < 32; d++) od[d] = 0.f;
#pragma unroll
                for (int tk = 0; tk < 15; tk++) {
                    float p = sc[tk] * inv;
                    const __half2* vp = (const __half2*)(qkvS + (bloc * 15 + tk) * QLD + 256 + head * 32);
#pragma unroll
                    for (int d2 = 0; d2 < 16; d2++) {
                        float2 f = __half22float2(vp[d2]);
                        od[d2 * 2] += p * f.x; od[d2 * 2 + 1] += p * f.y;
                    }
                }
                __half2* op = (__half2*)(buf1 + (bloc * 15 + lane) * LDAh + head * 32);
#pragma unroll
                for (int d2 = 0; d2 < 16; d2++)
                    op[d2] = __floats2half2_rn(od[d2 * 2], od[d2 * 2 + 1]);
            }
        }
        __syncthreads();
        PRE(); WAITW(); __syncthreads();
        ZA(acc);
        MML(bufB, acc);
        __syncthreads();
        EPILN(acc, bo + l * 128, ln2_g + l * 128, ln2_b + l * 128, 1, 1);
        float acc2[2][4][4];
        ZA(acc2);
        for (int kt = 0; kt < 4; kt++) {
            PRE(); WAITW(); __syncthreads();
            ZA(acc);
            MML(hSB, acc);
            __syncthreads();
            {
                int gnb = wn * 32 + tig * 2;
                const float* bias = b1g + l * 512 + kt * 128;
#pragma unroll
                for (int mf = 0; mf < 2; mf++)
#pragma unroll
                    for (int rp = 0; rp < 2; rp++) {
                        int gm = wm * 32 + mf * 16 + rp * 8 + gid;
#pragma unroll
                        for (int nf = 0; nf < 4; nf++) {
                            int c = gnb + nf * 8;
                            float v0 = fmaxf(acc[mf][nf][rp * 2] + bias[c], 0.f);
                            float v1 = fmaxf(acc[mf][nf][rp * 2 + 1] + bias[c + 1], 0.f);
                            *(__half2*)(buf1 + gm * LDAh + c) = __floats2half2_rn(v0, v1);
                        }
                    }
            }
            __syncthreads();
            PRE(); WAITW(); __syncthreads();
            MML(bufB, acc2);
            __syncthreads();
        }
        if (l == 0) {
            EPILN(acc2, b2g, ln1_g + 128, ln1_b + 128, 1, 1);
        } else {
            EPILN(acc2, b2g + 128, nullptr, nullptr, 1, 0);
            if (tid < 128) {
#pragma unroll
                for (int lb = 0; lb < 4; lb++) {
                    float s = 0.f;
#pragma unroll
                    for (int t = 0; t < 15; t++) s += aS[(lb * 15 + t) * 132 + tid];
                    out[((size_t)(b0 + lb) * 26 + 24) * 128 + tid] = s * (1.0f / 15.0f);
                }
            }
        }
    }
}

// ======================================================================
// host launcher — 4 launches, two independent chains forked across streams
// ======================================================================
extern "C" void kernel_launch(void* const* d_in, const int* in_sizes, int n_in,
                              void* d_out, int out_size) {
    const int*   xx    = (const int*)d_in[0];
    const float* ss    = (const float*)d_in[1];
    const float* Win   = (const float*)d_in[2];
    const float* b_in  = (const float*)d_in[3];
    const float* Wl    = (const float*)d_in[4];
    const float* bl    = (const float*)d_in[5];
    const float* Wr    = (const float*)d_in[6];
    const float* ln_g  = (const float*)d_in[7];
    const float* ln_b  = (const float*)d_in[8];
    const float* Wqkv  = (const float*)d_in[9];
    const float* bqkv  = (const float*)d_in[10];
    const float* Wo    = (const float*)d_in[11];
    const float* bo    = (const float*)d_in[12];
    const float* ln1_g = (const float*)d_in[13];
    const float* ln1_b = (const float*)d_in[14];
    const float* ln2_g = (const float*)d_in[15];
    const float* ln2_b = (const float*)d_in[16];
    const float* W1    = (const float*)d_in[17];
    const float* b1    = (const float*)d_in[18];
    const float* W2    = (const float*)d_in[19];
    const float* b2    = (const float*)d_in[20];
    const float* Wact  = (const float*)d_in[21];
    const float* bact  = (const float*)d_in[22];
    const float* Wsc   = (const float*)d_in[23];
    const float* bsc   = (const float*)d_in[24];
    float* out = (float*)d_out;

    cudaFuncSetAttribute(k_gnn3, cudaFuncAttributeMaxDynamicSharedMemorySize, GNN3_DSMEM);
    cudaFuncSetAttribute(k_tf, cudaFuncAttributeMaxDynamicSharedMemorySize, TF_SMEM);

    cudaStream_t s2;
    cudaEvent_t e0, e1;
    cudaStreamCreateWithFlags(&s2, cudaStreamNonBlocking);
    cudaEventCreateWithFlags(&e0, cudaEventDisableTiming);
    cudaEventCreateWithFlags(&e1, cudaEventDisableTiming);

    // fork: side chain (wtf -> tf) depends only on inputs
    cudaEventRecord(e0, 0);
    cudaStreamWaitEvent(s2, e0, 0);
    k_wtf<<<448, 256, 0, s2>>>(Wqkv, Wo, W1, W2, Wact);
    k_tf<<<128, 256, TF_SMEM, s2>>>(xx, bact, bqkv, bo, b1, b2,
                                    ln1_g, ln1_b, ln2_g, ln2_b, out);
    cudaEventRecord(e1, s2);

    // main chain: init -> gnn3
    k_init<<<Bsz, 512>>>(xx, ss, Win, b_in);
    k_gnn3<<<512, 256, GNN3_DSMEM>>>(Wr, Wl, bl, ln_g, ln_b,
                                     ss, Wsc, bsc, out);
    // join
    cudaStreamWaitEvent(0, e1, 0);
}